// round 10
// baseline (speedup 1.0000x reference)
#include <cuda_runtime.h>
#include <cuda_bf16.h>
#include <math.h>
#include <stdint.h>

// Problem constants
#define B_   2
#define S_   2048
#define D_   1024
#define H_   16
#define HD_  64
#define R_   8
#define T_   2056      // S_ + R_
#define HALF_ 128
#define QKVW_ 3072     // 3*D_
#define MPAD_ 4352     // B_*T_ = 4112 padded to multiple of 256

// Scratch (device globals; no allocation allowed)
__device__ __align__(16) __nv_bfloat16 g_xr_hi[(size_t)MPAD_ * D_];
__device__ __align__(16) __nv_bfloat16 g_xr_lo[(size_t)MPAD_ * D_];
__device__ __align__(16) __nv_bfloat16 g_wq_hi[(size_t)QKVW_ * D_];
__device__ __align__(16) __nv_bfloat16 g_wq_lo[(size_t)QKVW_ * D_];
__device__ __align__(16) __nv_bfloat16 g_wo_hi[(size_t)D_ * D_];
__device__ __align__(16) __nv_bfloat16 g_wo_lo[(size_t)D_ * D_];
__device__ __align__(16) __nv_bfloat16 g_at_hi[(size_t)B_ * S_ * D_];
__device__ __align__(16) __nv_bfloat16 g_at_lo[(size_t)B_ * S_ * D_];
__device__ __align__(16) __nv_bfloat16 g_qkv_hi[(size_t)B_ * T_ * QKVW_];
__device__ __align__(16) __nv_bfloat16 g_qkv_lo[(size_t)B_ * T_ * QKVW_];

// ---------------------------------------------------------------------------
// helpers
// ---------------------------------------------------------------------------
__device__ __forceinline__ uint32_t smem_u32(const void* p) {
    uint32_t a;
    asm("{ .reg .u64 t; cvta.to.shared.u64 t, %1; cvt.u32.u64 %0, t; }"
        : "=r"(a) : "l"(p));
    return a;
}
__device__ __forceinline__ uint32_t sw128(uint32_t off) {
    return off ^ ((off >> 3) & 0x70);
}
__device__ __forceinline__ void cp16(uint32_t dst, const void* src) {
    asm volatile("cp.async.cg.shared.global [%0], [%1], 16;"
                 :: "r"(dst), "l"(src) : "memory");
}
__device__ __forceinline__ void cp_commit() {
    asm volatile("cp.async.commit_group;" ::: "memory");
}
__device__ __forceinline__ void cp_wait0() {
    asm volatile("cp.async.wait_group 0;" ::: "memory");
}
__device__ __forceinline__ void cp_wait1() {
    asm volatile("cp.async.wait_group 1;" ::: "memory");
}
__device__ __forceinline__ void ldm_x4(uint32_t* r, uint32_t addr) {
    asm volatile("ldmatrix.sync.aligned.m8n8.x4.shared.b16 {%0,%1,%2,%3}, [%4];"
                 : "=r"(r[0]), "=r"(r[1]), "=r"(r[2]), "=r"(r[3]) : "r"(addr));
}
__device__ __forceinline__ void ldm_x4_t(uint32_t* r, uint32_t addr) {
    asm volatile("ldmatrix.sync.aligned.m8n8.x4.trans.shared.b16 {%0,%1,%2,%3}, [%4];"
                 : "=r"(r[0]), "=r"(r[1]), "=r"(r[2]), "=r"(r[3]) : "r"(addr));
}
__device__ __forceinline__ void mma16816(float* c, const uint32_t* a, const uint32_t* b) {
    asm volatile(
        "mma.sync.aligned.m16n8k16.row.col.f32.bf16.bf16.f32 "
        "{%0,%1,%2,%3}, {%4,%5,%6,%7}, {%8,%9}, {%0,%1,%2,%3};"
        : "+f"(c[0]), "+f"(c[1]), "+f"(c[2]), "+f"(c[3])
        : "r"(a[0]), "r"(a[1]), "r"(a[2]), "r"(a[3]), "r"(b[0]), "r"(b[1]));
}

// pack 4 floats -> hi bf16x4 (uint2) and lo bf16x4 (uint2)
__device__ __forceinline__ void split4(float4 v, uint2& hi, uint2& lo) {
    __nv_bfloat16 h0 = __float2bfloat16_rn(v.x);
    __nv_bfloat16 h1 = __float2bfloat16_rn(v.y);
    __nv_bfloat16 h2 = __float2bfloat16_rn(v.z);
    __nv_bfloat16 h3 = __float2bfloat16_rn(v.w);
    hi.x = ((uint32_t)__bfloat16_as_ushort(h1) << 16) | __bfloat16_as_ushort(h0);
    hi.y = ((uint32_t)__bfloat16_as_ushort(h3) << 16) | __bfloat16_as_ushort(h2);
    __nv_bfloat162 l01 = __floats2bfloat162_rn(v.x - __bfloat162float(h0),
                                               v.y - __bfloat162float(h1));
    __nv_bfloat162 l23 = __floats2bfloat162_rn(v.z - __bfloat162float(h2),
                                               v.w - __bfloat162float(h3));
    lo.x = *(uint32_t*)&l01;
    lo.y = *(uint32_t*)&l23;
}
// pack 2 floats -> hi bf16x2 word and lo bf16x2 word
__device__ __forceinline__ void split2(float a, float b, uint32_t& hi, uint32_t& lo) {
    __nv_bfloat16 h0 = __float2bfloat16_rn(a);
    __nv_bfloat16 h1 = __float2bfloat16_rn(b);
    hi = ((uint32_t)__bfloat16_as_ushort(h1) << 16) | __bfloat16_as_ushort(h0);
    __nv_bfloat162 l = __floats2bfloat162_rn(a - __bfloat162float(h0),
                                             b - __bfloat162float(h1));
    lo = *(uint32_t*)&l;
}

// ---------------------------------------------------------------------------
// Kernel 1: build xr (hi/lo planes); rows [B_*T_, MPAD_) zero-filled.
// ---------------------------------------------------------------------------
__global__ void build_xr_split(const float* __restrict__ x,
                               const float* __restrict__ ada,
                               const float* __restrict__ regs,
                               __nv_bfloat16* __restrict__ xh,
                               __nv_bfloat16* __restrict__ xl)
{
    int i = blockIdx.x * blockDim.x + threadIdx.x;
    const int D4 = D_ / 4;
    if (i >= MPAD_ * D4) return;
    int d4 = i % D4;
    int row = i / D4;
    uint2 hi = make_uint2(0u, 0u), lo = make_uint2(0u, 0u);
    if (row < B_ * T_) {
        int t = row % T_;
        int b = row / T_;
        float4 v;
        if (t < R_) {
            float4 rv = ((const float4*)regs)[t * D4 + d4];
            float4 av = ((const float4*)ada)[b * D4 + d4];
            v = make_float4(rv.x * (1.f + av.x), rv.y * (1.f + av.y),
                            rv.z * (1.f + av.z), rv.w * (1.f + av.w));
        } else {
            v = ((const float4*)x)[((size_t)b * S_ + (t - R_)) * D4 + d4];
        }
        split4(v, hi, lo);
    }
    ((uint2*)xh)[i] = hi;
    ((uint2*)xl)[i] = lo;
}

// ---------------------------------------------------------------------------
// Kernel: generic fp32 -> (hi, lo) bf16 split
// ---------------------------------------------------------------------------
__global__ void split_planes(const float* __restrict__ src,
                             __nv_bfloat16* __restrict__ hi,
                             __nv_bfloat16* __restrict__ lo, int n4)
{
    int i = blockIdx.x * blockDim.x + threadIdx.x;
    if (i >= n4) return;
    float4 v = ((const float4*)src)[i];
    uint2 h, l;
    split4(v, h, l);
    ((uint2*)hi)[i] = h;
    ((uint2*)lo)[i] = l;
}

// ---------------------------------------------------------------------------
// Kernel: split-bf16 tensor-core GEMM, 256x128 CTA tile (unchanged, proven).
// ---------------------------------------------------------------------------
#define GSTAGE_BYTES 98304
#define GEMM_SMEM (2 * GSTAGE_BYTES)

__global__ __launch_bounds__(256, 1)
void gemm_bf16(const __nv_bfloat16* __restrict__ Ah,
               const __nv_bfloat16* __restrict__ Al,
               const __nv_bfloat16* __restrict__ Bh,
               const __nv_bfloat16* __restrict__ Bl,
               const float* __restrict__ bias,
               float* __restrict__ Cf,
               __nv_bfloat16* __restrict__ Chi,
               __nv_bfloat16* __restrict__ Clo,
               int M, int N, int K, int splitOut)
{
    extern __shared__ __align__(128) char smem[];
    const uint32_t sb = smem_u32(smem);
    const int tid = threadIdx.x, wid = tid >> 5, lane = tid & 31;
    const int brow = blockIdx.y * 256, bcol = blockIdx.x * 128;

    const int r0 = tid >> 3, lseg = tid & 7;
    const uint32_t sw0 = sw128((uint32_t)r0 * 128 + lseg * 16);
    const size_t aBase = (size_t)(brow + r0) * K;
    const size_t bBase = (size_t)(bcol + r0) * K;
    const int esel = lseg * 8;
    const size_t rstep = (size_t)32 * K;

    auto issue = [&](int c) {
        const uint32_t sdst = sb + (c & 1) * GSTAGE_BYTES;
        const size_t ebase = (size_t)c * 64 + esel;
#pragma unroll
        for (int j = 0; j < 8; j++) {
            const uint32_t off = sw0 + j * 4096;
            const size_t ao = aBase + j * rstep + ebase;
            cp16(sdst +         off, Ah + ao);
            cp16(sdst + 32768 + off, Al + ao);
        }
#pragma unroll
        for (int j = 0; j < 4; j++) {
            const uint32_t off = sw0 + j * 4096;
            const size_t bo = bBase + j * rstep + ebase;
            cp16(sdst + 65536 + off, Bh + bo);
            cp16(sdst + 81920 + off, Bl + bo);
        }
        cp_commit();
    };

    issue(0);

    float acc[4][8][4];
#pragma unroll
    for (int a = 0; a < 4; a++)
#pragma unroll
        for (int b = 0; b < 8; b++)
#pragma unroll
            for (int cc = 0; cc < 4; cc++) acc[a][b][cc] = 0.f;

    const int mb = (wid >> 1) * 64, nb = (wid & 1) * 64;
    const int laneA_row = mb + (lane & 15);
    const uint32_t laneA_k = (lane >> 4) * 16;
    const int laneB_row = nb + ((lane >> 4) << 3) + (lane & 7);
    const uint32_t laneB_k = ((lane >> 3) & 1) * 16;

    const int nCh = K >> 6;
    for (int c = 0; c < nCh; c++) {
        cp_wait0();
        __syncthreads();
        if (c + 1 < nCh) issue(c + 1);

        const uint32_t s = sb + (c & 1) * GSTAGE_BYTES;
#pragma unroll
        for (int ks = 0; ks < 4; ks++) {
            uint32_t bh[8][2], bl[8][2];
#pragma unroll
            for (int ntp = 0; ntp < 4; ntp++) {
                uint32_t byte = (uint32_t)(laneB_row + ntp * 16) * 128 + ks * 32 + laneB_k;
                uint32_t sw = sw128(byte);
                uint32_t r[4];
                ldm_x4(r, s + 65536 + sw);
                bh[2 * ntp][0] = r[0]; bh[2 * ntp][1] = r[1];
                bh[2 * ntp + 1][0] = r[2]; bh[2 * ntp + 1][1] = r[3];
                ldm_x4(r, s + 81920 + sw);
                bl[2 * ntp][0] = r[0]; bl[2 * ntp][1] = r[1];
                bl[2 * ntp + 1][0] = r[2]; bl[2 * ntp + 1][1] = r[3];
            }
#pragma unroll
            for (int mt = 0; mt < 4; mt++) {
                uint32_t byte = (uint32_t)(laneA_row + mt * 16) * 128 + ks * 32 + laneA_k;
                uint32_t sw = sw128(byte);
                uint32_t ah[4], al[4];
                ldm_x4(ah, s + sw);
                ldm_x4(al, s + 32768 + sw);
#pragma unroll
                for (int nt = 0; nt < 8; nt++) mma16816(acc[mt][nt], ah, bh[nt]);
#pragma unroll
                for (int nt = 0; nt < 8; nt++) mma16816(acc[mt][nt], ah, bl[nt]);
#pragma unroll
                for (int nt = 0; nt < 8; nt++) mma16816(acc[mt][nt], al, bh[nt]);
            }
        }
    }

#pragma unroll
    for (int mt = 0; mt < 4; mt++) {
        const int rr0 = brow + mb + mt * 16 + (lane >> 2);
        const int rr1 = rr0 + 8;
#pragma unroll
        for (int nt = 0; nt < 8; nt++) {
            const int col = bcol + nb + nt * 8 + (lane & 3) * 2;
            float2 bv = *(const float2*)(bias + col);
            if (splitOut) {
                uint32_t hi, lo;
                if (rr0 < M) {
                    split2(acc[mt][nt][0] + bv.x, acc[mt][nt][1] + bv.y, hi, lo);
                    *(uint32_t*)(Chi + (size_t)rr0 * N + col) = hi;
                    *(uint32_t*)(Clo + (size_t)rr0 * N + col) = lo;
                }
                if (rr1 < M) {
                    split2(acc[mt][nt][2] + bv.x, acc[mt][nt][3] + bv.y, hi, lo);
                    *(uint32_t*)(Chi + (size_t)rr1 * N + col) = hi;
                    *(uint32_t*)(Clo + (size_t)rr1 * N + col) = lo;
                }
            } else {
                if (rr0 < M) {
                    float2 o = make_float2(acc[mt][nt][0] + bv.x, acc[mt][nt][1] + bv.y);
                    *(float2*)(Cf + (size_t)rr0 * N + col) = o;
                }
                if (rr1 < M) {
                    float2 o = make_float2(acc[mt][nt][2] + bv.x, acc[mt][nt][3] + bv.y);
                    *(float2*)(Cf + (size_t)rr1 * N + col) = o;
                }
            }
        }
    }
}

// ---------------------------------------------------------------------------
// Kernel: tensor-core sliding-window flash attention (split-bf16).
// 128 queries x 1 head per CTA, 256 threads (8 warps, warp = 16q x 64k).
// Window span per CTA = 384 tokens + regs -> ~42% fewer K/V bytes than 64q.
// smem: Q 32KB + 2-stage K/V ring 2x32KB = 96KB -> 2 CTAs/SM.
// ---------------------------------------------------------------------------
#define ATTN_SMEM (32768 + 2 * 32768)

__global__ __launch_bounds__(256)
void attn_tc(const __nv_bfloat16* __restrict__ qh,
             const __nv_bfloat16* __restrict__ ql,
             __nv_bfloat16* __restrict__ oh,
             __nv_bfloat16* __restrict__ ol)
{
    extern __shared__ __align__(1024) char asmem[];
    const uint32_t sbase = smem_u32(asmem);
    const uint32_t sQh = sbase, sQl = sbase + 16384;

    const int b  = blockIdx.z, h = blockIdx.y;
    const int qb = blockIdx.x * 128;
    const int tid = threadIdx.x, warp = tid >> 5, lane = tid & 31;
    const size_t bbase = (size_t)b * T_ * QKVW_;
    const int hcol = h * HD_;

    const int kstart = max(0, qb - HALF_);
    const int kend   = min(S_, qb + 128 + HALF_);
    const int nchunks = 1 + ((kend - kstart) >> 6);   // chunk 0 = regs only

    // ---- K/V chunk loader: 8 cp16 per thread (4 planes x 64 rows x 8 segs) ----
    auto issueKV = [&](int c) {
        const uint32_t kvb = sbase + 32768 + (c & 1) * 32768;
#pragma unroll
        for (int i = 0; i < 8; i++) {
            int slot = tid + i * 256;          // 0..2047
            int plane = slot >> 9;             // 0=Kh 1=Kl 2=Vh 3=Vl
            int s2 = slot & 511;
            int row = s2 >> 3, seg = s2 & 7;
            int grow;
            if (c == 0) grow = (row < R_) ? row : 0;
            else        grow = R_ + kstart + (c - 1) * 64 + row;
            const __nv_bfloat16* pl = (plane & 1) ? ql : qh;
            const __nv_bfloat16* src = pl + bbase + (size_t)grow * QKVW_ +
                                       ((plane >> 1) + 1) * D_ + hcol + seg * 8;
            cp16(kvb + plane * 8192 + sw128((uint32_t)row * 128 + seg * 16), src);
        }
        cp_commit();
    };

    // ---- Q load (2 planes x 128 rows x 8 segs) folded into group 0 ----
    {
#pragma unroll
        for (int i = 0; i < 8; i++) {
            int slot = tid + i * 256;          // 0..2047
            int plane = slot >> 10;            // 0=Qh 1=Ql
            int s2 = slot & 1023;
            int row = s2 >> 3, seg = s2 & 7;
            const __nv_bfloat16* pl = plane ? ql : qh;
            const __nv_bfloat16* src = pl + bbase + (size_t)(R_ + qb + row) * QKVW_ +
                                       hcol + seg * 8;
            cp16((plane ? sQl : sQh) + sw128((uint32_t)row * 128 + seg * 16), src);
        }
        issueKV(0);   // commits group 0 = Q + KV chunk 0
    }

    float oacc[8][4];
    float m[2] = {-1e30f, -1e30f}, lsum[2] = {0.f, 0.f};
#pragma unroll
    for (int nt = 0; nt < 8; nt++)
#pragma unroll
        for (int e = 0; e < 4; e++) oacc[nt][e] = 0.f;

    const int qtok0 = qb + warp * 16 + (lane >> 2);
    const int laneA_row = warp * 16 + (lane & 15);
    const uint32_t laneA_k = (lane >> 4) * 16;

    for (int c = 0; c < nchunks; c++) {
        __syncthreads();                      // stage (c+1)&1 free of chunk c-1 readers
        if (c + 1 < nchunks) { issueKV(c + 1); cp_wait1(); }
        else                 { cp_wait0(); }
        __syncthreads();                      // chunk c visible to all warps

        const uint32_t kvb = sbase + 32768 + (c & 1) * 32768;
        const uint32_t sKh = kvb, sKl = kvb + 8192;
        const uint32_t sVh = kvb + 16384, sVl = kvb + 24576;

        // ---- S = Q K^T ----
        float sacc[8][4];
#pragma unroll
        for (int nt = 0; nt < 8; nt++)
#pragma unroll
            for (int e = 0; e < 4; e++) sacc[nt][e] = 0.f;

#pragma unroll
        for (int ks = 0; ks < 4; ks++) {
            uint32_t ah[4], al[4];
            uint32_t qoff = sw128((uint32_t)laneA_row * 128 + ks * 32 + laneA_k);
            ldm_x4(ah, sQh + qoff);
            ldm_x4(al, sQl + qoff);
            uint32_t bh[8][2], bl[8][2];
#pragma unroll
            for (int ntp = 0; ntp < 4; ntp++) {
                uint32_t row = ntp * 16 + ((lane >> 4) << 3) + (lane & 7);
                uint32_t off = sw128(row * 128 + ks * 32 + ((lane >> 3) & 1) * 16);
                uint32_t r[4];
                ldm_x4(r, sKh + off);
                bh[2 * ntp][0] = r[0]; bh[2 * ntp][1] = r[1];
                bh[2 * ntp + 1][0] = r[2]; bh[2 * ntp + 1][1] = r[3];
                ldm_x4(r, sKl + off);
                bl[2 * ntp][0] = r[0]; bl[2 * ntp][1] = r[1];
                bl[2 * ntp + 1][0] = r[2]; bl[2 * ntp + 1][1] = r[3];
            }
#pragma unroll
            for (int nt = 0; nt < 8; nt++) mma16816(sacc[nt], ah, bh[nt]);
#pragma unroll
            for (int nt = 0; nt < 8; nt++) mma16816(sacc[nt], ah, bl[nt]);
#pragma unroll
            for (int nt = 0; nt < 8; nt++) mma16816(sacc[nt], al, bh[nt]);
        }

        // ---- scale + mask ----
        const int colbase = kstart + (c - 1) * 64;
        const int col2 = 2 * (lane & 3);
#pragma unroll
        for (int nt = 0; nt < 8; nt++) {
#pragma unroll
            for (int e = 0; e < 4; e++) {
                int klocal = nt * 8 + col2 + (e & 1);
                int qtok = qtok0 + (e >> 1) * 8;
                bool valid;
                if (c == 0) {
                    valid = klocal < R_;
                } else {
                    int ktok = colbase + klocal;
                    valid = (ktok >= qtok - HALF_) && (ktok <= qtok + HALF_);
                }
                sacc[nt][e] = valid ? sacc[nt][e] * 0.125f : -1e30f;
            }
        }

        // ---- online softmax ----
        float mx[2] = {-1e30f, -1e30f};
#pragma unroll
        for (int nt = 0; nt < 8; nt++) {
            mx[0] = fmaxf(mx[0], fmaxf(sacc[nt][0], sacc[nt][1]));
            mx[1] = fmaxf(mx[1], fmaxf(sacc[nt][2], sacc[nt][3]));
        }
#pragma unroll
        for (int i = 0; i < 2; i++) {
            mx[i] = fmaxf(mx[i], __shfl_xor_sync(0xffffffffu, mx[i], 1));
            mx[i] = fmaxf(mx[i], __shfl_xor_sync(0xffffffffu, mx[i], 2));
        }
        float corr[2], ps[2] = {0.f, 0.f};
#pragma unroll
        for (int i = 0; i < 2; i++) {
            float mn = fmaxf(m[i], mx[i]);
            corr[i] = __expf(m[i] - mn);
            m[i] = mn;
        }
#pragma unroll
        for (int nt = 0; nt < 8; nt++) {
            sacc[nt][0] = __expf(sacc[nt][0] - m[0]);
            sacc[nt][1] = __expf(sacc[nt][1] - m[0]);
            sacc[nt][2] = __expf(sacc[nt][2] - m[1]);
            sacc[nt][3] = __expf(sacc[nt][3] - m[1]);
            ps[0] += sacc[nt][0] + sacc[nt][1];
            ps[1] += sacc[nt][2] + sacc[nt][3];
        }
#pragma unroll
        for (int i = 0; i < 2; i++) {
            ps[i] += __shfl_xor_sync(0xffffffffu, ps[i], 1);
            ps[i] += __shfl_xor_sync(0xffffffffu, ps[i], 2);
            lsum[i] = lsum[i] * corr[i] + ps[i];
        }
#pragma unroll
        for (int nt = 0; nt < 8; nt++) {
            oacc[nt][0] *= corr[0]; oacc[nt][1] *= corr[0];
            oacc[nt][2] *= corr[1]; oacc[nt][3] *= corr[1];
        }

        // ---- pack P into A fragments (hi/lo) ----
        uint32_t aph[4][4], apl[4][4];
#pragma unroll
        for (int ks = 0; ks < 4; ks++) {
            split2(sacc[2 * ks][0],     sacc[2 * ks][1],     aph[ks][0], apl[ks][0]);
            split2(sacc[2 * ks][2],     sacc[2 * ks][3],     aph[ks][1], apl[ks][1]);
            split2(sacc[2 * ks + 1][0], sacc[2 * ks + 1][1], aph[ks][2], apl[ks][2]);
            split2(sacc[2 * ks + 1][2], sacc[2 * ks + 1][3], aph[ks][3], apl[ks][3]);
        }

        // ---- O += P V ----
#pragma unroll
        for (int ks = 0; ks < 4; ks++) {
            uint32_t bvh[8][2], bvl[8][2];
#pragma unroll
            for (int ntp = 0; ntp < 4; ntp++) {
                uint32_t row = ks * 16 + ((lane >> 3) & 1) * 8 + (lane & 7);
                uint32_t off = sw128(row * 128 + ntp * 32 + (lane >> 4) * 16);
                uint32_t r[4];
                ldm_x4_t(r, sVh + off);
                bvh[2 * ntp][0] = r[0]; bvh[2 * ntp][1] = r[1];
                bvh[2 * ntp + 1][0] = r[2]; bvh[2 * ntp + 1][1] = r[3];
                ldm_x4_t(r, sVl + off);
                bvl[2 * ntp][0] = r[0]; bvl[2 * ntp][1] = r[1];
                bvl[2 * ntp + 1][0] = r[2]; bvl[2 * ntp + 1][1] = r[3];
            }
#pragma unroll
            for (int nt = 0; nt < 8; nt++) mma16816(oacc[nt], aph[ks], bvh[nt]);
#pragma unroll
            for (int nt = 0; nt < 8; nt++) mma16816(oacc[nt], aph[ks], bvl[nt]);
#pragma unroll
            for (int nt = 0; nt < 8; nt++) mma16816(oacc[nt], apl[ks], bvh[nt]);
        }
    }

    const float inv0 = 1.0f / lsum[0];
    const float inv1 = 1.0f / lsum[1];
    const int tok0 = qb + warp * 16 + (lane >> 2);
#pragma unroll
    for (int nt = 0; nt < 8; nt++) {
        const int d0 = nt * 8 + 2 * (lane & 3);
        size_t i0 = ((size_t)b * S_ + tok0) * D_ + h * HD_ + d0;
        size_t i1 = ((size_t)b * S_ + tok0 + 8) * D_ + h * HD_ + d0;
        uint32_t hi, lo;
        split2(oacc[nt][0] * inv0, oacc[nt][1] * inv0, hi, lo);
        *(uint32_t*)(oh + i0) = hi;
        *(uint32_t*)(ol + i0) = lo;
        split2(oacc[nt][2] * inv1, oacc[nt][3] * inv1, hi, lo);
        *(uint32_t*)(oh + i1) = hi;
        *(uint32_t*)(ol + i1) = lo;
    }
}

// ---------------------------------------------------------------------------
// Launch
// ---------------------------------------------------------------------------
extern "C" void kernel_launch(void* const* d_in, const int* in_sizes, int n_in,
                              void* d_out, int out_size)
{
    const float* x      = (const float*)d_in[0];
    const float* ada    = (const float*)d_in[1];
    const float* regs   = (const float*)d_in[2];
    const float* W_qkv  = (const float*)d_in[3];
    const float* b_qkv  = (const float*)d_in[4];
    const float* W_out  = (const float*)d_in[5];
    const float* b_out  = (const float*)d_in[6];
    float* out = (float*)d_out;

    __nv_bfloat16 *xrh, *xrl, *wqh, *wql, *woh, *wol, *ath, *atl, *qvh, *qvl;
    cudaGetSymbolAddress((void**)&xrh, g_xr_hi);
    cudaGetSymbolAddress((void**)&xrl, g_xr_lo);
    cudaGetSymbolAddress((void**)&wqh, g_wq_hi);
    cudaGetSymbolAddress((void**)&wql, g_wq_lo);
    cudaGetSymbolAddress((void**)&woh, g_wo_hi);
    cudaGetSymbolAddress((void**)&wol, g_wo_lo);
    cudaGetSymbolAddress((void**)&ath, g_at_hi);
    cudaGetSymbolAddress((void**)&atl, g_at_lo);
    cudaGetSymbolAddress((void**)&qvh, g_qkv_hi);
    cudaGetSymbolAddress((void**)&qvl, g_qkv_lo);

    cudaFuncSetAttribute(gemm_bf16, cudaFuncAttributeMaxDynamicSharedMemorySize, GEMM_SMEM);
    cudaFuncSetAttribute(attn_tc, cudaFuncAttributeMaxDynamicSharedMemorySize, ATTN_SMEM);

    // 1. splits (xr padded to MPAD_ rows)
    const int n4 = MPAD_ * (D_ / 4);
    build_xr_split<<<(n4 + 255) / 256, 256>>>(x, ada, regs, xrh, xrl);
    const int wq4 = QKVW_ * D_ / 4;
    split_planes<<<(wq4 + 255) / 256, 256>>>(W_qkv, wqh, wql, wq4);
    const int wo4 = D_ * D_ / 4;
    split_planes<<<(wo4 + 255) / 256, 256>>>(W_out, woh, wol, wo4);

    // 2. qkv planes = split(xr @ W_qkv^T + b_qkv) : M=4112, N=3072, K=1024
    gemm_bf16<<<dim3(QKVW_ / 128, MPAD_ / 256), 256, GEMM_SMEM>>>(
        xrh, xrl, wqh, wql, b_qkv, nullptr, qvh, qvl, B_ * T_, QKVW_, D_, 1);

    // 3. windowed attention (128q tiles, pre-split inputs) -> hi/lo planes
    attn_tc<<<dim3(S_ / 128, H_, B_), 256, ATTN_SMEM>>>(qvh, qvl, ath, atl);

    // 4. out = attn @ W_out^T + b_out : M=4096, N=1024, K=1024 (fp32 out)
    gemm_bf16<<<dim3(D_ / 128, (B_ * S_) / 256), 256, GEMM_SMEM>>>(
        ath, atl, woh, wol, b_out, out, nullptr, nullptr, B_ * S_, D_, D_, 0);
}

// round 11
// speedup vs baseline: 1.0558x; 1.0558x over previous
#include <cuda_runtime.h>
#include <cuda_bf16.h>
#include <math.h>
#include <stdint.h>

// Problem constants
#define B_   2
#define S_   2048
#define D_   1024
#define H_   16
#define HD_  64
#define R_   8
#define T_   2056      // S_ + R_
#define HALF_ 128
#define QKVW_ 3072     // 3*D_
#define MPAD_ 4352     // B_*T_ = 4112 padded to multiple of 256

// Scratch (device globals; no allocation allowed)
__device__ __align__(16) __nv_bfloat16 g_xr_hi[(size_t)MPAD_ * D_];
__device__ __align__(16) __nv_bfloat16 g_xr_lo[(size_t)MPAD_ * D_];
__device__ __align__(16) __nv_bfloat16 g_wq_hi[(size_t)QKVW_ * D_];
__device__ __align__(16) __nv_bfloat16 g_wq_lo[(size_t)QKVW_ * D_];
__device__ __align__(16) __nv_bfloat16 g_wo_hi[(size_t)D_ * D_];
__device__ __align__(16) __nv_bfloat16 g_wo_lo[(size_t)D_ * D_];
__device__ __align__(16) __nv_bfloat16 g_at_hi[(size_t)B_ * S_ * D_];
__device__ __align__(16) __nv_bfloat16 g_at_lo[(size_t)B_ * S_ * D_];
__device__ __align__(16) __nv_bfloat16 g_qkv_hi[(size_t)B_ * T_ * QKVW_];
__device__ __align__(16) __nv_bfloat16 g_qkv_lo[(size_t)B_ * T_ * QKVW_];

// ---------------------------------------------------------------------------
// helpers
// ---------------------------------------------------------------------------
__device__ __forceinline__ uint32_t smem_u32(const void* p) {
    uint32_t a;
    asm("{ .reg .u64 t; cvta.to.shared.u64 t, %1; cvt.u32.u64 %0, t; }"
        : "=r"(a) : "l"(p));
    return a;
}
__device__ __forceinline__ uint32_t sw128(uint32_t off) {
    return off ^ ((off >> 3) & 0x70);
}
__device__ __forceinline__ void cp16(uint32_t dst, const void* src) {
    asm volatile("cp.async.cg.shared.global [%0], [%1], 16;"
                 :: "r"(dst), "l"(src) : "memory");
}
__device__ __forceinline__ void cp_commit() {
    asm volatile("cp.async.commit_group;" ::: "memory");
}
__device__ __forceinline__ void cp_wait0() {
    asm volatile("cp.async.wait_group 0;" ::: "memory");
}
__device__ __forceinline__ void cp_wait1() {
    asm volatile("cp.async.wait_group 1;" ::: "memory");
}
__device__ __forceinline__ void ldm_x4(uint32_t* r, uint32_t addr) {
    asm volatile("ldmatrix.sync.aligned.m8n8.x4.shared.b16 {%0,%1,%2,%3}, [%4];"
                 : "=r"(r[0]), "=r"(r[1]), "=r"(r[2]), "=r"(r[3]) : "r"(addr));
}
__device__ __forceinline__ void ldm_x4_t(uint32_t* r, uint32_t addr) {
    asm volatile("ldmatrix.sync.aligned.m8n8.x4.trans.shared.b16 {%0,%1,%2,%3}, [%4];"
                 : "=r"(r[0]), "=r"(r[1]), "=r"(r[2]), "=r"(r[3]) : "r"(addr));
}
__device__ __forceinline__ void mma16816(float* c, const uint32_t* a, const uint32_t* b) {
    asm volatile(
        "mma.sync.aligned.m16n8k16.row.col.f32.bf16.bf16.f32 "
        "{%0,%1,%2,%3}, {%4,%5,%6,%7}, {%8,%9}, {%0,%1,%2,%3};"
        : "+f"(c[0]), "+f"(c[1]), "+f"(c[2]), "+f"(c[3])
        : "r"(a[0]), "r"(a[1]), "r"(a[2]), "r"(a[3]), "r"(b[0]), "r"(b[1]));
}

// pack 4 floats -> hi bf16x4 (uint2) and lo bf16x4 (uint2)
__device__ __forceinline__ void split4(float4 v, uint2& hi, uint2& lo) {
    __nv_bfloat16 h0 = __float2bfloat16_rn(v.x);
    __nv_bfloat16 h1 = __float2bfloat16_rn(v.y);
    __nv_bfloat16 h2 = __float2bfloat16_rn(v.z);
    __nv_bfloat16 h3 = __float2bfloat16_rn(v.w);
    hi.x = ((uint32_t)__bfloat16_as_ushort(h1) << 16) | __bfloat16_as_ushort(h0);
    hi.y = ((uint32_t)__bfloat16_as_ushort(h3) << 16) | __bfloat16_as_ushort(h2);
    __nv_bfloat162 l01 = __floats2bfloat162_rn(v.x - __bfloat162float(h0),
                                               v.y - __bfloat162float(h1));
    __nv_bfloat162 l23 = __floats2bfloat162_rn(v.z - __bfloat162float(h2),
                                               v.w - __bfloat162float(h3));
    lo.x = *(uint32_t*)&l01;
    lo.y = *(uint32_t*)&l23;
}
// pack 2 floats -> hi bf16x2 word and lo bf16x2 word
__device__ __forceinline__ void split2(float a, float b, uint32_t& hi, uint32_t& lo) {
    __nv_bfloat16 h0 = __float2bfloat16_rn(a);
    __nv_bfloat16 h1 = __float2bfloat16_rn(b);
    hi = ((uint32_t)__bfloat16_as_ushort(h1) << 16) | __bfloat16_as_ushort(h0);
    __nv_bfloat162 l = __floats2bfloat162_rn(a - __bfloat162float(h0),
                                             b - __bfloat162float(h1));
    lo = *(uint32_t*)&l;
}

// ---------------------------------------------------------------------------
// Kernel 1 (merged prep): one launch covers
//   [0, n_xr)         : build xr hi/lo (rows >= B_*T_ zero-filled)
//   [n_xr, +wq4)      : split W_qkv
//   [n_xr+wq4, +wo4)  : split W_out
// ---------------------------------------------------------------------------
#define N_XR (MPAD_ * (D_ / 4))
#define N_WQ (QKVW_ * D_ / 4)
#define N_WO (D_ * D_ / 4)
#define N_PREP (N_XR + N_WQ + N_WO)

__global__ void prep_split(const float* __restrict__ x,
                           const float* __restrict__ ada,
                           const float* __restrict__ regs,
                           const float* __restrict__ Wq,
                           const float* __restrict__ Wo,
                           __nv_bfloat16* __restrict__ xh,
                           __nv_bfloat16* __restrict__ xl,
                           __nv_bfloat16* __restrict__ wqh,
                           __nv_bfloat16* __restrict__ wql,
                           __nv_bfloat16* __restrict__ woh,
                           __nv_bfloat16* __restrict__ wol)
{
    int i = blockIdx.x * blockDim.x + threadIdx.x;
    if (i >= N_PREP) return;
    const int D4 = D_ / 4;

    if (i < N_XR) {
        int d4 = i % D4;
        int row = i / D4;
        uint2 hi = make_uint2(0u, 0u), lo = make_uint2(0u, 0u);
        if (row < B_ * T_) {
            int t = row % T_;
            int b = row / T_;
            float4 v;
            if (t < R_) {
                float4 rv = ((const float4*)regs)[t * D4 + d4];
                float4 av = ((const float4*)ada)[b * D4 + d4];
                v = make_float4(rv.x * (1.f + av.x), rv.y * (1.f + av.y),
                                rv.z * (1.f + av.z), rv.w * (1.f + av.w));
            } else {
                v = ((const float4*)x)[((size_t)b * S_ + (t - R_)) * D4 + d4];
            }
            split4(v, hi, lo);
        }
        ((uint2*)xh)[i] = hi;
        ((uint2*)xl)[i] = lo;
    } else if (i < N_XR + N_WQ) {
        int j = i - N_XR;
        float4 v = ((const float4*)Wq)[j];
        uint2 h, l;
        split4(v, h, l);
        ((uint2*)wqh)[j] = h;
        ((uint2*)wql)[j] = l;
    } else {
        int j = i - N_XR - N_WQ;
        float4 v = ((const float4*)Wo)[j];
        uint2 h, l;
        split4(v, h, l);
        ((uint2*)woh)[j] = h;
        ((uint2*)wol)[j] = l;
    }
}

// ---------------------------------------------------------------------------
// Kernel: split-bf16 tensor-core GEMM, 256x128 CTA tile (proven, unchanged).
// ---------------------------------------------------------------------------
#define GSTAGE_BYTES 98304
#define GEMM_SMEM (2 * GSTAGE_BYTES)

__global__ __launch_bounds__(256, 1)
void gemm_bf16(const __nv_bfloat16* __restrict__ Ah,
               const __nv_bfloat16* __restrict__ Al,
               const __nv_bfloat16* __restrict__ Bh,
               const __nv_bfloat16* __restrict__ Bl,
               const float* __restrict__ bias,
               float* __restrict__ Cf,
               __nv_bfloat16* __restrict__ Chi,
               __nv_bfloat16* __restrict__ Clo,
               int M, int N, int K, int splitOut)
{
    extern __shared__ __align__(128) char smem[];
    const uint32_t sb = smem_u32(smem);
    const int tid = threadIdx.x, wid = tid >> 5, lane = tid & 31;
    const int brow = blockIdx.y * 256, bcol = blockIdx.x * 128;

    const int r0 = tid >> 3, lseg = tid & 7;
    const uint32_t sw0 = sw128((uint32_t)r0 * 128 + lseg * 16);
    const size_t aBase = (size_t)(brow + r0) * K;
    const size_t bBase = (size_t)(bcol + r0) * K;
    const int esel = lseg * 8;
    const size_t rstep = (size_t)32 * K;

    auto issue = [&](int c) {
        const uint32_t sdst = sb + (c & 1) * GSTAGE_BYTES;
        const size_t ebase = (size_t)c * 64 + esel;
#pragma unroll
        for (int j = 0; j < 8; j++) {
            const uint32_t off = sw0 + j * 4096;
            const size_t ao = aBase + j * rstep + ebase;
            cp16(sdst +         off, Ah + ao);
            cp16(sdst + 32768 + off, Al + ao);
        }
#pragma unroll
        for (int j = 0; j < 4; j++) {
            const uint32_t off = sw0 + j * 4096;
            const size_t bo = bBase + j * rstep + ebase;
            cp16(sdst + 65536 + off, Bh + bo);
            cp16(sdst + 81920 + off, Bl + bo);
        }
        cp_commit();
    };

    issue(0);

    float acc[4][8][4];
#pragma unroll
    for (int a = 0; a < 4; a++)
#pragma unroll
        for (int b = 0; b < 8; b++)
#pragma unroll
            for (int cc = 0; cc < 4; cc++) acc[a][b][cc] = 0.f;

    const int mb = (wid >> 1) * 64, nb = (wid & 1) * 64;
    const int laneA_row = mb + (lane & 15);
    const uint32_t laneA_k = (lane >> 4) * 16;
    const int laneB_row = nb + ((lane >> 4) << 3) + (lane & 7);
    const uint32_t laneB_k = ((lane >> 3) & 1) * 16;

    const int nCh = K >> 6;
    for (int c = 0; c < nCh; c++) {
        cp_wait0();
        __syncthreads();
        if (c + 1 < nCh) issue(c + 1);

        const uint32_t s = sb + (c & 1) * GSTAGE_BYTES;
#pragma unroll
        for (int ks = 0; ks < 4; ks++) {
            uint32_t bh[8][2], bl[8][2];
#pragma unroll
            for (int ntp = 0; ntp < 4; ntp++) {
                uint32_t byte = (uint32_t)(laneB_row + ntp * 16) * 128 + ks * 32 + laneB_k;
                uint32_t sw = sw128(byte);
                uint32_t r[4];
                ldm_x4(r, s + 65536 + sw);
                bh[2 * ntp][0] = r[0]; bh[2 * ntp][1] = r[1];
                bh[2 * ntp + 1][0] = r[2]; bh[2 * ntp + 1][1] = r[3];
                ldm_x4(r, s + 81920 + sw);
                bl[2 * ntp][0] = r[0]; bl[2 * ntp][1] = r[1];
                bl[2 * ntp + 1][0] = r[2]; bl[2 * ntp + 1][1] = r[3];
            }
#pragma unroll
            for (int mt = 0; mt < 4; mt++) {
                uint32_t byte = (uint32_t)(laneA_row + mt * 16) * 128 + ks * 32 + laneA_k;
                uint32_t sw = sw128(byte);
                uint32_t ah[4], al[4];
                ldm_x4(ah, s + sw);
                ldm_x4(al, s + 32768 + sw);
#pragma unroll
                for (int nt = 0; nt < 8; nt++) mma16816(acc[mt][nt], ah, bh[nt]);
#pragma unroll
                for (int nt = 0; nt < 8; nt++) mma16816(acc[mt][nt], ah, bl[nt]);
#pragma unroll
                for (int nt = 0; nt < 8; nt++) mma16816(acc[mt][nt], al, bh[nt]);
            }
        }
    }

#pragma unroll
    for (int mt = 0; mt < 4; mt++) {
        const int rr0 = brow + mb + mt * 16 + (lane >> 2);
        const int rr1 = rr0 + 8;
#pragma unroll
        for (int nt = 0; nt < 8; nt++) {
            const int col = bcol + nb + nt * 8 + (lane & 3) * 2;
            float2 bv = *(const float2*)(bias + col);
            if (splitOut) {
                uint32_t hi, lo;
                if (rr0 < M) {
                    split2(acc[mt][nt][0] + bv.x, acc[mt][nt][1] + bv.y, hi, lo);
                    *(uint32_t*)(Chi + (size_t)rr0 * N + col) = hi;
                    *(uint32_t*)(Clo + (size_t)rr0 * N + col) = lo;
                }
                if (rr1 < M) {
                    split2(acc[mt][nt][2] + bv.x, acc[mt][nt][3] + bv.y, hi, lo);
                    *(uint32_t*)(Chi + (size_t)rr1 * N + col) = hi;
                    *(uint32_t*)(Clo + (size_t)rr1 * N + col) = lo;
                }
            } else {
                if (rr0 < M) {
                    float2 o = make_float2(acc[mt][nt][0] + bv.x, acc[mt][nt][1] + bv.y);
                    *(float2*)(Cf + (size_t)rr0 * N + col) = o;
                }
                if (rr1 < M) {
                    float2 o = make_float2(acc[mt][nt][2] + bv.x, acc[mt][nt][3] + bv.y);
                    *(float2*)(Cf + (size_t)rr1 * N + col) = o;
                }
            }
        }
    }
}

// ---------------------------------------------------------------------------
// Kernel: tensor-core sliding-window flash attention (split-bf16).
// R9-proven 64q configuration: 64 queries x 1 head, 128 threads (4 warps),
// pre-split bf16 inputs via cp.async, 2-stage K/V ring.
// smem: Q 16KB + 2 stages x 32KB = 80KB.
// ---------------------------------------------------------------------------
#define ATTN_SMEM (16384 + 2 * 32768)

__global__ __launch_bounds__(128)
void attn_tc(const __nv_bfloat16* __restrict__ qh,
             const __nv_bfloat16* __restrict__ ql,
             __nv_bfloat16* __restrict__ oh,
             __nv_bfloat16* __restrict__ ol)
{
    extern __shared__ __align__(1024) char asmem[];
    const uint32_t sbase = smem_u32(asmem);
    const uint32_t sQh = sbase, sQl = sbase + 8192;

    const int b  = blockIdx.z, h = blockIdx.y;
    const int qb = blockIdx.x * 64;
    const int tid = threadIdx.x, warp = tid >> 5, lane = tid & 31;
    const size_t bbase = (size_t)b * T_ * QKVW_;
    const int hcol = h * HD_;

    const int kstart = max(0, qb - HALF_);
    const int kend   = min(S_, qb + 64 + HALF_);
    const int nchunks = 1 + ((kend - kstart) >> 6);   // chunk 0 = regs only

    auto issueKV = [&](int c) {
        const uint32_t kvb = sbase + 16384 + (c & 1) * 32768;
#pragma unroll
        for (int i = 0; i < 16; i++) {
            int slot = tid + i * 128;          // 0..2047
            int plane = slot >> 9;             // 0=Kh 1=Kl 2=Vh 3=Vl
            int s2 = slot & 511;
            int row = s2 >> 3, seg = s2 & 7;
            int grow;
            if (c == 0) grow = (row < R_) ? row : 0;
            else        grow = R_ + kstart + (c - 1) * 64 + row;
            const __nv_bfloat16* pl = (plane & 1) ? ql : qh;
            const __nv_bfloat16* src = pl + bbase + (size_t)grow * QKVW_ +
                                       ((plane >> 1) + 1) * D_ + hcol + seg * 8;
            cp16(kvb + plane * 8192 + sw128((uint32_t)row * 128 + seg * 16), src);
        }
        cp_commit();
    };

    {
#pragma unroll
        for (int i = 0; i < 8; i++) {
            int slot = tid + i * 128;          // 0..1023
            int plane = slot >> 9;             // 0=Qh 1=Ql
            int s2 = slot & 511;
            int row = s2 >> 3, seg = s2 & 7;
            const __nv_bfloat16* pl = plane ? ql : qh;
            const __nv_bfloat16* src = pl + bbase + (size_t)(R_ + qb + row) * QKVW_ +
                                       hcol + seg * 8;
            cp16((plane ? sQl : sQh) + sw128((uint32_t)row * 128 + seg * 16), src);
        }
        issueKV(0);   // commits group 0 = Q + KV chunk 0
    }

    float oacc[8][4];
    float m[2] = {-1e30f, -1e30f}, lsum[2] = {0.f, 0.f};
#pragma unroll
    for (int nt = 0; nt < 8; nt++)
#pragma unroll
        for (int e = 0; e < 4; e++) oacc[nt][e] = 0.f;

    const int qtok0 = qb + warp * 16 + (lane >> 2);
    const int laneA_row = warp * 16 + (lane & 15);
    const uint32_t laneA_k = (lane >> 4) * 16;

    for (int c = 0; c < nchunks; c++) {
        __syncthreads();
        if (c + 1 < nchunks) { issueKV(c + 1); cp_wait1(); }
        else                 { cp_wait0(); }
        __syncthreads();

        const uint32_t kvb = sbase + 16384 + (c & 1) * 32768;
        const uint32_t sKh = kvb, sKl = kvb + 8192;
        const uint32_t sVh = kvb + 16384, sVl = kvb + 24576;

        float sacc[8][4];
#pragma unroll
        for (int nt = 0; nt < 8; nt++)
#pragma unroll
            for (int e = 0; e < 4; e++) sacc[nt][e] = 0.f;

#pragma unroll
        for (int ks = 0; ks < 4; ks++) {
            uint32_t ah[4], al[4];
            uint32_t qoff = sw128((uint32_t)laneA_row * 128 + ks * 32 + laneA_k);
            ldm_x4(ah, sQh + qoff);
            ldm_x4(al, sQl + qoff);
            uint32_t bh[8][2], bl[8][2];
#pragma unroll
            for (int ntp = 0; ntp < 4; ntp++) {
                uint32_t row = ntp * 16 + ((lane >> 4) << 3) + (lane & 7);
                uint32_t off = sw128(row * 128 + ks * 32 + ((lane >> 3) & 1) * 16);
                uint32_t r[4];
                ldm_x4(r, sKh + off);
                bh[2 * ntp][0] = r[0]; bh[2 * ntp][1] = r[1];
                bh[2 * ntp + 1][0] = r[2]; bh[2 * ntp + 1][1] = r[3];
                ldm_x4(r, sKl + off);
                bl[2 * ntp][0] = r[0]; bl[2 * ntp][1] = r[1];
                bl[2 * ntp + 1][0] = r[2]; bl[2 * ntp + 1][1] = r[3];
            }
#pragma unroll
            for (int nt = 0; nt < 8; nt++) mma16816(sacc[nt], ah, bh[nt]);
#pragma unroll
            for (int nt = 0; nt < 8; nt++) mma16816(sacc[nt], ah, bl[nt]);
#pragma unroll
            for (int nt = 0; nt < 8; nt++) mma16816(sacc[nt], al, bh[nt]);
        }

        const int colbase = kstart + (c - 1) * 64;
        const int col2 = 2 * (lane & 3);
#pragma unroll
        for (int nt = 0; nt < 8; nt++) {
#pragma unroll
            for (int e = 0; e < 4; e++) {
                int klocal = nt * 8 + col2 + (e & 1);
                int qtok = qtok0 + (e >> 1) * 8;
                bool valid;
                if (c == 0) {
                    valid = klocal < R_;
                } else {
                    int ktok = colbase + klocal;
                    valid = (ktok >= qtok - HALF_) && (ktok <= qtok + HALF_);
                }
                sacc[nt][e] = valid ? sacc[nt][e] * 0.125f : -1e30f;
            }
        }

        float mx[2] = {-1e30f, -1e30f};
#pragma unroll
        for (int nt = 0; nt < 8; nt++) {
            mx[0] = fmaxf(mx[0], fmaxf(sacc[nt][0], sacc[nt][1]));
            mx[1] = fmaxf(mx[1], fmaxf(sacc[nt][2], sacc[nt][3]));
        }
#pragma unroll
        for (int i = 0; i < 2; i++) {
            mx[i] = fmaxf(mx[i], __shfl_xor_sync(0xffffffffu, mx[i], 1));
            mx[i] = fmaxf(mx[i], __shfl_xor_sync(0xffffffffu, mx[i], 2));
        }
        float corr[2], ps[2] = {0.f, 0.f};
#pragma unroll
        for (int i = 0; i < 2; i++) {
            float mn = fmaxf(m[i], mx[i]);
            corr[i] = __expf(m[i] - mn);
            m[i] = mn;
        }
#pragma unroll
        for (int nt = 0; nt < 8; nt++) {
            sacc[nt][0] = __expf(sacc[nt][0] - m[0]);
            sacc[nt][1] = __expf(sacc[nt][1] - m[0]);
            sacc[nt][2] = __expf(sacc[nt][2] - m[1]);
            sacc[nt][3] = __expf(sacc[nt][3] - m[1]);
            ps[0] += sacc[nt][0] + sacc[nt][1];
            ps[1] += sacc[nt][2] + sacc[nt][3];
        }
#pragma unroll
        for (int i = 0; i < 2; i++) {
            ps[i] += __shfl_xor_sync(0xffffffffu, ps[i], 1);
            ps[i] += __shfl_xor_sync(0xffffffffu, ps[i], 2);
            lsum[i] = lsum[i] * corr[i] + ps[i];
        }
#pragma unroll
        for (int nt = 0; nt < 8; nt++) {
            oacc[nt][0] *= corr[0]; oacc[nt][1] *= corr[0];
            oacc[nt][2] *= corr[1]; oacc[nt][3] *= corr[1];
        }

        uint32_t aph[4][4], apl[4][4];
#pragma unroll
        for (int ks = 0; ks < 4; ks++) {
            split2(sacc[2 * ks][0],     sacc[2 * ks][1],     aph[ks][0], apl[ks][0]);
            split2(sacc[2 * ks][2],     sacc[2 * ks][3],     aph[ks][1], apl[ks][1]);
            split2(sacc[2 * ks + 1][0], sacc[2 * ks + 1][1], aph[ks][2], apl[ks][2]);
            split2(sacc[2 * ks + 1][2], sacc[2 * ks + 1][3], aph[ks][3], apl[ks][3]);
        }

#pragma unroll
        for (int ks = 0; ks < 4; ks++) {
            uint32_t bvh[8][2], bvl[8][2];
#pragma unroll
            for (int ntp = 0; ntp < 4; ntp++) {
                uint32_t row = ks * 16 + ((lane >> 3) & 1) * 8 + (lane & 7);
                uint32_t off = sw128(row * 128 + ntp * 32 + (lane >> 4) * 16);
                uint32_t r[4];
                ldm_x4_t(r, sVh + off);
                bvh[2 * ntp][0] = r[0]; bvh[2 * ntp][1] = r[1];
                bvh[2 * ntp + 1][0] = r[2]; bvh[2 * ntp + 1][1] = r[3];
                ldm_x4_t(r, sVl + off);
                bvl[2 * ntp][0] = r[0]; bvl[2 * ntp][1] = r[1];
                bvl[2 * ntp + 1][0] = r[2]; bvl[2 * ntp + 1][1] = r[3];
            }
#pragma unroll
            for (int nt = 0; nt < 8; nt++) mma16816(oacc[nt], aph[ks], bvh[nt]);
#pragma unroll
            for (int nt = 0; nt < 8; nt++) mma16816(oacc[nt], aph[ks], bvl[nt]);
#pragma unroll
            for (int nt = 0; nt < 8; nt++) mma16816(oacc[nt], apl[ks], bvh[nt]);
        }
    }

    const float inv0 = 1.0f / lsum[0];
    const float inv1 = 1.0f / lsum[1];
    const int tok0 = qb + warp * 16 + (lane >> 2);
#pragma unroll
    for (int nt = 0; nt < 8; nt++) {
        const int d0 = nt * 8 + 2 * (lane & 3);
        size_t i0 = ((size_t)b * S_ + tok0) * D_ + h * HD_ + d0;
        size_t i1 = ((size_t)b * S_ + tok0 + 8) * D_ + h * HD_ + d0;
        uint32_t hi, lo;
        split2(oacc[nt][0] * inv0, oacc[nt][1] * inv0, hi, lo);
        *(uint32_t*)(oh + i0) = hi;
        *(uint32_t*)(ol + i0) = lo;
        split2(oacc[nt][2] * inv1, oacc[nt][3] * inv1, hi, lo);
        *(uint32_t*)(oh + i1) = hi;
        *(uint32_t*)(ol + i1) = lo;
    }
}

// ---------------------------------------------------------------------------
// Launch
// ---------------------------------------------------------------------------
extern "C" void kernel_launch(void* const* d_in, const int* in_sizes, int n_in,
                              void* d_out, int out_size)
{
    const float* x      = (const float*)d_in[0];
    const float* ada    = (const float*)d_in[1];
    const float* regs   = (const float*)d_in[2];
    const float* W_qkv  = (const float*)d_in[3];
    const float* b_qkv  = (const float*)d_in[4];
    const float* W_out  = (const float*)d_in[5];
    const float* b_out  = (const float*)d_in[6];
    float* out = (float*)d_out;

    __nv_bfloat16 *xrh, *xrl, *wqh, *wql, *woh, *wol, *ath, *atl, *qvh, *qvl;
    cudaGetSymbolAddress((void**)&xrh, g_xr_hi);
    cudaGetSymbolAddress((void**)&xrl, g_xr_lo);
    cudaGetSymbolAddress((void**)&wqh, g_wq_hi);
    cudaGetSymbolAddress((void**)&wql, g_wq_lo);
    cudaGetSymbolAddress((void**)&woh, g_wo_hi);
    cudaGetSymbolAddress((void**)&wol, g_wo_lo);
    cudaGetSymbolAddress((void**)&ath, g_at_hi);
    cudaGetSymbolAddress((void**)&atl, g_at_lo);
    cudaGetSymbolAddress((void**)&qvh, g_qkv_hi);
    cudaGetSymbolAddress((void**)&qvl, g_qkv_lo);

    cudaFuncSetAttribute(gemm_bf16, cudaFuncAttributeMaxDynamicSharedMemorySize, GEMM_SMEM);
    cudaFuncSetAttribute(attn_tc, cudaFuncAttributeMaxDynamicSharedMemorySize, ATTN_SMEM);

    // 1. merged prep: build xr planes + split both weight matrices (ONE launch)
    prep_split<<<(N_PREP + 255) / 256, 256>>>(x, ada, regs, W_qkv, W_out,
                                              xrh, xrl, wqh, wql, woh, wol);

    // 2. qkv planes = split(xr @ W_qkv^T + b_qkv) : M=4112, N=3072, K=1024
    gemm_bf16<<<dim3(QKVW_ / 128, MPAD_ / 256), 256, GEMM_SMEM>>>(
        xrh, xrl, wqh, wql, b_qkv, nullptr, qvh, qvl, B_ * T_, QKVW_, D_, 1);

    // 3. windowed attention (64q tiles, pre-split inputs) -> hi/lo planes
    attn_tc<<<dim3(S_ / 64, H_, B_), 128, ATTN_SMEM>>>(qvh, qvl, ath, atl);

    // 4. out = attn @ W_out^T + b_out : M=4096, N=1024, K=1024 (fp32 out)
    gemm_bf16<<<dim3(D_ / 128, (B_ * S_) / 256), 256, GEMM_SMEM>>>(
        ath, atl, woh, wol, b_out, out, nullptr, nullptr, B_ * S_, D_, D_, 0);
}

// round 13
// speedup vs baseline: 1.0843x; 1.0270x over previous
#include <cuda_runtime.h>
#include <cuda_bf16.h>
#include <math.h>
#include <stdint.h>

// Problem constants
#define B_   2
#define S_   2048
#define D_   1024
#define H_   16
#define HD_  64
#define R_   8
#define T_   2056      // S_ + R_
#define HALF_ 128
#define QKVW_ 3072     // 3*D_
#define MPAD_ 4352     // B_*T_ = 4112 padded to multiple of 256

// Scratch (device globals; no allocation allowed)
__device__ __align__(16) __nv_bfloat16 g_xr_hi[(size_t)MPAD_ * D_];
__device__ __align__(16) __nv_bfloat16 g_xr_lo[(size_t)MPAD_ * D_];
__device__ __align__(16) __nv_bfloat16 g_wq_hi[(size_t)QKVW_ * D_];
__device__ __align__(16) __nv_bfloat16 g_wq_lo[(size_t)QKVW_ * D_];
__device__ __align__(16) __nv_bfloat16 g_wo_hi[(size_t)D_ * D_];
__device__ __align__(16) __nv_bfloat16 g_wo_lo[(size_t)D_ * D_];
__device__ __align__(16) __nv_bfloat16 g_at_hi[(size_t)B_ * S_ * D_];
__device__ __align__(16) __nv_bfloat16 g_at_lo[(size_t)B_ * S_ * D_];
__device__ __align__(16) __nv_bfloat16 g_qkv_hi[(size_t)B_ * T_ * QKVW_];
__device__ __align__(16) __nv_bfloat16 g_qkv_lo[(size_t)B_ * T_ * QKVW_];

// ---------------------------------------------------------------------------
// helpers
// ---------------------------------------------------------------------------
__device__ __forceinline__ uint32_t smem_u32(const void* p) {
    uint32_t a;
    asm("{ .reg .u64 t; cvta.to.shared.u64 t, %1; cvt.u32.u64 %0, t; }"
        : "=r"(a) : "l"(p));
    return a;
}
__device__ __forceinline__ uint32_t sw128(uint32_t off) {
    return off ^ ((off >> 3) & 0x70);
}
__device__ __forceinline__ void cp16(uint32_t dst, const void* src) {
    asm volatile("cp.async.cg.shared.global [%0], [%1], 16;"
                 :: "r"(dst), "l"(src) : "memory");
}
__device__ __forceinline__ void cp_commit() {
    asm volatile("cp.async.commit_group;" ::: "memory");
}
__device__ __forceinline__ void cp_wait0() {
    asm volatile("cp.async.wait_group 0;" ::: "memory");
}
__device__ __forceinline__ void cp_wait1() {
    asm volatile("cp.async.wait_group 1;" ::: "memory");
}
__device__ __forceinline__ void ldm_x4(uint32_t* r, uint32_t addr) {
    asm volatile("ldmatrix.sync.aligned.m8n8.x4.shared.b16 {%0,%1,%2,%3}, [%4];"
                 : "=r"(r[0]), "=r"(r[1]), "=r"(r[2]), "=r"(r[3]) : "r"(addr));
}
__device__ __forceinline__ void ldm_x4_t(uint32_t* r, uint32_t addr) {
    asm volatile("ldmatrix.sync.aligned.m8n8.x4.trans.shared.b16 {%0,%1,%2,%3}, [%4];"
                 : "=r"(r[0]), "=r"(r[1]), "=r"(r[2]), "=r"(r[3]) : "r"(addr));
}
__device__ __forceinline__ void mma16816(float* c, const uint32_t* a, const uint32_t* b) {
    asm volatile(
        "mma.sync.aligned.m16n8k16.row.col.f32.bf16.bf16.f32 "
        "{%0,%1,%2,%3}, {%4,%5,%6,%7}, {%8,%9}, {%0,%1,%2,%3};"
        : "+f"(c[0]), "+f"(c[1]), "+f"(c[2]), "+f"(c[3])
        : "r"(a[0]), "r"(a[1]), "r"(a[2]), "r"(a[3]), "r"(b[0]), "r"(b[1]));
}

// pack 4 floats -> hi bf16x4 (uint2) and lo bf16x4 (uint2)
__device__ __forceinline__ void split4(float4 v, uint2& hi, uint2& lo) {
    __nv_bfloat16 h0 = __float2bfloat16_rn(v.x);
    __nv_bfloat16 h1 = __float2bfloat16_rn(v.y);
    __nv_bfloat16 h2 = __float2bfloat16_rn(v.z);
    __nv_bfloat16 h3 = __float2bfloat16_rn(v.w);
    hi.x = ((uint32_t)__bfloat16_as_ushort(h1) << 16) | __bfloat16_as_ushort(h0);
    hi.y = ((uint32_t)__bfloat16_as_ushort(h3) << 16) | __bfloat16_as_ushort(h2);
    __nv_bfloat162 l01 = __floats2bfloat162_rn(v.x - __bfloat162float(h0),
                                               v.y - __bfloat162float(h1));
    __nv_bfloat162 l23 = __floats2bfloat162_rn(v.z - __bfloat162float(h2),
                                               v.w - __bfloat162float(h3));
    lo.x = *(uint32_t*)&l01;
    lo.y = *(uint32_t*)&l23;
}
// pack 2 floats -> hi bf16x2 word and lo bf16x2 word
__device__ __forceinline__ void split2(float a, float b, uint32_t& hi, uint32_t& lo) {
    __nv_bfloat16 h0 = __float2bfloat16_rn(a);
    __nv_bfloat16 h1 = __float2bfloat16_rn(b);
    hi = ((uint32_t)__bfloat16_as_ushort(h1) << 16) | __bfloat16_as_ushort(h0);
    __nv_bfloat162 l = __floats2bfloat162_rn(a - __bfloat162float(h0),
                                             b - __bfloat162float(h1));
    lo = *(uint32_t*)&l;
}

// ---------------------------------------------------------------------------
// Kernel 1 (merged prep): one launch covers xr build + both weight splits
// ---------------------------------------------------------------------------
#define N_XR (MPAD_ * (D_ / 4))
#define N_WQ (QKVW_ * D_ / 4)
#define N_WO (D_ * D_ / 4)
#define N_PREP (N_XR + N_WQ + N_WO)

__global__ void prep_split(const float* __restrict__ x,
                           const float* __restrict__ ada,
                           const float* __restrict__ regs,
                           const float* __restrict__ Wq,
                           const float* __restrict__ Wo,
                           __nv_bfloat16* __restrict__ xh,
                           __nv_bfloat16* __restrict__ xl,
                           __nv_bfloat16* __restrict__ wqh,
                           __nv_bfloat16* __restrict__ wql,
                           __nv_bfloat16* __restrict__ woh,
                           __nv_bfloat16* __restrict__ wol)
{
    int i = blockIdx.x * blockDim.x + threadIdx.x;
    if (i >= N_PREP) return;
    const int D4 = D_ / 4;

    if (i < N_XR) {
        int d4 = i % D4;
        int row = i / D4;
        uint2 hi = make_uint2(0u, 0u), lo = make_uint2(0u, 0u);
        if (row < B_ * T_) {
            int t = row % T_;
            int b = row / T_;
            float4 v;
            if (t < R_) {
                float4 rv = ((const float4*)regs)[t * D4 + d4];
                float4 av = ((const float4*)ada)[b * D4 + d4];
                v = make_float4(rv.x * (1.f + av.x), rv.y * (1.f + av.y),
                                rv.z * (1.f + av.z), rv.w * (1.f + av.w));
            } else {
                v = ((const float4*)x)[((size_t)b * S_ + (t - R_)) * D4 + d4];
            }
            split4(v, hi, lo);
        }
        ((uint2*)xh)[i] = hi;
        ((uint2*)xl)[i] = lo;
    } else if (i < N_XR + N_WQ) {
        int j = i - N_XR;
        float4 v = ((const float4*)Wq)[j];
        uint2 h, l;
        split4(v, h, l);
        ((uint2*)wqh)[j] = h;
        ((uint2*)wql)[j] = l;
    } else {
        int j = i - N_XR - N_WQ;
        float4 v = ((const float4*)Wo)[j];
        uint2 h, l;
        split4(v, h, l);
        ((uint2*)woh)[j] = h;
        ((uint2*)wol)[j] = l;
    }
}

// ---------------------------------------------------------------------------
// Kernel: split-bf16 tensor-core GEMM, 256x128 CTA tile (proven, unchanged).
// ---------------------------------------------------------------------------
#define GSTAGE_BYTES 98304
#define GEMM_SMEM (2 * GSTAGE_BYTES)

__global__ __launch_bounds__(256, 1)
void gemm_bf16(const __nv_bfloat16* __restrict__ Ah,
               const __nv_bfloat16* __restrict__ Al,
               const __nv_bfloat16* __restrict__ Bh,
               const __nv_bfloat16* __restrict__ Bl,
               const float* __restrict__ bias,
               float* __restrict__ Cf,
               __nv_bfloat16* __restrict__ Chi,
               __nv_bfloat16* __restrict__ Clo,
               int M, int N, int K, int splitOut)
{
    extern __shared__ __align__(128) char smem[];
    const uint32_t sb = smem_u32(smem);
    const int tid = threadIdx.x, wid = tid >> 5, lane = tid & 31;
    const int brow = blockIdx.y * 256, bcol = blockIdx.x * 128;

    const int r0 = tid >> 3, lseg = tid & 7;
    const uint32_t sw0 = sw128((uint32_t)r0 * 128 + lseg * 16);
    const size_t aBase = (size_t)(brow + r0) * K;
    const size_t bBase = (size_t)(bcol + r0) * K;
    const int esel = lseg * 8;
    const size_t rstep = (size_t)32 * K;

    auto issue = [&](int c) {
        const uint32_t sdst = sb + (c & 1) * GSTAGE_BYTES;
        const size_t ebase = (size_t)c * 64 + esel;
#pragma unroll
        for (int j = 0; j < 8; j++) {
            const uint32_t off = sw0 + j * 4096;
            const size_t ao = aBase + j * rstep + ebase;
            cp16(sdst +         off, Ah + ao);
            cp16(sdst + 32768 + off, Al + ao);
        }
#pragma unroll
        for (int j = 0; j < 4; j++) {
            const uint32_t off = sw0 + j * 4096;
            const size_t bo = bBase + j * rstep + ebase;
            cp16(sdst + 65536 + off, Bh + bo);
            cp16(sdst + 81920 + off, Bl + bo);
        }
        cp_commit();
    };

    issue(0);

    float acc[4][8][4];
#pragma unroll
    for (int a = 0; a < 4; a++)
#pragma unroll
        for (int b = 0; b < 8; b++)
#pragma unroll
            for (int cc = 0; cc < 4; cc++) acc[a][b][cc] = 0.f;

    const int mb = (wid >> 1) * 64, nb = (wid & 1) * 64;
    const int laneA_row = mb + (lane & 15);
    const uint32_t laneA_k = (lane >> 4) * 16;
    const int laneB_row = nb + ((lane >> 4) << 3) + (lane & 7);
    const uint32_t laneB_k = ((lane >> 3) & 1) * 16;

    const int nCh = K >> 6;
    for (int c = 0; c < nCh; c++) {
        cp_wait0();
        __syncthreads();
        if (c + 1 < nCh) issue(c + 1);

        const uint32_t s = sb + (c & 1) * GSTAGE_BYTES;
#pragma unroll
        for (int ks = 0; ks < 4; ks++) {
            uint32_t bh[8][2], bl[8][2];
#pragma unroll
            for (int ntp = 0; ntp < 4; ntp++) {
                uint32_t byte = (uint32_t)(laneB_row + ntp * 16) * 128 + ks * 32 + laneB_k;
                uint32_t sw = sw128(byte);
                uint32_t r[4];
                ldm_x4(r, s + 65536 + sw);
                bh[2 * ntp][0] = r[0]; bh[2 * ntp][1] = r[1];
                bh[2 * ntp + 1][0] = r[2]; bh[2 * ntp + 1][1] = r[3];
                ldm_x4(r, s + 81920 + sw);
                bl[2 * ntp][0] = r[0]; bl[2 * ntp][1] = r[1];
                bl[2 * ntp + 1][0] = r[2]; bl[2 * ntp + 1][1] = r[3];
            }
#pragma unroll
            for (int mt = 0; mt < 4; mt++) {
                uint32_t byte = (uint32_t)(laneA_row + mt * 16) * 128 + ks * 32 + laneA_k;
                uint32_t sw = sw128(byte);
                uint32_t ah[4], al[4];
                ldm_x4(ah, s + sw);
                ldm_x4(al, s + 32768 + sw);
#pragma unroll
                for (int nt = 0; nt < 8; nt++) mma16816(acc[mt][nt], ah, bh[nt]);
#pragma unroll
                for (int nt = 0; nt < 8; nt++) mma16816(acc[mt][nt], ah, bl[nt]);
#pragma unroll
                for (int nt = 0; nt < 8; nt++) mma16816(acc[mt][nt], al, bh[nt]);
            }
        }
    }

#pragma unroll
    for (int mt = 0; mt < 4; mt++) {
        const int rr0 = brow + mb + mt * 16 + (lane >> 2);
        const int rr1 = rr0 + 8;
#pragma unroll
        for (int nt = 0; nt < 8; nt++) {
            const int col = bcol + nb + nt * 8 + (lane & 3) * 2;
            float2 bv = *(const float2*)(bias + col);
            if (splitOut) {
                uint32_t hi, lo;
                if (rr0 < M) {
                    split2(acc[mt][nt][0] + bv.x, acc[mt][nt][1] + bv.y, hi, lo);
                    *(uint32_t*)(Chi + (size_t)rr0 * N + col) = hi;
                    *(uint32_t*)(Clo + (size_t)rr0 * N + col) = lo;
                }
                if (rr1 < M) {
                    split2(acc[mt][nt][2] + bv.x, acc[mt][nt][3] + bv.y, hi, lo);
                    *(uint32_t*)(Chi + (size_t)rr1 * N + col) = hi;
                    *(uint32_t*)(Clo + (size_t)rr1 * N + col) = lo;
                }
            } else {
                if (rr0 < M) {
                    float2 o = make_float2(acc[mt][nt][0] + bv.x, acc[mt][nt][1] + bv.y);
                    *(float2*)(Cf + (size_t)rr0 * N + col) = o;
                }
                if (rr1 < M) {
                    float2 o = make_float2(acc[mt][nt][2] + bv.x, acc[mt][nt][3] + bv.y);
                    *(float2*)(Cf + (size_t)rr1 * N + col) = o;
                }
            }
        }
    }
}

// ---------------------------------------------------------------------------
// Kernel: tensor-core sliding-window flash attention (split-bf16).
// 64q x 1 head, 128 threads. Dedicated cheap register path (8 reg keys
// padded to 16, 48 MMAs) initializes the online softmax; main loop handles
// only true window chunks (3-5 per CTA instead of 4-6).
// smem: Q 16KB + regK/V 8KB + 2-stage ring 64KB = 88KB.
// ---------------------------------------------------------------------------
#define ATTN_SMEM (16384 + 8192 + 2 * 32768)

__global__ __launch_bounds__(128)
void attn_tc(const __nv_bfloat16* __restrict__ qh,
             const __nv_bfloat16* __restrict__ ql,
             __nv_bfloat16* __restrict__ oh,
             __nv_bfloat16* __restrict__ ol)
{
    extern __shared__ __align__(1024) char asmem[];
    const uint32_t sbase = smem_u32(asmem);
    const uint32_t sQh = sbase, sQl = sbase + 8192;
    const uint32_t sReg = sbase + 16384;            // RKh,RKl,RVh,RVl x 2KB
    const uint32_t sRing = sbase + 24576;

    const int b  = blockIdx.z, h = blockIdx.y;
    const int qb = blockIdx.x * 64;
    const int tid = threadIdx.x, warp = tid >> 5, lane = tid & 31;
    const size_t bbase = (size_t)b * T_ * QKVW_;
    const int hcol = h * HD_;

    const int kstart = max(0, qb - HALF_);
    const int kend   = min(S_, qb + 64 + HALF_);
    const int nwin   = (kend - kstart) >> 6;        // 3..5 window chunks

    // window chunk loader (no register special-case)
    auto issueKV = [&](int c) {
        const uint32_t kvb = sRing + (c & 1) * 32768;
#pragma unroll
        for (int i = 0; i < 16; i++) {
            int slot = tid + i * 128;          // 0..2047
            int plane = slot >> 9;             // 0=Kh 1=Kl 2=Vh 3=Vl
            int s2 = slot & 511;
            int row = s2 >> 3, seg = s2 & 7;
            int grow = R_ + kstart + c * 64 + row;
            const __nv_bfloat16* pl = (plane & 1) ? ql : qh;
            const __nv_bfloat16* src = pl + bbase + (size_t)grow * QKVW_ +
                                       ((plane >> 1) + 1) * D_ + hcol + seg * 8;
            cp16(kvb + plane * 8192 + sw128((uint32_t)row * 128 + seg * 16), src);
        }
        cp_commit();
    };

    // group A: Q (1024 slots) + reg K/V 16 rows x 4 planes (512 slots)
    {
#pragma unroll
        for (int i = 0; i < 8; i++) {
            int slot = tid + i * 128;          // 0..1023
            int plane = slot >> 9;             // 0=Qh 1=Ql
            int s2 = slot & 511;
            int row = s2 >> 3, seg = s2 & 7;
            const __nv_bfloat16* pl = plane ? ql : qh;
            const __nv_bfloat16* src = pl + bbase + (size_t)(R_ + qb + row) * QKVW_ +
                                       hcol + seg * 8;
            cp16((plane ? sQl : sQh) + sw128((uint32_t)row * 128 + seg * 16), src);
        }
#pragma unroll
        for (int i = 0; i < 4; i++) {
            int slot = tid + i * 128;          // 0..511
            int plane = slot >> 7;             // 0=RKh 1=RKl 2=RVh 3=RVl
            int s2 = slot & 127;
            int row = s2 >> 3, seg = s2 & 7;   // rows 0..15 (8..15 dup row 0)
            int grow = (row < R_) ? row : 0;
            const __nv_bfloat16* pl = (plane & 1) ? ql : qh;
            const __nv_bfloat16* src = pl + bbase + (size_t)grow * QKVW_ +
                                       ((plane >> 1) + 1) * D_ + hcol + seg * 8;
            cp16(sReg + plane * 2048 + sw128((uint32_t)row * 128 + seg * 16), src);
        }
        cp_commit();    // group A
        issueKV(0);     // group B
    }

    float oacc[8][4];
    float m[2], lsum[2];
#pragma unroll
    for (int nt = 0; nt < 8; nt++)
#pragma unroll
        for (int e = 0; e < 4; e++) oacc[nt][e] = 0.f;

    const int qtok0 = qb + warp * 16 + (lane >> 2);
    const int laneA_row = warp * 16 + (lane & 15);
    const uint32_t laneA_k = (lane >> 4) * 16;
    const int col2 = 2 * (lane & 3);

    // ---- register path: wait for group A (leaves chunk0 in flight) ----
    cp_wait1();
    __syncthreads();
    {
        float racc[2][4];
#pragma unroll
        for (int nt = 0; nt < 2; nt++)
#pragma unroll
            for (int e = 0; e < 4; e++) racc[nt][e] = 0.f;

#pragma unroll
        for (int ks = 0; ks < 4; ks++) {
            uint32_t ah[4], al[4];
            uint32_t qoff = sw128((uint32_t)laneA_row * 128 + ks * 32 + laneA_k);
            ldm_x4(ah, sQh + qoff);
            ldm_x4(al, sQl + qoff);
            uint32_t row = ((lane >> 4) << 3) + (lane & 7);
            uint32_t off = sw128(row * 128 + ks * 32 + ((lane >> 3) & 1) * 16);
            uint32_t rh[4], rl[4];
            ldm_x4(rh, sReg + off);            // RKh
            ldm_x4(rl, sReg + 2048 + off);     // RKl
            uint32_t bh0[2] = {rh[0], rh[1]}, bh1[2] = {rh[2], rh[3]};
            uint32_t bl0[2] = {rl[0], rl[1]}, bl1[2] = {rl[2], rl[3]};
            mma16816(racc[0], ah, bh0); mma16816(racc[1], ah, bh1);
            mma16816(racc[0], ah, bl0); mma16816(racc[1], ah, bl1);
            mma16816(racc[0], al, bh0); mma16816(racc[1], al, bh1);
        }

        // mask (klocal < R_) + scale
#pragma unroll
        for (int nt = 0; nt < 2; nt++)
#pragma unroll
            for (int e = 0; e < 4; e++) {
                int klocal = nt * 8 + col2 + (e & 1);
                racc[nt][e] = (klocal < R_) ? racc[nt][e] * 0.125f : -1e30f;
            }

        // init online softmax state
        float mx[2];
        mx[0] = fmaxf(fmaxf(racc[0][0], racc[0][1]), fmaxf(racc[1][0], racc[1][1]));
        mx[1] = fmaxf(fmaxf(racc[0][2], racc[0][3]), fmaxf(racc[1][2], racc[1][3]));
#pragma unroll
        for (int i = 0; i < 2; i++) {
            mx[i] = fmaxf(mx[i], __shfl_xor_sync(0xffffffffu, mx[i], 1));
            mx[i] = fmaxf(mx[i], __shfl_xor_sync(0xffffffffu, mx[i], 2));
            m[i] = mx[i];
        }
        float ps[2] = {0.f, 0.f};
#pragma unroll
        for (int nt = 0; nt < 2; nt++) {
            racc[nt][0] = __expf(racc[nt][0] - m[0]);
            racc[nt][1] = __expf(racc[nt][1] - m[0]);
            racc[nt][2] = __expf(racc[nt][2] - m[1]);
            racc[nt][3] = __expf(racc[nt][3] - m[1]);
            ps[0] += racc[nt][0] + racc[nt][1];
            ps[1] += racc[nt][2] + racc[nt][3];
        }
#pragma unroll
        for (int i = 0; i < 2; i++) {
            ps[i] += __shfl_xor_sync(0xffffffffu, ps[i], 1);
            ps[i] += __shfl_xor_sync(0xffffffffu, ps[i], 2);
            lsum[i] = ps[i];
        }

        // pack P (16 keys) into one ks-step of A fragments
        uint32_t aph[4], apl[4];
        split2(racc[0][0], racc[0][1], aph[0], apl[0]);
        split2(racc[0][2], racc[0][3], aph[1], apl[1]);
        split2(racc[1][0], racc[1][1], aph[2], apl[2]);
        split2(racc[1][2], racc[1][3], aph[3], apl[3]);

        // O = P V_reg  (1 ks step)
        uint32_t bvh[8][2], bvl[8][2];
#pragma unroll
        for (int ntp = 0; ntp < 4; ntp++) {
            uint32_t row = ((lane >> 3) & 1) * 8 + (lane & 7);
            uint32_t off = sw128(row * 128 + ntp * 32 + (lane >> 4) * 16);
            uint32_t r[4];
            ldm_x4_t(r, sReg + 4096 + off);    // RVh
            bvh[2 * ntp][0] = r[0]; bvh[2 * ntp][1] = r[1];
            bvh[2 * ntp + 1][0] = r[2]; bvh[2 * ntp + 1][1] = r[3];
            ldm_x4_t(r, sReg + 6144 + off);    // RVl
            bvl[2 * ntp][0] = r[0]; bvl[2 * ntp][1] = r[1];
            bvl[2 * ntp + 1][0] = r[2]; bvl[2 * ntp + 1][1] = r[3];
        }
#pragma unroll
        for (int nt = 0; nt < 8; nt++) mma16816(oacc[nt], aph, bvh[nt]);
#pragma unroll
        for (int nt = 0; nt < 8; nt++) mma16816(oacc[nt], aph, bvl[nt]);
#pragma unroll
        for (int nt = 0; nt < 8; nt++) mma16816(oacc[nt], apl, bvh[nt]);
    }

    // ---- window chunks ----
    for (int c = 0; c < nwin; c++) {
        __syncthreads();
        if (c + 1 < nwin) { issueKV(c + 1); cp_wait1(); }
        else              { cp_wait0(); }
        __syncthreads();

        const uint32_t kvb = sRing + (c & 1) * 32768;
        const uint32_t sKh = kvb, sKl = kvb + 8192;
        const uint32_t sVh = kvb + 16384, sVl = kvb + 24576;

        float sacc[8][4];
#pragma unroll
        for (int nt = 0; nt < 8; nt++)
#pragma unroll
            for (int e = 0; e < 4; e++) sacc[nt][e] = 0.f;

#pragma unroll
        for (int ks = 0; ks < 4; ks++) {
            uint32_t ah[4], al[4];
            uint32_t qoff = sw128((uint32_t)laneA_row * 128 + ks * 32 + laneA_k);
            ldm_x4(ah, sQh + qoff);
            ldm_x4(al, sQl + qoff);
            uint32_t bh[8][2], bl[8][2];
#pragma unroll
            for (int ntp = 0; ntp < 4; ntp++) {
                uint32_t row = ntp * 16 + ((lane >> 4) << 3) + (lane & 7);
                uint32_t off = sw128(row * 128 + ks * 32 + ((lane >> 3) & 1) * 16);
                uint32_t r[4];
                ldm_x4(r, sKh + off);
                bh[2 * ntp][0] = r[0]; bh[2 * ntp][1] = r[1];
                bh[2 * ntp + 1][0] = r[2]; bh[2 * ntp + 1][1] = r[3];
                ldm_x4(r, sKl + off);
                bl[2 * ntp][0] = r[0]; bl[2 * ntp][1] = r[1];
                bl[2 * ntp + 1][0] = r[2]; bl[2 * ntp + 1][1] = r[3];
            }
#pragma unroll
            for (int nt = 0; nt < 8; nt++) mma16816(sacc[nt], ah, bh[nt]);
#pragma unroll
            for (int nt = 0; nt < 8; nt++) mma16816(sacc[nt], ah, bl[nt]);
#pragma unroll
            for (int nt = 0; nt < 8; nt++) mma16816(sacc[nt], al, bh[nt]);
        }

        const int colbase = kstart + c * 64;
#pragma unroll
        for (int nt = 0; nt < 8; nt++) {
#pragma unroll
            for (int e = 0; e < 4; e++) {
                int ktok = colbase + nt * 8 + col2 + (e & 1);
                int qtok = qtok0 + (e >> 1) * 8;
                bool valid = (ktok >= qtok - HALF_) && (ktok <= qtok + HALF_);
                sacc[nt][e] = valid ? sacc[nt][e] * 0.125f : -1e30f;
            }
        }

        float mx[2] = {-1e30f, -1e30f};
#pragma unroll
        for (int nt = 0; nt < 8; nt++) {
            mx[0] = fmaxf(mx[0], fmaxf(sacc[nt][0], sacc[nt][1]));
            mx[1] = fmaxf(mx[1], fmaxf(sacc[nt][2], sacc[nt][3]));
        }
#pragma unroll
        for (int i = 0; i < 2; i++) {
            mx[i] = fmaxf(mx[i], __shfl_xor_sync(0xffffffffu, mx[i], 1));
            mx[i] = fmaxf(mx[i], __shfl_xor_sync(0xffffffffu, mx[i], 2));
        }
        float corr[2], ps[2] = {0.f, 0.f};
#pragma unroll
        for (int i = 0; i < 2; i++) {
            float mn = fmaxf(m[i], mx[i]);
            corr[i] = __expf(m[i] - mn);
            m[i] = mn;
        }
#pragma unroll
        for (int nt = 0; nt < 8; nt++) {
            sacc[nt][0] = __expf(sacc[nt][0] - m[0]);
            sacc[nt][1] = __expf(sacc[nt][1] - m[0]);
            sacc[nt][2] = __expf(sacc[nt][2] - m[1]);
            sacc[nt][3] = __expf(sacc[nt][3] - m[1]);
            ps[0] += sacc[nt][0] + sacc[nt][1];
            ps[1] += sacc[nt][2] + sacc[nt][3];
        }
#pragma unroll
        for (int i = 0; i < 2; i++) {
            ps[i] += __shfl_xor_sync(0xffffffffu, ps[i], 1);
            ps[i] += __shfl_xor_sync(0xffffffffu, ps[i], 2);
            lsum[i] = lsum[i] * corr[i] + ps[i];
        }
#pragma unroll
        for (int nt = 0; nt < 8; nt++) {
            oacc[nt][0] *= corr[0]; oacc[nt][1] *= corr[0];
            oacc[nt][2] *= corr[1]; oacc[nt][3] *= corr[1];
        }

        uint32_t aph[4][4], apl[4][4];
#pragma unroll
        for (int ks = 0; ks < 4; ks++) {
            split2(sacc[2 * ks][0],     sacc[2 * ks][1],     aph[ks][0], apl[ks][0]);
            split2(sacc[2 * ks][2],     sacc[2 * ks][3],     aph[ks][1], apl[ks][1]);
            split2(sacc[2 * ks + 1][0], sacc[2 * ks + 1][1], aph[ks][2], apl[ks][2]);
            split2(sacc[2 * ks + 1][2], sacc[2 * ks + 1][3], aph[ks][3], apl[ks][3]);
        }

#pragma unroll
        for (int ks = 0; ks < 4; ks++) {
            uint32_t bvh[8][2], bvl[8][2];
#pragma unroll
            for (int ntp = 0; ntp < 4; ntp++) {
                uint32_t row = ks * 16 + ((lane >> 3) & 1) * 8 + (lane & 7);
                uint32_t off = sw128(row * 128 + ntp * 32 + (lane >> 4) * 16);
                uint32_t r[4];
                ldm_x4_t(r, sVh + off);
                bvh[2 * ntp][0] = r[0]; bvh[2 * ntp][1] = r[1];
                bvh[2 * ntp + 1][0] = r[2]; bvh[2 * ntp + 1][1] = r[3];
                ldm_x4_t(r, sVl + off);
                bvl[2 * ntp][0] = r[0]; bvl[2 * ntp][1] = r[1];
                bvl[2 * ntp + 1][0] = r[2]; bvl[2 * ntp + 1][1] = r[3];
            }
#pragma unroll
            for (int nt = 0; nt < 8; nt++) mma16816(oacc[nt], aph[ks], bvh[nt]);
#pragma unroll
            for (int nt = 0; nt < 8; nt++) mma16816(oacc[nt], aph[ks], bvl[nt]);
#pragma unroll
            for (int nt = 0; nt < 8; nt++) mma16816(oacc[nt], apl[ks], bvh[nt]);
        }
    }

    const float inv0 = 1.0f / lsum[0];
    const float inv1 = 1.0f / lsum[1];
    const int tok0 = qb + warp * 16 + (lane >> 2);
#pragma unroll
    for (int nt = 0; nt < 8; nt++) {
        const int d0 = nt * 8 + 2 * (lane & 3);
        size_t i0 = ((size_t)b * S_ + tok0) * D_ + h * HD_ + d0;
        size_t i1 = ((size_t)b * S_ + tok0 + 8) * D_ + h * HD_ + d0;
        uint32_t hi, lo;
        split2(oacc[nt][0] * inv0, oacc[nt][1] * inv0, hi, lo);
        *(uint32_t*)(oh + i0) = hi;
        *(uint32_t*)(ol + i0) = lo;
        split2(oacc[nt][2] * inv1, oacc[nt][3] * inv1, hi, lo);
        *(uint32_t*)(oh + i1) = hi;
        *(uint32_t*)(ol + i1) = lo;
    }
}

// ---------------------------------------------------------------------------
// Launch
// ---------------------------------------------------------------------------
extern "C" void kernel_launch(void* const* d_in, const int* in_sizes, int n_in,
                              void* d_out, int out_size)
{
    const float* x      = (const float*)d_in[0];
    const float* ada    = (const float*)d_in[1];
    const float* regs   = (const float*)d_in[2];
    const float* W_qkv  = (const float*)d_in[3];
    const float* b_qkv  = (const float*)d_in[4];
    const float* W_out  = (const float*)d_in[5];
    const float* b_out  = (const float*)d_in[6];
    float* out = (float*)d_out;

    __nv_bfloat16 *xrh, *xrl, *wqh, *wql, *woh, *wol, *ath, *atl, *qvh, *qvl;
    cudaGetSymbolAddress((void**)&xrh, g_xr_hi);
    cudaGetSymbolAddress((void**)&xrl, g_xr_lo);
    cudaGetSymbolAddress((void**)&wqh, g_wq_hi);
    cudaGetSymbolAddress((void**)&wql, g_wq_lo);
    cudaGetSymbolAddress((void**)&woh, g_wo_hi);
    cudaGetSymbolAddress((void**)&wol, g_wo_lo);
    cudaGetSymbolAddress((void**)&ath, g_at_hi);
    cudaGetSymbolAddress((void**)&atl, g_at_lo);
    cudaGetSymbolAddress((void**)&qvh, g_qkv_hi);
    cudaGetSymbolAddress((void**)&qvl, g_qkv_lo);

    cudaFuncSetAttribute(gemm_bf16, cudaFuncAttributeMaxDynamicSharedMemorySize, GEMM_SMEM);
    cudaFuncSetAttribute(attn_tc, cudaFuncAttributeMaxDynamicSharedMemorySize, ATTN_SMEM);

    // 1. merged prep
    prep_split<<<(N_PREP + 255) / 256, 256>>>(x, ada, regs, W_qkv, W_out,
                                              xrh, xrl, wqh, wql, woh, wol);

    // 2. qkv planes = split(xr @ W_qkv^T + b_qkv) : M=4112, N=3072, K=1024
    gemm_bf16<<<dim3(QKVW_ / 128, MPAD_ / 256), 256, GEMM_SMEM>>>(
        xrh, xrl, wqh, wql, b_qkv, nullptr, qvh, qvl, B_ * T_, QKVW_, D_, 1);

    // 3. windowed attention (64q tiles, register fast path) -> hi/lo planes
    attn_tc<<<dim3(S_ / 64, H_, B_), 128, ATTN_SMEM>>>(qvh, qvl, ath, atl);

    // 4. out = attn @ W_out^T + b_out : M=4096, N=1024, K=1024 (fp32 out)
    gemm_bf16<<<dim3(D_ / 128, (B_ * S_) / 256), 256, GEMM_SMEM>>>(
        ath, atl, woh, wol, b_out, out, nullptr, nullptr, B_ * S_, D_, D_, 0);
}

// round 14
// speedup vs baseline: 1.3888x; 1.2809x over previous
#include <cuda_runtime.h>
#include <cuda_fp16.h>
#include <math.h>
#include <stdint.h>

// Problem constants
#define B_   2
#define S_   2048
#define D_   1024
#define H_   16
#define HD_  64
#define R_   8
#define T_   2056      // S_ + R_
#define HALF_ 128
#define QKVW_ 3072     // 3*D_
#define MPAD_ 4352     // B_*T_ = 4112 padded to multiple of 256

// Scratch (device globals; no allocation allowed)
__device__ __align__(16) __half g_xr_hi[(size_t)MPAD_ * D_];
__device__ __align__(16) __half g_xr_lo[(size_t)MPAD_ * D_];
__device__ __align__(16) __half g_wq_hi[(size_t)QKVW_ * D_];
__device__ __align__(16) __half g_wo_hi[(size_t)D_ * D_];
__device__ __align__(16) __half g_at_hi[(size_t)B_ * S_ * D_];
__device__ __align__(16) __half g_at_lo[(size_t)B_ * S_ * D_];
__device__ __align__(16) __half g_qkv_hi[(size_t)B_ * T_ * QKVW_];
__device__ __align__(16) __half g_qkv_lo[(size_t)B_ * T_ * QKVW_];

// ---------------------------------------------------------------------------
// helpers
// ---------------------------------------------------------------------------
__device__ __forceinline__ uint32_t smem_u32(const void* p) {
    uint32_t a;
    asm("{ .reg .u64 t; cvta.to.shared.u64 t, %1; cvt.u32.u64 %0, t; }"
        : "=r"(a) : "l"(p));
    return a;
}
__device__ __forceinline__ uint32_t sw128(uint32_t off) {
    return off ^ ((off >> 3) & 0x70);
}
__device__ __forceinline__ void cp16(uint32_t dst, const void* src) {
    asm volatile("cp.async.cg.shared.global [%0], [%1], 16;"
                 :: "r"(dst), "l"(src) : "memory");
}
__device__ __forceinline__ void cp_commit() {
    asm volatile("cp.async.commit_group;" ::: "memory");
}
__device__ __forceinline__ void cp_wait0() {
    asm volatile("cp.async.wait_group 0;" ::: "memory");
}
__device__ __forceinline__ void cp_wait1() {
    asm volatile("cp.async.wait_group 1;" ::: "memory");
}
__device__ __forceinline__ void ldm_x4(uint32_t* r, uint32_t addr) {
    asm volatile("ldmatrix.sync.aligned.m8n8.x4.shared.b16 {%0,%1,%2,%3}, [%4];"
                 : "=r"(r[0]), "=r"(r[1]), "=r"(r[2]), "=r"(r[3]) : "r"(addr));
}
__device__ __forceinline__ void ldm_x4_t(uint32_t* r, uint32_t addr) {
    asm volatile("ldmatrix.sync.aligned.m8n8.x4.trans.shared.b16 {%0,%1,%2,%3}, [%4];"
                 : "=r"(r[0]), "=r"(r[1]), "=r"(r[2]), "=r"(r[3]) : "r"(addr));
}
// fp16 inputs, fp32 accumulate
__device__ __forceinline__ void mma16816(float* c, const uint32_t* a, const uint32_t* b) {
    asm volatile(
        "mma.sync.aligned.m16n8k16.row.col.f32.f16.f16.f32 "
        "{%0,%1,%2,%3}, {%4,%5,%6,%7}, {%8,%9}, {%0,%1,%2,%3};"
        : "+f"(c[0]), "+f"(c[1]), "+f"(c[2]), "+f"(c[3])
        : "r"(a[0]), "r"(a[1]), "r"(a[2]), "r"(a[3]), "r"(b[0]), "r"(b[1]));
}

// pack 4 floats -> hi fp16x4 (uint2) and lo fp16x4 (uint2)
__device__ __forceinline__ void split4(float4 v, uint2& hi, uint2& lo) {
    __half h0 = __float2half_rn(v.x);
    __half h1 = __float2half_rn(v.y);
    __half h2 = __float2half_rn(v.z);
    __half h3 = __float2half_rn(v.w);
    hi.x = ((uint32_t)__half_as_ushort(h1) << 16) | __half_as_ushort(h0);
    hi.y = ((uint32_t)__half_as_ushort(h3) << 16) | __half_as_ushort(h2);
    __half2 l01 = __floats2half2_rn(v.x - __half2float(h0),
                                    v.y - __half2float(h1));
    __half2 l23 = __floats2half2_rn(v.z - __half2float(h2),
                                    v.w - __half2float(h3));
    lo.x = *(uint32_t*)&l01;
    lo.y = *(uint32_t*)&l23;
}
// hi-only fp16x4
__device__ __forceinline__ uint2 round4h(float4 v) {
    uint2 hi;
    __half2 p01 = __floats2half2_rn(v.x, v.y);
    __half2 p23 = __floats2half2_rn(v.z, v.w);
    hi.x = *(uint32_t*)&p01;
    hi.y = *(uint32_t*)&p23;
    return hi;
}
// pack 2 floats -> hi fp16x2 word and lo fp16x2 word
__device__ __forceinline__ void split2(float a, float b, uint32_t& hi, uint32_t& lo) {
    __half h0 = __float2half_rn(a);
    __half h1 = __float2half_rn(b);
    hi = ((uint32_t)__half_as_ushort(h1) << 16) | __half_as_ushort(h0);
    __half2 l = __floats2half2_rn(a - __half2float(h0),
                                  b - __half2float(h1));
    lo = *(uint32_t*)&l;
}

// ---------------------------------------------------------------------------
// Kernel 1 (merged prep): xr build (hi/lo) + weight rounds (hi only)
// ---------------------------------------------------------------------------
#define N_XR (MPAD_ * (D_ / 4))
#define N_WQ (QKVW_ * D_ / 4)
#define N_WO (D_ * D_ / 4)
#define N_PREP (N_XR + N_WQ + N_WO)

__global__ void prep_split(const float* __restrict__ x,
                           const float* __restrict__ ada,
                           const float* __restrict__ regs,
                           const float* __restrict__ Wq,
                           const float* __restrict__ Wo,
                           __half* __restrict__ xh,
                           __half* __restrict__ xl,
                           __half* __restrict__ wqh,
                           __half* __restrict__ woh)
{
    int i = blockIdx.x * blockDim.x + threadIdx.x;
    if (i >= N_PREP) return;
    const int D4 = D_ / 4;

    if (i < N_XR) {
        int d4 = i % D4;
        int row = i / D4;
        uint2 hi = make_uint2(0u, 0u), lo = make_uint2(0u, 0u);
        if (row < B_ * T_) {
            int t = row % T_;
            int b = row / T_;
            float4 v;
            if (t < R_) {
                float4 rv = ((const float4*)regs)[t * D4 + d4];
                float4 av = ((const float4*)ada)[b * D4 + d4];
                v = make_float4(rv.x * (1.f + av.x), rv.y * (1.f + av.y),
                                rv.z * (1.f + av.z), rv.w * (1.f + av.w));
            } else {
                v = ((const float4*)x)[((size_t)b * S_ + (t - R_)) * D4 + d4];
            }
            split4(v, hi, lo);
        }
        ((uint2*)xh)[i] = hi;
        ((uint2*)xl)[i] = lo;
    } else if (i < N_XR + N_WQ) {
        int j = i - N_XR;
        ((uint2*)wqh)[j] = round4h(((const float4*)Wq)[j]);
    } else {
        int j = i - N_XR - N_WQ;
        ((uint2*)woh)[j] = round4h(((const float4*)Wo)[j]);
    }
}

// ---------------------------------------------------------------------------
// Kernel: 2-term fp16 tensor-core GEMM, 256x128 CTA tile.
// C[M,N] = (Ah + Al) @ Bh^T + bias.
// Stage layout: [Ah 32K][Al 32K][Bh 16K] = 80KB; 2 stages = 160KB.
// ---------------------------------------------------------------------------
#define GSTAGE_BYTES 81920
#define GEMM_SMEM (2 * GSTAGE_BYTES)

__global__ __launch_bounds__(256, 1)
void gemm_fp16(const __half* __restrict__ Ah,
               const __half* __restrict__ Al,
               const __half* __restrict__ Bh,
               const float* __restrict__ bias,
               float* __restrict__ Cf,
               __half* __restrict__ Chi,
               __half* __restrict__ Clo,
               int M, int N, int K, int splitOut)
{
    extern __shared__ __align__(128) char smem[];
    const uint32_t sb = smem_u32(smem);
    const int tid = threadIdx.x, wid = tid >> 5, lane = tid & 31;
    const int brow = blockIdx.y * 256, bcol = blockIdx.x * 128;

    const int r0 = tid >> 3, lseg = tid & 7;
    const uint32_t sw0 = sw128((uint32_t)r0 * 128 + lseg * 16);
    const size_t aBase = (size_t)(brow + r0) * K;
    const size_t bBase = (size_t)(bcol + r0) * K;
    const int esel = lseg * 8;
    const size_t rstep = (size_t)32 * K;

    auto issue = [&](int c) {
        const uint32_t sdst = sb + (c & 1) * GSTAGE_BYTES;
        const size_t ebase = (size_t)c * 64 + esel;
#pragma unroll
        for (int j = 0; j < 8; j++) {
            const uint32_t off = sw0 + j * 4096;
            const size_t ao = aBase + j * rstep + ebase;
            cp16(sdst +         off, Ah + ao);
            cp16(sdst + 32768 + off, Al + ao);
        }
#pragma unroll
        for (int j = 0; j < 4; j++) {
            cp16(sdst + 65536 + sw0 + j * 4096, Bh + bBase + j * rstep + ebase);
        }
        cp_commit();
    };

    issue(0);

    float acc[4][8][4];
#pragma unroll
    for (int a = 0; a < 4; a++)
#pragma unroll
        for (int b = 0; b < 8; b++)
#pragma unroll
            for (int cc = 0; cc < 4; cc++) acc[a][b][cc] = 0.f;

    const int mb = (wid >> 1) * 64, nb = (wid & 1) * 64;
    const int laneA_row = mb + (lane & 15);
    const uint32_t laneA_k = (lane >> 4) * 16;
    const int laneB_row = nb + ((lane >> 4) << 3) + (lane & 7);
    const uint32_t laneB_k = ((lane >> 3) & 1) * 16;

    const int nCh = K >> 6;
    for (int c = 0; c < nCh; c++) {
        cp_wait0();
        __syncthreads();
        if (c + 1 < nCh) issue(c + 1);

        const uint32_t s = sb + (c & 1) * GSTAGE_BYTES;
#pragma unroll
        for (int ks = 0; ks < 4; ks++) {
            uint32_t bh[8][2];
#pragma unroll
            for (int ntp = 0; ntp < 4; ntp++) {
                uint32_t byte = (uint32_t)(laneB_row + ntp * 16) * 128 + ks * 32 + laneB_k;
                uint32_t sw = sw128(byte);
                uint32_t r[4];
                ldm_x4(r, s + 65536 + sw);
                bh[2 * ntp][0] = r[0]; bh[2 * ntp][1] = r[1];
                bh[2 * ntp + 1][0] = r[2]; bh[2 * ntp + 1][1] = r[3];
            }
#pragma unroll
            for (int mt = 0; mt < 4; mt++) {
                uint32_t byte = (uint32_t)(laneA_row + mt * 16) * 128 + ks * 32 + laneA_k;
                uint32_t sw = sw128(byte);
                uint32_t ah[4], al[4];
                ldm_x4(ah, s + sw);
                ldm_x4(al, s + 32768 + sw);
#pragma unroll
                for (int nt = 0; nt < 8; nt++) mma16816(acc[mt][nt], ah, bh[nt]);
#pragma unroll
                for (int nt = 0; nt < 8; nt++) mma16816(acc[mt][nt], al, bh[nt]);
            }
        }
    }

#pragma unroll
    for (int mt = 0; mt < 4; mt++) {
        const int rr0 = brow + mb + mt * 16 + (lane >> 2);
        const int rr1 = rr0 + 8;
#pragma unroll
        for (int nt = 0; nt < 8; nt++) {
            const int col = bcol + nb + nt * 8 + (lane & 3) * 2;
            float2 bv = *(const float2*)(bias + col);
            if (splitOut) {
                uint32_t hi, lo;
                if (rr0 < M) {
                    split2(acc[mt][nt][0] + bv.x, acc[mt][nt][1] + bv.y, hi, lo);
                    *(uint32_t*)(Chi + (size_t)rr0 * N + col) = hi;
                    *(uint32_t*)(Clo + (size_t)rr0 * N + col) = lo;
                }
                if (rr1 < M) {
                    split2(acc[mt][nt][2] + bv.x, acc[mt][nt][3] + bv.y, hi, lo);
                    *(uint32_t*)(Chi + (size_t)rr1 * N + col) = hi;
                    *(uint32_t*)(Clo + (size_t)rr1 * N + col) = lo;
                }
            } else {
                if (rr0 < M) {
                    float2 o = make_float2(acc[mt][nt][0] + bv.x, acc[mt][nt][1] + bv.y);
                    *(float2*)(Cf + (size_t)rr0 * N + col) = o;
                }
                if (rr1 < M) {
                    float2 o = make_float2(acc[mt][nt][2] + bv.x, acc[mt][nt][3] + bv.y);
                    *(float2*)(Cf + (size_t)rr1 * N + col) = o;
                }
            }
        }
    }
}

// ---------------------------------------------------------------------------
// Kernel: tensor-core sliding-window flash attention (fp16 split, 3-term).
// Structure identical to R13 (register fast path + 2-stage window ring).
// ---------------------------------------------------------------------------
#define ATTN_SMEM (16384 + 8192 + 2 * 32768)

__global__ __launch_bounds__(128)
void attn_tc(const __half* __restrict__ qh,
             const __half* __restrict__ ql,
             __half* __restrict__ oh,
             __half* __restrict__ ol)
{
    extern __shared__ __align__(1024) char asmem[];
    const uint32_t sbase = smem_u32(asmem);
    const uint32_t sQh = sbase, sQl = sbase + 8192;
    const uint32_t sReg = sbase + 16384;            // RKh,RKl,RVh,RVl x 2KB
    const uint32_t sRing = sbase + 24576;

    const int b  = blockIdx.z, h = blockIdx.y;
    const int qb = blockIdx.x * 64;
    const int tid = threadIdx.x, warp = tid >> 5, lane = tid & 31;
    const size_t bbase = (size_t)b * T_ * QKVW_;
    const int hcol = h * HD_;

    const int kstart = max(0, qb - HALF_);
    const int kend   = min(S_, qb + 64 + HALF_);
    const int nwin   = (kend - kstart) >> 6;        // 3..5 window chunks

    auto issueKV = [&](int c) {
        const uint32_t kvb = sRing + (c & 1) * 32768;
#pragma unroll
        for (int i = 0; i < 16; i++) {
            int slot = tid + i * 128;          // 0..2047
            int plane = slot >> 9;             // 0=Kh 1=Kl 2=Vh 3=Vl
            int s2 = slot & 511;
            int row = s2 >> 3, seg = s2 & 7;
            int grow = R_ + kstart + c * 64 + row;
            const __half* pl = (plane & 1) ? ql : qh;
            const __half* src = pl + bbase + (size_t)grow * QKVW_ +
                                ((plane >> 1) + 1) * D_ + hcol + seg * 8;
            cp16(kvb + plane * 8192 + sw128((uint32_t)row * 128 + seg * 16), src);
        }
        cp_commit();
    };

    // group A: Q (1024 slots) + reg K/V 16 rows x 4 planes (512 slots)
    {
#pragma unroll
        for (int i = 0; i < 8; i++) {
            int slot = tid + i * 128;
            int plane = slot >> 9;             // 0=Qh 1=Ql
            int s2 = slot & 511;
            int row = s2 >> 3, seg = s2 & 7;
            const __half* pl = plane ? ql : qh;
            const __half* src = pl + bbase + (size_t)(R_ + qb + row) * QKVW_ +
                                hcol + seg * 8;
            cp16((plane ? sQl : sQh) + sw128((uint32_t)row * 128 + seg * 16), src);
        }
#pragma unroll
        for (int i = 0; i < 4; i++) {
            int slot = tid + i * 128;          // 0..511
            int plane = slot >> 7;             // 0=RKh 1=RKl 2=RVh 3=RVl
            int s2 = slot & 127;
            int row = s2 >> 3, seg = s2 & 7;   // rows 0..15 (8..15 dup row 0)
            int grow = (row < R_) ? row : 0;
            const __half* pl = (plane & 1) ? ql : qh;
            const __half* src = pl + bbase + (size_t)grow * QKVW_ +
                                ((plane >> 1) + 1) * D_ + hcol + seg * 8;
            cp16(sReg + plane * 2048 + sw128((uint32_t)row * 128 + seg * 16), src);
        }
        cp_commit();    // group A
        issueKV(0);     // group B
    }

    float oacc[8][4];
    float m[2], lsum[2];
#pragma unroll
    for (int nt = 0; nt < 8; nt++)
#pragma unroll
        for (int e = 0; e < 4; e++) oacc[nt][e] = 0.f;

    const int qtok0 = qb + warp * 16 + (lane >> 2);
    const int laneA_row = warp * 16 + (lane & 15);
    const uint32_t laneA_k = (lane >> 4) * 16;
    const int col2 = 2 * (lane & 3);

    // ---- register path ----
    cp_wait1();
    __syncthreads();
    {
        float racc[2][4];
#pragma unroll
        for (int nt = 0; nt < 2; nt++)
#pragma unroll
            for (int e = 0; e < 4; e++) racc[nt][e] = 0.f;

#pragma unroll
        for (int ks = 0; ks < 4; ks++) {
            uint32_t ah[4], al[4];
            uint32_t qoff = sw128((uint32_t)laneA_row * 128 + ks * 32 + laneA_k);
            ldm_x4(ah, sQh + qoff);
            ldm_x4(al, sQl + qoff);
            uint32_t row = ((lane >> 4) << 3) + (lane & 7);
            uint32_t off = sw128(row * 128 + ks * 32 + ((lane >> 3) & 1) * 16);
            uint32_t rh[4], rl[4];
            ldm_x4(rh, sReg + off);            // RKh
            ldm_x4(rl, sReg + 2048 + off);     // RKl
            uint32_t bh0[2] = {rh[0], rh[1]}, bh1[2] = {rh[2], rh[3]};
            uint32_t bl0[2] = {rl[0], rl[1]}, bl1[2] = {rl[2], rl[3]};
            mma16816(racc[0], ah, bh0); mma16816(racc[1], ah, bh1);
            mma16816(racc[0], ah, bl0); mma16816(racc[1], ah, bl1);
            mma16816(racc[0], al, bh0); mma16816(racc[1], al, bh1);
        }

#pragma unroll
        for (int nt = 0; nt < 2; nt++)
#pragma unroll
            for (int e = 0; e < 4; e++) {
                int klocal = nt * 8 + col2 + (e & 1);
                racc[nt][e] = (klocal < R_) ? racc[nt][e] * 0.125f : -1e30f;
            }

        float mx[2];
        mx[0] = fmaxf(fmaxf(racc[0][0], racc[0][1]), fmaxf(racc[1][0], racc[1][1]));
        mx[1] = fmaxf(fmaxf(racc[0][2], racc[0][3]), fmaxf(racc[1][2], racc[1][3]));
#pragma unroll
        for (int i = 0; i < 2; i++) {
            mx[i] = fmaxf(mx[i], __shfl_xor_sync(0xffffffffu, mx[i], 1));
            mx[i] = fmaxf(mx[i], __shfl_xor_sync(0xffffffffu, mx[i], 2));
            m[i] = mx[i];
        }
        float ps[2] = {0.f, 0.f};
#pragma unroll
        for (int nt = 0; nt < 2; nt++) {
            racc[nt][0] = __expf(racc[nt][0] - m[0]);
            racc[nt][1] = __expf(racc[nt][1] - m[0]);
            racc[nt][2] = __expf(racc[nt][2] - m[1]);
            racc[nt][3] = __expf(racc[nt][3] - m[1]);
            ps[0] += racc[nt][0] + racc[nt][1];
            ps[1] += racc[nt][2] + racc[nt][3];
        }
#pragma unroll
        for (int i = 0; i < 2; i++) {
            ps[i] += __shfl_xor_sync(0xffffffffu, ps[i], 1);
            ps[i] += __shfl_xor_sync(0xffffffffu, ps[i], 2);
            lsum[i] = ps[i];
        }

        uint32_t aph[4], apl[4];
        split2(racc[0][0], racc[0][1], aph[0], apl[0]);
        split2(racc[0][2], racc[0][3], aph[1], apl[1]);
        split2(racc[1][0], racc[1][1], aph[2], apl[2]);
        split2(racc[1][2], racc[1][3], aph[3], apl[3]);

        uint32_t bvh[8][2], bvl[8][2];
#pragma unroll
        for (int ntp = 0; ntp < 4; ntp++) {
            uint32_t row = ((lane >> 3) & 1) * 8 + (lane & 7);
            uint32_t off = sw128(row * 128 + ntp * 32 + (lane >> 4) * 16);
            uint32_t r[4];
            ldm_x4_t(r, sReg + 4096 + off);    // RVh
            bvh[2 * ntp][0] = r[0]; bvh[2 * ntp][1] = r[1];
            bvh[2 * ntp + 1][0] = r[2]; bvh[2 * ntp + 1][1] = r[3];
            ldm_x4_t(r, sReg + 6144 + off);    // RVl
            bvl[2 * ntp][0] = r[0]; bvl[2 * ntp][1] = r[1];
            bvl[2 * ntp + 1][0] = r[2]; bvl[2 * ntp + 1][1] = r[3];
        }
#pragma unroll
        for (int nt = 0; nt < 8; nt++) mma16816(oacc[nt], aph, bvh[nt]);
#pragma unroll
        for (int nt = 0; nt < 8; nt++) mma16816(oacc[nt], aph, bvl[nt]);
#pragma unroll
        for (int nt = 0; nt < 8; nt++) mma16816(oacc[nt], apl, bvh[nt]);
    }

    // ---- window chunks ----
    for (int c = 0; c < nwin; c++) {
        __syncthreads();
        if (c + 1 < nwin) { issueKV(c + 1); cp_wait1(); }
        else              { cp_wait0(); }
        __syncthreads();

        const uint32_t kvb = sRing + (c & 1) * 32768;
        const uint32_t sKh = kvb, sKl = kvb + 8192;
        const uint32_t sVh = kvb + 16384, sVl = kvb + 24576;

        float sacc[8][4];
#pragma unroll
        for (int nt = 0; nt < 8; nt++)
#pragma unroll
            for (int e = 0; e < 4; e++) sacc[nt][e] = 0.f;

#pragma unroll
        for (int ks = 0; ks < 4; ks++) {
            uint32_t ah[4], al[4];
            uint32_t qoff = sw128((uint32_t)laneA_row * 128 + ks * 32 + laneA_k);
            ldm_x4(ah, sQh + qoff);
            ldm_x4(al, sQl + qoff);
            uint32_t bh[8][2], bl[8][2];
#pragma unroll
            for (int ntp = 0; ntp < 4; ntp++) {
                uint32_t row = ntp * 16 + ((lane >> 4) << 3) + (lane & 7);
                uint32_t off = sw128(row * 128 + ks * 32 + ((lane >> 3) & 1) * 16);
                uint32_t r[4];
                ldm_x4(r, sKh + off);
                bh[2 * ntp][0] = r[0]; bh[2 * ntp][1] = r[1];
                bh[2 * ntp + 1][0] = r[2]; bh[2 * ntp + 1][1] = r[3];
                ldm_x4(r, sKl + off);
                bl[2 * ntp][0] = r[0]; bl[2 * ntp][1] = r[1];
                bl[2 * ntp + 1][0] = r[2]; bl[2 * ntp + 1][1] = r[3];
            }
#pragma unroll
            for (int nt = 0; nt < 8; nt++) mma16816(sacc[nt], ah, bh[nt]);
#pragma unroll
            for (int nt = 0; nt < 8; nt++) mma16816(sacc[nt], ah, bl[nt]);
#pragma unroll
            for (int nt = 0; nt < 8; nt++) mma16816(sacc[nt], al, bh[nt]);
        }

        const int colbase = kstart + c * 64;
#pragma unroll
        for (int nt = 0; nt < 8; nt++) {
#pragma unroll
            for (int e = 0; e < 4; e++) {
                int ktok = colbase + nt * 8 + col2 + (e & 1);
                int qtok = qtok0 + (e >> 1) * 8;
                bool valid = (ktok >= qtok - HALF_) && (ktok <= qtok + HALF_);
                sacc[nt][e] = valid ? sacc[nt][e] * 0.125f : -1e30f;
            }
        }

        float mx[2] = {-1e30f, -1e30f};
#pragma unroll
        for (int nt = 0; nt < 8; nt++) {
            mx[0] = fmaxf(mx[0], fmaxf(sacc[nt][0], sacc[nt][1]));
            mx[1] = fmaxf(mx[1], fmaxf(sacc[nt][2], sacc[nt][3]));
        }
#pragma unroll
        for (int i = 0; i < 2; i++) {
            mx[i] = fmaxf(mx[i], __shfl_xor_sync(0xffffffffu, mx[i], 1));
            mx[i] = fmaxf(mx[i], __shfl_xor_sync(0xffffffffu, mx[i], 2));
        }
        float corr[2], ps[2] = {0.f, 0.f};
#pragma unroll
        for (int i = 0; i < 2; i++) {
            float mn = fmaxf(m[i], mx[i]);
            corr[i] = __expf(m[i] - mn);
            m[i] = mn;
        }
#pragma unroll
        for (int nt = 0; nt < 8; nt++) {
            sacc[nt][0] = __expf(sacc[nt][0] - m[0]);
            sacc[nt][1] = __expf(sacc[nt][1] - m[0]);
            sacc[nt][2] = __expf(sacc[nt][2] - m[1]);
            sacc[nt][3] = __expf(sacc[nt][3] - m[1]);
            ps[0] += sacc[nt][0] + sacc[nt][1];
            ps[1] += sacc[nt][2] + sacc[nt][3];
        }
#pragma unroll
        for (int i = 0; i < 2; i++) {
            ps[i] += __shfl_xor_sync(0xffffffffu, ps[i], 1);
            ps[i] += __shfl_xor_sync(0xffffffffu, ps[i], 2);
            lsum[i] = lsum[i] * corr[i] + ps[i];
        }
#pragma unroll
        for (int nt = 0; nt < 8; nt++) {
            oacc[nt][0] *= corr[0]; oacc[nt][1] *= corr[0];
            oacc[nt][2] *= corr[1]; oacc[nt][3] *= corr[1];
        }

        uint32_t aph[4][4], apl[4][4];
#pragma unroll
        for (int ks = 0; ks < 4; ks++) {
            split2(sacc[2 * ks][0],     sacc[2 * ks][1],     aph[ks][0], apl[ks][0]);
            split2(sacc[2 * ks][2],     sacc[2 * ks][3],     aph[ks][1], apl[ks][1]);
            split2(sacc[2 * ks + 1][0], sacc[2 * ks + 1][1], aph[ks][2], apl[ks][2]);
            split2(sacc[2 * ks + 1][2], sacc[2 * ks + 1][3], aph[ks][3], apl[ks][3]);
        }

#pragma unroll
        for (int ks = 0; ks < 4; ks++) {
            uint32_t bvh[8][2], bvl[8][2];
#pragma unroll
            for (int ntp = 0; ntp < 4; ntp++) {
                uint32_t row = ks * 16 + ((lane >> 3) & 1) * 8 + (lane & 7);
                uint32_t off = sw128(row * 128 + ntp * 32 + (lane >> 4) * 16);
                uint32_t r[4];
                ldm_x4_t(r, sVh + off);
                bvh[2 * ntp][0] = r[0]; bvh[2 * ntp][1] = r[1];
                bvh[2 * ntp + 1][0] = r[2]; bvh[2 * ntp + 1][1] = r[3];
                ldm_x4_t(r, sVl + off);
                bvl[2 * ntp][0] = r[0]; bvl[2 * ntp][1] = r[1];
                bvl[2 * ntp + 1][0] = r[2]; bvl[2 * ntp + 1][1] = r[3];
            }
#pragma unroll
            for (int nt = 0; nt < 8; nt++) mma16816(oacc[nt], aph[ks], bvh[nt]);
#pragma unroll
            for (int nt = 0; nt < 8; nt++) mma16816(oacc[nt], aph[ks], bvl[nt]);
#pragma unroll
            for (int nt = 0; nt < 8; nt++) mma16816(oacc[nt], apl[ks], bvh[nt]);
        }
    }

    const float inv0 = 1.0f / lsum[0];
    const float inv1 = 1.0f / lsum[1];
    const int tok0 = qb + warp * 16 + (lane >> 2);
#pragma unroll
    for (int nt = 0; nt < 8; nt++) {
        const int d0 = nt * 8 + 2 * (lane & 3);
        size_t i0 = ((size_t)b * S_ + tok0) * D_ + h * HD_ + d0;
        size_t i1 = ((size_t)b * S_ + tok0 + 8) * D_ + h * HD_ + d0;
        uint32_t hi, lo;
        split2(oacc[nt][0] * inv0, oacc[nt][1] * inv0, hi, lo);
        *(uint32_t*)(oh + i0) = hi;
        *(uint32_t*)(ol + i0) = lo;
        split2(oacc[nt][2] * inv1, oacc[nt][3] * inv1, hi, lo);
        *(uint32_t*)(oh + i1) = hi;
        *(uint32_t*)(ol + i1) = lo;
    }
}

// ---------------------------------------------------------------------------
// Launch
// ---------------------------------------------------------------------------
extern "C" void kernel_launch(void* const* d_in, const int* in_sizes, int n_in,
                              void* d_out, int out_size)
{
    const float* x      = (const float*)d_in[0];
    const float* ada    = (const float*)d_in[1];
    const float* regs   = (const float*)d_in[2];
    const float* W_qkv  = (const float*)d_in[3];
    const float* b_qkv  = (const float*)d_in[4];
    const float* W_out  = (const float*)d_in[5];
    const float* b_out  = (const float*)d_in[6];
    float* out = (float*)d_out;

    __half *xrh, *xrl, *wqh, *woh, *ath, *atl, *qvh, *qvl;
    cudaGetSymbolAddress((void**)&xrh, g_xr_hi);
    cudaGetSymbolAddress((void**)&xrl, g_xr_lo);
    cudaGetSymbolAddress((void**)&wqh, g_wq_hi);
    cudaGetSymbolAddress((void**)&woh, g_wo_hi);
    cudaGetSymbolAddress((void**)&ath, g_at_hi);
    cudaGetSymbolAddress((void**)&atl, g_at_lo);
    cudaGetSymbolAddress((void**)&qvh, g_qkv_hi);
    cudaGetSymbolAddress((void**)&qvl, g_qkv_lo);

    cudaFuncSetAttribute(gemm_fp16, cudaFuncAttributeMaxDynamicSharedMemorySize, GEMM_SMEM);
    cudaFuncSetAttribute(attn_tc, cudaFuncAttributeMaxDynamicSharedMemorySize, ATTN_SMEM);

    // 1. merged prep
    prep_split<<<(N_PREP + 255) / 256, 256>>>(x, ada, regs, W_qkv, W_out,
                                              xrh, xrl, wqh, woh);

    // 2. qkv planes = split((xr_h + xr_l) @ Wq_h^T + b_qkv) : M=4112, N=3072
    gemm_fp16<<<dim3(QKVW_ / 128, MPAD_ / 256), 256, GEMM_SMEM>>>(
        xrh, xrl, wqh, b_qkv, nullptr, qvh, qvl, B_ * T_, QKVW_, D_, 1);

    // 3. windowed attention (fp16 split, register fast path) -> hi/lo planes
    attn_tc<<<dim3(S_ / 64, H_, B_), 128, ATTN_SMEM>>>(qvh, qvl, ath, atl);

    // 4. out = (at_h + at_l) @ Wo_h^T + b_out : M=4096, N=1024 (fp32 out)
    gemm_fp16<<<dim3(D_ / 128, (B_ * S_) / 256), 256, GEMM_SMEM>>>(
        ath, atl, woh, b_out, out, nullptr, nullptr, B_ * S_, D_, D_, 0);
}

// round 15
// speedup vs baseline: 1.4654x; 1.0551x over previous
#include <cuda_runtime.h>
#include <cuda_fp16.h>
#include <math.h>
#include <stdint.h>

// Problem constants
#define B_   2
#define S_   2048
#define D_   1024
#define H_   16
#define HD_  64
#define R_   8
#define T_   2056      // S_ + R_
#define HALF_ 128
#define QKVW_ 3072     // 3*D_
#define MPAD_ 4352     // B_*T_ = 4112 padded to multiple of 256

// Scratch (device globals; no allocation allowed)
__device__ __align__(16) __half g_xr_hi[(size_t)MPAD_ * D_];
__device__ __align__(16) __half g_xr_lo[(size_t)MPAD_ * D_];
__device__ __align__(16) __half g_wq_hi[(size_t)QKVW_ * D_];
__device__ __align__(16) __half g_wo_hi[(size_t)D_ * D_];
__device__ __align__(16) __half g_at_hi[(size_t)B_ * S_ * D_];
__device__ __align__(16) __half g_at_lo[(size_t)B_ * S_ * D_];
__device__ __align__(16) __half g_qkv_hi[(size_t)B_ * T_ * QKVW_];
__device__ __align__(16) __half g_qkv_lo[(size_t)B_ * T_ * QKVW_];

// ---------------------------------------------------------------------------
// helpers
// ---------------------------------------------------------------------------
__device__ __forceinline__ uint32_t smem_u32(const void* p) {
    uint32_t a;
    asm("{ .reg .u64 t; cvta.to.shared.u64 t, %1; cvt.u32.u64 %0, t; }"
        : "=r"(a) : "l"(p));
    return a;
}
__device__ __forceinline__ uint32_t sw128(uint32_t off) {
    return off ^ ((off >> 3) & 0x70);
}
__device__ __forceinline__ void cp16(uint32_t dst, const void* src) {
    asm volatile("cp.async.cg.shared.global [%0], [%1], 16;"
                 :: "r"(dst), "l"(src) : "memory");
}
__device__ __forceinline__ void cp_commit() {
    asm volatile("cp.async.commit_group;" ::: "memory");
}
__device__ __forceinline__ void cp_wait0() {
    asm volatile("cp.async.wait_group 0;" ::: "memory");
}
__device__ __forceinline__ void cp_wait1() {
    asm volatile("cp.async.wait_group 1;" ::: "memory");
}
__device__ __forceinline__ void ldm_x4(uint32_t* r, uint32_t addr) {
    asm volatile("ldmatrix.sync.aligned.m8n8.x4.shared.b16 {%0,%1,%2,%3}, [%4];"
                 : "=r"(r[0]), "=r"(r[1]), "=r"(r[2]), "=r"(r[3]) : "r"(addr));
}
__device__ __forceinline__ void ldm_x4_t(uint32_t* r, uint32_t addr) {
    asm volatile("ldmatrix.sync.aligned.m8n8.x4.trans.shared.b16 {%0,%1,%2,%3}, [%4];"
                 : "=r"(r[0]), "=r"(r[1]), "=r"(r[2]), "=r"(r[3]) : "r"(addr));
}
// fp16 inputs, fp32 accumulate
__device__ __forceinline__ void mma16816(float* c, const uint32_t* a, const uint32_t* b) {
    asm volatile(
        "mma.sync.aligned.m16n8k16.row.col.f32.f16.f16.f32 "
        "{%0,%1,%2,%3}, {%4,%5,%6,%7}, {%8,%9}, {%0,%1,%2,%3};"
        : "+f"(c[0]), "+f"(c[1]), "+f"(c[2]), "+f"(c[3])
        : "r"(a[0]), "r"(a[1]), "r"(a[2]), "r"(a[3]), "r"(b[0]), "r"(b[1]));
}

// pack 4 floats -> hi fp16x4 (uint2) and lo fp16x4 (uint2)
__device__ __forceinline__ void split4(float4 v, uint2& hi, uint2& lo) {
    __half h0 = __float2half_rn(v.x);
    __half h1 = __float2half_rn(v.y);
    __half h2 = __float2half_rn(v.z);
    __half h3 = __float2half_rn(v.w);
    hi.x = ((uint32_t)__half_as_ushort(h1) << 16) | __half_as_ushort(h0);
    hi.y = ((uint32_t)__half_as_ushort(h3) << 16) | __half_as_ushort(h2);
    __half2 l01 = __floats2half2_rn(v.x - __half2float(h0),
                                    v.y - __half2float(h1));
    __half2 l23 = __floats2half2_rn(v.z - __half2float(h2),
                                    v.w - __half2float(h3));
    lo.x = *(uint32_t*)&l01;
    lo.y = *(uint32_t*)&l23;
}
// hi-only fp16x4
__device__ __forceinline__ uint2 round4h(float4 v) {
    uint2 hi;
    __half2 p01 = __floats2half2_rn(v.x, v.y);
    __half2 p23 = __floats2half2_rn(v.z, v.w);
    hi.x = *(uint32_t*)&p01;
    hi.y = *(uint32_t*)&p23;
    return hi;
}
// pack 2 floats -> hi fp16x2 word and lo fp16x2 word
__device__ __forceinline__ void split2(float a, float b, uint32_t& hi, uint32_t& lo) {
    __half h0 = __float2half_rn(a);
    __half h1 = __float2half_rn(b);
    hi = ((uint32_t)__half_as_ushort(h1) << 16) | __half_as_ushort(h0);
    __half2 l = __floats2half2_rn(a - __half2float(h0),
                                  b - __half2float(h1));
    lo = *(uint32_t*)&l;
}

// ---------------------------------------------------------------------------
// Kernel 1 (merged prep): xr build (hi/lo) + weight rounds (hi only)
// ---------------------------------------------------------------------------
#define N_XR (MPAD_ * (D_ / 4))
#define N_WQ (QKVW_ * D_ / 4)
#define N_WO (D_ * D_ / 4)
#define N_PREP (N_XR + N_WQ + N_WO)

__global__ void prep_split(const float* __restrict__ x,
                           const float* __restrict__ ada,
                           const float* __restrict__ regs,
                           const float* __restrict__ Wq,
                           const float* __restrict__ Wo,
                           __half* __restrict__ xh,
                           __half* __restrict__ xl,
                           __half* __restrict__ wqh,
                           __half* __restrict__ woh)
{
    int i = blockIdx.x * blockDim.x + threadIdx.x;
    if (i >= N_PREP) return;
    const int D4 = D_ / 4;

    if (i < N_XR) {
        int d4 = i % D4;
        int row = i / D4;
        uint2 hi = make_uint2(0u, 0u), lo = make_uint2(0u, 0u);
        if (row < B_ * T_) {
            int t = row % T_;
            int b = row / T_;
            float4 v;
            if (t < R_) {
                float4 rv = ((const float4*)regs)[t * D4 + d4];
                float4 av = ((const float4*)ada)[b * D4 + d4];
                v = make_float4(rv.x * (1.f + av.x), rv.y * (1.f + av.y),
                                rv.z * (1.f + av.z), rv.w * (1.f + av.w));
            } else {
                v = ((const float4*)x)[((size_t)b * S_ + (t - R_)) * D4 + d4];
            }
            split4(v, hi, lo);
        }
        ((uint2*)xh)[i] = hi;
        ((uint2*)xl)[i] = lo;
    } else if (i < N_XR + N_WQ) {
        int j = i - N_XR;
        ((uint2*)wqh)[j] = round4h(((const float4*)Wq)[j]);
    } else {
        int j = i - N_XR - N_WQ;
        ((uint2*)woh)[j] = round4h(((const float4*)Wo)[j]);
    }
}

// ---------------------------------------------------------------------------
// Kernel: 2-term fp16 tensor-core GEMM, 256x128 CTA tile (proven R14).
// ---------------------------------------------------------------------------
#define GSTAGE_BYTES 81920
#define GEMM_SMEM (2 * GSTAGE_BYTES)

__global__ __launch_bounds__(256, 1)
void gemm_fp16(const __half* __restrict__ Ah,
               const __half* __restrict__ Al,
               const __half* __restrict__ Bh,
               const float* __restrict__ bias,
               float* __restrict__ Cf,
               __half* __restrict__ Chi,
               __half* __restrict__ Clo,
               int M, int N, int K, int splitOut)
{
    extern __shared__ __align__(128) char smem[];
    const uint32_t sb = smem_u32(smem);
    const int tid = threadIdx.x, wid = tid >> 5, lane = tid & 31;
    const int brow = blockIdx.y * 256, bcol = blockIdx.x * 128;

    const int r0 = tid >> 3, lseg = tid & 7;
    const uint32_t sw0 = sw128((uint32_t)r0 * 128 + lseg * 16);
    const size_t aBase = (size_t)(brow + r0) * K;
    const size_t bBase = (size_t)(bcol + r0) * K;
    const int esel = lseg * 8;
    const size_t rstep = (size_t)32 * K;

    auto issue = [&](int c) {
        const uint32_t sdst = sb + (c & 1) * GSTAGE_BYTES;
        const size_t ebase = (size_t)c * 64 + esel;
#pragma unroll
        for (int j = 0; j < 8; j++) {
            const uint32_t off = sw0 + j * 4096;
            const size_t ao = aBase + j * rstep + ebase;
            cp16(sdst +         off, Ah + ao);
            cp16(sdst + 32768 + off, Al + ao);
        }
#pragma unroll
        for (int j = 0; j < 4; j++) {
            cp16(sdst + 65536 + sw0 + j * 4096, Bh + bBase + j * rstep + ebase);
        }
        cp_commit();
    };

    issue(0);

    float acc[4][8][4];
#pragma unroll
    for (int a = 0; a < 4; a++)
#pragma unroll
        for (int b = 0; b < 8; b++)
#pragma unroll
            for (int cc = 0; cc < 4; cc++) acc[a][b][cc] = 0.f;

    const int mb = (wid >> 1) * 64, nb = (wid & 1) * 64;
    const int laneA_row = mb + (lane & 15);
    const uint32_t laneA_k = (lane >> 4) * 16;
    const int laneB_row = nb + ((lane >> 4) << 3) + (lane & 7);
    const uint32_t laneB_k = ((lane >> 3) & 1) * 16;

    const int nCh = K >> 6;
    for (int c = 0; c < nCh; c++) {
        cp_wait0();
        __syncthreads();
        if (c + 1 < nCh) issue(c + 1);

        const uint32_t s = sb + (c & 1) * GSTAGE_BYTES;
#pragma unroll
        for (int ks = 0; ks < 4; ks++) {
            uint32_t bh[8][2];
#pragma unroll
            for (int ntp = 0; ntp < 4; ntp++) {
                uint32_t byte = (uint32_t)(laneB_row + ntp * 16) * 128 + ks * 32 + laneB_k;
                uint32_t sw = sw128(byte);
                uint32_t r[4];
                ldm_x4(r, s + 65536 + sw);
                bh[2 * ntp][0] = r[0]; bh[2 * ntp][1] = r[1];
                bh[2 * ntp + 1][0] = r[2]; bh[2 * ntp + 1][1] = r[3];
            }
#pragma unroll
            for (int mt = 0; mt < 4; mt++) {
                uint32_t byte = (uint32_t)(laneA_row + mt * 16) * 128 + ks * 32 + laneA_k;
                uint32_t sw = sw128(byte);
                uint32_t ah[4], al[4];
                ldm_x4(ah, s + sw);
                ldm_x4(al, s + 32768 + sw);
#pragma unroll
                for (int nt = 0; nt < 8; nt++) mma16816(acc[mt][nt], ah, bh[nt]);
#pragma unroll
                for (int nt = 0; nt < 8; nt++) mma16816(acc[mt][nt], al, bh[nt]);
            }
        }
    }

#pragma unroll
    for (int mt = 0; mt < 4; mt++) {
        const int rr0 = brow + mb + mt * 16 + (lane >> 2);
        const int rr1 = rr0 + 8;
#pragma unroll
        for (int nt = 0; nt < 8; nt++) {
            const int col = bcol + nb + nt * 8 + (lane & 3) * 2;
            float2 bv = *(const float2*)(bias + col);
            if (splitOut) {
                uint32_t hi, lo;
                if (rr0 < M) {
                    split2(acc[mt][nt][0] + bv.x, acc[mt][nt][1] + bv.y, hi, lo);
                    *(uint32_t*)(Chi + (size_t)rr0 * N + col) = hi;
                    *(uint32_t*)(Clo + (size_t)rr0 * N + col) = lo;
                }
                if (rr1 < M) {
                    split2(acc[mt][nt][2] + bv.x, acc[mt][nt][3] + bv.y, hi, lo);
                    *(uint32_t*)(Chi + (size_t)rr1 * N + col) = hi;
                    *(uint32_t*)(Clo + (size_t)rr1 * N + col) = lo;
                }
            } else {
                if (rr0 < M) {
                    float2 o = make_float2(acc[mt][nt][0] + bv.x, acc[mt][nt][1] + bv.y);
                    *(float2*)(Cf + (size_t)rr0 * N + col) = o;
                }
                if (rr1 < M) {
                    float2 o = make_float2(acc[mt][nt][2] + bv.x, acc[mt][nt][3] + bv.y);
                    *(float2*)(Cf + (size_t)rr1 * N + col) = o;
                }
            }
        }
    }
}

// ---------------------------------------------------------------------------
// Kernel: tensor-core sliding-window flash attention, 2-term fp16.
// S = (Qh+Ql)·Kh ; O = (Ph+Pl)·Vh.  K/V hi planes only -> bytes halved.
// 64q x 1 head, 128 threads; register fast path; 2-stage 16KB K/V ring.
// smem: Q 16KB + reg 4KB + ring 32KB = 52KB.
// ---------------------------------------------------------------------------
#define ATTN_SMEM (16384 + 4096 + 2 * 16384)

__global__ __launch_bounds__(128)
void attn_tc(const __half* __restrict__ qh,
             const __half* __restrict__ ql,
             __half* __restrict__ oh,
             __half* __restrict__ ol)
{
    extern __shared__ __align__(1024) char asmem[];
    const uint32_t sbase = smem_u32(asmem);
    const uint32_t sQh = sbase, sQl = sbase + 8192;
    const uint32_t sReg = sbase + 16384;            // RKh 2KB, RVh 2KB
    const uint32_t sRing = sbase + 20480;

    const int b  = blockIdx.z, h = blockIdx.y;
    const int qb = blockIdx.x * 64;
    const int tid = threadIdx.x, warp = tid >> 5, lane = tid & 31;
    const size_t bbase = (size_t)b * T_ * QKVW_;
    const int hcol = h * HD_;

    const int kstart = max(0, qb - HALF_);
    const int kend   = min(S_, qb + 64 + HALF_);
    const int nwin   = (kend - kstart) >> 6;        // 3..5 window chunks

    // window chunk loader: hi planes only (Kh, Vh), 8 cp16/thread
    auto issueKV = [&](int c) {
        const uint32_t kvb = sRing + (c & 1) * 16384;
#pragma unroll
        for (int i = 0; i < 8; i++) {
            int slot = tid + i * 128;          // 0..1023
            int plane = slot >> 9;             // 0=Kh 1=Vh
            int s2 = slot & 511;
            int row = s2 >> 3, seg = s2 & 7;
            int grow = R_ + kstart + c * 64 + row;
            const __half* src = qh + bbase + (size_t)grow * QKVW_ +
                                (plane + 1) * D_ + hcol + seg * 8;
            cp16(kvb + plane * 8192 + sw128((uint32_t)row * 128 + seg * 16), src);
        }
        cp_commit();
    };

    // group A: Q hi/lo (1024 slots) + reg Kh/Vh 16 rows (256 slots)
    {
#pragma unroll
        for (int i = 0; i < 8; i++) {
            int slot = tid + i * 128;
            int plane = slot >> 9;             // 0=Qh 1=Ql
            int s2 = slot & 511;
            int row = s2 >> 3, seg = s2 & 7;
            const __half* pl = plane ? ql : qh;
            const __half* src = pl + bbase + (size_t)(R_ + qb + row) * QKVW_ +
                                hcol + seg * 8;
            cp16((plane ? sQl : sQh) + sw128((uint32_t)row * 128 + seg * 16), src);
        }
#pragma unroll
        for (int i = 0; i < 2; i++) {
            int slot = tid + i * 128;          // 0..255
            int plane = slot >> 7;             // 0=RKh 1=RVh
            int s2 = slot & 127;
            int row = s2 >> 3, seg = s2 & 7;   // rows 0..15 (8..15 dup row 0)
            int grow = (row < R_) ? row : 0;
            const __half* src = qh + bbase + (size_t)grow * QKVW_ +
                                (plane + 1) * D_ + hcol + seg * 8;
            cp16(sReg + plane * 2048 + sw128((uint32_t)row * 128 + seg * 16), src);
        }
        cp_commit();    // group A
        issueKV(0);     // group B
    }

    float oacc[8][4];
    float m[2], lsum[2];
#pragma unroll
    for (int nt = 0; nt < 8; nt++)
#pragma unroll
        for (int e = 0; e < 4; e++) oacc[nt][e] = 0.f;

    const int qtok0 = qb + warp * 16 + (lane >> 2);
    const int laneA_row = warp * 16 + (lane & 15);
    const uint32_t laneA_k = (lane >> 4) * 16;
    const int col2 = 2 * (lane & 3);

    // ---- register path ----
    cp_wait1();
    __syncthreads();
    {
        float racc[2][4];
#pragma unroll
        for (int nt = 0; nt < 2; nt++)
#pragma unroll
            for (int e = 0; e < 4; e++) racc[nt][e] = 0.f;

#pragma unroll
        for (int ks = 0; ks < 4; ks++) {
            uint32_t ah[4], al[4];
            uint32_t qoff = sw128((uint32_t)laneA_row * 128 + ks * 32 + laneA_k);
            ldm_x4(ah, sQh + qoff);
            ldm_x4(al, sQl + qoff);
            uint32_t row = ((lane >> 4) << 3) + (lane & 7);
            uint32_t off = sw128(row * 128 + ks * 32 + ((lane >> 3) & 1) * 16);
            uint32_t rh[4];
            ldm_x4(rh, sReg + off);            // RKh
            uint32_t bh0[2] = {rh[0], rh[1]}, bh1[2] = {rh[2], rh[3]};
            mma16816(racc[0], ah, bh0); mma16816(racc[1], ah, bh1);
            mma16816(racc[0], al, bh0); mma16816(racc[1], al, bh1);
        }

#pragma unroll
        for (int nt = 0; nt < 2; nt++)
#pragma unroll
            for (int e = 0; e < 4; e++) {
                int klocal = nt * 8 + col2 + (e & 1);
                racc[nt][e] = (klocal < R_) ? racc[nt][e] * 0.125f : -1e30f;
            }

        float mx[2];
        mx[0] = fmaxf(fmaxf(racc[0][0], racc[0][1]), fmaxf(racc[1][0], racc[1][1]));
        mx[1] = fmaxf(fmaxf(racc[0][2], racc[0][3]), fmaxf(racc[1][2], racc[1][3]));
#pragma unroll
        for (int i = 0; i < 2; i++) {
            mx[i] = fmaxf(mx[i], __shfl_xor_sync(0xffffffffu, mx[i], 1));
            mx[i] = fmaxf(mx[i], __shfl_xor_sync(0xffffffffu, mx[i], 2));
            m[i] = mx[i];
        }
        float ps[2] = {0.f, 0.f};
#pragma unroll
        for (int nt = 0; nt < 2; nt++) {
            racc[nt][0] = __expf(racc[nt][0] - m[0]);
            racc[nt][1] = __expf(racc[nt][1] - m[0]);
            racc[nt][2] = __expf(racc[nt][2] - m[1]);
            racc[nt][3] = __expf(racc[nt][3] - m[1]);
            ps[0] += racc[nt][0] + racc[nt][1];
            ps[1] += racc[nt][2] + racc[nt][3];
        }
#pragma unroll
        for (int i = 0; i < 2; i++) {
            ps[i] += __shfl_xor_sync(0xffffffffu, ps[i], 1);
            ps[i] += __shfl_xor_sync(0xffffffffu, ps[i], 2);
            lsum[i] = ps[i];
        }

        uint32_t aph[4], apl[4];
        split2(racc[0][0], racc[0][1], aph[0], apl[0]);
        split2(racc[0][2], racc[0][3], aph[1], apl[1]);
        split2(racc[1][0], racc[1][1], aph[2], apl[2]);
        split2(racc[1][2], racc[1][3], aph[3], apl[3]);

        uint32_t bvh[8][2];
#pragma unroll
        for (int ntp = 0; ntp < 4; ntp++) {
            uint32_t row = ((lane >> 3) & 1) * 8 + (lane & 7);
            uint32_t off = sw128(row * 128 + ntp * 32 + (lane >> 4) * 16);
            uint32_t r[4];
            ldm_x4_t(r, sReg + 2048 + off);    // RVh
            bvh[2 * ntp][0] = r[0]; bvh[2 * ntp][1] = r[1];
            bvh[2 * ntp + 1][0] = r[2]; bvh[2 * ntp + 1][1] = r[3];
        }
#pragma unroll
        for (int nt = 0; nt < 8; nt++) mma16816(oacc[nt], aph, bvh[nt]);
#pragma unroll
        for (int nt = 0; nt < 8; nt++) mma16816(oacc[nt], apl, bvh[nt]);
    }

    // ---- window chunks ----
    for (int c = 0; c < nwin; c++) {
        __syncthreads();
        if (c + 1 < nwin) { issueKV(c + 1); cp_wait1(); }
        else              { cp_wait0(); }
        __syncthreads();

        const uint32_t kvb = sRing + (c & 1) * 16384;
        const uint32_t sKh = kvb, sVh = kvb + 8192;

        float sacc[8][4];
#pragma unroll
        for (int nt = 0; nt < 8; nt++)
#pragma unroll
            for (int e = 0; e < 4; e++) sacc[nt][e] = 0.f;

#pragma unroll
        for (int ks = 0; ks < 4; ks++) {
            uint32_t ah[4], al[4];
            uint32_t qoff = sw128((uint32_t)laneA_row * 128 + ks * 32 + laneA_k);
            ldm_x4(ah, sQh + qoff);
            ldm_x4(al, sQl + qoff);
            uint32_t bh[8][2];
#pragma unroll
            for (int ntp = 0; ntp < 4; ntp++) {
                uint32_t row = ntp * 16 + ((lane >> 4) << 3) + (lane & 7);
                uint32_t off = sw128(row * 128 + ks * 32 + ((lane >> 3) & 1) * 16);
                uint32_t r[4];
                ldm_x4(r, sKh + off);
                bh[2 * ntp][0] = r[0]; bh[2 * ntp][1] = r[1];
                bh[2 * ntp + 1][0] = r[2]; bh[2 * ntp + 1][1] = r[3];
            }
#pragma unroll
            for (int nt = 0; nt < 8; nt++) mma16816(sacc[nt], ah, bh[nt]);
#pragma unroll
            for (int nt = 0; nt < 8; nt++) mma16816(sacc[nt], al, bh[nt]);
        }

        const int colbase = kstart + c * 64;
#pragma unroll
        for (int nt = 0; nt < 8; nt++) {
#pragma unroll
            for (int e = 0; e < 4; e++) {
                int ktok = colbase + nt * 8 + col2 + (e & 1);
                int qtok = qtok0 + (e >> 1) * 8;
                bool valid = (ktok >= qtok - HALF_) && (ktok <= qtok + HALF_);
                sacc[nt][e] = valid ? sacc[nt][e] * 0.125f : -1e30f;
            }
        }

        float mx[2] = {-1e30f, -1e30f};
#pragma unroll
        for (int nt = 0; nt < 8; nt++) {
            mx[0] = fmaxf(mx[0], fmaxf(sacc[nt][0], sacc[nt][1]));
            mx[1] = fmaxf(mx[1], fmaxf(sacc[nt][2], sacc[nt][3]));
        }
#pragma unroll
        for (int i = 0; i < 2; i++) {
            mx[i] = fmaxf(mx[i], __shfl_xor_sync(0xffffffffu, mx[i], 1));
            mx[i] = fmaxf(mx[i], __shfl_xor_sync(0xffffffffu, mx[i], 2));
        }
        float corr[2], ps[2] = {0.f, 0.f};
#pragma unroll
        for (int i = 0; i < 2; i++) {
            float mn = fmaxf(m[i], mx[i]);
            corr[i] = __expf(m[i] - mn);
            m[i] = mn;
        }
#pragma unroll
        for (int nt = 0; nt < 8; nt++) {
            sacc[nt][0] = __expf(sacc[nt][0] - m[0]);
            sacc[nt][1] = __expf(sacc[nt][1] - m[0]);
            sacc[nt][2] = __expf(sacc[nt][2] - m[1]);
            sacc[nt][3] = __expf(sacc[nt][3] - m[1]);
            ps[0] += sacc[nt][0] + sacc[nt][1];
            ps[1] += sacc[nt][2] + sacc[nt][3];
        }
#pragma unroll
        for (int i = 0; i < 2; i++) {
            ps[i] += __shfl_xor_sync(0xffffffffu, ps[i], 1);
            ps[i] += __shfl_xor_sync(0xffffffffu, ps[i], 2);
            lsum[i] = lsum[i] * corr[i] + ps[i];
        }
#pragma unroll
        for (int nt = 0; nt < 8; nt++) {
            oacc[nt][0] *= corr[0]; oacc[nt][1] *= corr[0];
            oacc[nt][2] *= corr[1]; oacc[nt][3] *= corr[1];
        }

        uint32_t aph[4][4], apl[4][4];
#pragma unroll
        for (int ks = 0; ks < 4; ks++) {
            split2(sacc[2 * ks][0],     sacc[2 * ks][1],     aph[ks][0], apl[ks][0]);
            split2(sacc[2 * ks][2],     sacc[2 * ks][3],     aph[ks][1], apl[ks][1]);
            split2(sacc[2 * ks + 1][0], sacc[2 * ks + 1][1], aph[ks][2], apl[ks][2]);
            split2(sacc[2 * ks + 1][2], sacc[2 * ks + 1][3], aph[ks][3], apl[ks][3]);
        }

#pragma unroll
        for (int ks = 0; ks < 4; ks++) {
            uint32_t bvh[8][2];
#pragma unroll
            for (int ntp = 0; ntp < 4; ntp++) {
                uint32_t row = ks * 16 + ((lane >> 3) & 1) * 8 + (lane & 7);
                uint32_t off = sw128(row * 128 + ntp * 32 + (lane >> 4) * 16);
                uint32_t r[4];
                ldm_x4_t(r, sVh + off);
                bvh[2 * ntp][0] = r[0]; bvh[2 * ntp][1] = r[1];
                bvh[2 * ntp + 1][0] = r[2]; bvh[2 * ntp + 1][1] = r[3];
            }
#pragma unroll
            for (int nt = 0; nt < 8; nt++) mma16816(oacc[nt], aph[ks], bvh[nt]);
#pragma unroll
            for (int nt = 0; nt < 8; nt++) mma16816(oacc[nt], apl[ks], bvh[nt]);
        }
    }

    const float inv0 = 1.0f / lsum[0];
    const float inv1 = 1.0f / lsum[1];
    const int tok0 = qb + warp * 16 + (lane >> 2);
#pragma unroll
    for (int nt = 0; nt < 8; nt++) {
        const int d0 = nt * 8 + 2 * (lane & 3);
        size_t i0 = ((size_t)b * S_ + tok0) * D_ + h * HD_ + d0;
        size_t i1 = ((size_t)b * S_ + tok0 + 8) * D_ + h * HD_ + d0;
        uint32_t hi, lo;
        split2(oacc[nt][0] * inv0, oacc[nt][1] * inv0, hi, lo);
        *(uint32_t*)(oh + i0) = hi;
        *(uint32_t*)(ol + i0) = lo;
        split2(oacc[nt][2] * inv1, oacc[nt][3] * inv1, hi, lo);
        *(uint32_t*)(oh + i1) = hi;
        *(uint32_t*)(ol + i1) = lo;
    }
}

// ---------------------------------------------------------------------------
// Launch
// ---------------------------------------------------------------------------
extern "C" void kernel_launch(void* const* d_in, const int* in_sizes, int n_in,
                              void* d_out, int out_size)
{
    const float* x      = (const float*)d_in[0];
    const float* ada    = (const float*)d_in[1];
    const float* regs   = (const float*)d_in[2];
    const float* W_qkv  = (const float*)d_in[3];
    const float* b_qkv  = (const float*)d_in[4];
    const float* W_out  = (const float*)d_in[5];
    const float* b_out  = (const float*)d_in[6];
    float* out = (float*)d_out;

    __half *xrh, *xrl, *wqh, *woh, *ath, *atl, *qvh, *qvl;
    cudaGetSymbolAddress((void**)&xrh, g_xr_hi);
    cudaGetSymbolAddress((void**)&xrl, g_xr_lo);
    cudaGetSymbolAddress((void**)&wqh, g_wq_hi);
    cudaGetSymbolAddress((void**)&woh, g_wo_hi);
    cudaGetSymbolAddress((void**)&ath, g_at_hi);
    cudaGetSymbolAddress((void**)&atl, g_at_lo);
    cudaGetSymbolAddress((void**)&qvh, g_qkv_hi);
    cudaGetSymbolAddress((void**)&qvl, g_qkv_lo);

    cudaFuncSetAttribute(gemm_fp16, cudaFuncAttributeMaxDynamicSharedMemorySize, GEMM_SMEM);
    cudaFuncSetAttribute(attn_tc, cudaFuncAttributeMaxDynamicSharedMemorySize, ATTN_SMEM);

    // 1. merged prep
    prep_split<<<(N_PREP + 255) / 256, 256>>>(x, ada, regs, W_qkv, W_out,
                                              xrh, xrl, wqh, woh);

    // 2. qkv planes = split((xr_h + xr_l) @ Wq_h^T + b_qkv) : M=4112, N=3072
    gemm_fp16<<<dim3(QKVW_ / 128, MPAD_ / 256), 256, GEMM_SMEM>>>(
        xrh, xrl, wqh, b_qkv, nullptr, qvh, qvl, B_ * T_, QKVW_, D_, 1);

    // 3. windowed attention (2-term fp16, hi-only K/V) -> hi/lo planes
    attn_tc<<<dim3(S_ / 64, H_, B_), 128, ATTN_SMEM>>>(qvh, qvl, ath, atl);

    // 4. out = (at_h + at_l) @ Wo_h^T + b_out : M=4096, N=1024 (fp32 out)
    gemm_fp16<<<dim3(D_ / 128, (B_ * S_) / 256), 256, GEMM_SMEM>>>(
        ath, atl, woh, b_out, out, nullptr, nullptr, B_ * S_, D_, D_, 0);
}

// round 16
// speedup vs baseline: 2.4780x; 1.6910x over previous
#include <cuda_runtime.h>
#include <cuda_fp16.h>
#include <math.h>
#include <stdint.h>

// Problem constants
#define B_   2
#define S_   2048
#define D_   1024
#define H_   16
#define HD_  64
#define R_   8
#define T_   2056      // S_ + R_
#define HALF_ 128
#define QKVW_ 3072     // 3*D_
#define MPAD_ 4352     // B_*T_ = 4112 padded to multiple of 256

// Scratch (device globals; no allocation allowed)
__device__ __align__(16) __half g_xr[(size_t)MPAD_ * D_];
__device__ __align__(16) __half g_wq[(size_t)QKVW_ * D_];
__device__ __align__(16) __half g_wo[(size_t)D_ * D_];
__device__ __align__(16) __half g_at[(size_t)B_ * S_ * D_];
__device__ __align__(16) __half g_qkv[(size_t)B_ * T_ * QKVW_];

// ---------------------------------------------------------------------------
// helpers
// ---------------------------------------------------------------------------
__device__ __forceinline__ uint32_t smem_u32(const void* p) {
    uint32_t a;
    asm("{ .reg .u64 t; cvta.to.shared.u64 t, %1; cvt.u32.u64 %0, t; }"
        : "=r"(a) : "l"(p));
    return a;
}
__device__ __forceinline__ uint32_t sw128(uint32_t off) {
    return off ^ ((off >> 3) & 0x70);
}
__device__ __forceinline__ void cp16(uint32_t dst, const void* src) {
    asm volatile("cp.async.cg.shared.global [%0], [%1], 16;"
                 :: "r"(dst), "l"(src) : "memory");
}
__device__ __forceinline__ void cp_commit() {
    asm volatile("cp.async.commit_group;" ::: "memory");
}
__device__ __forceinline__ void cp_wait0() {
    asm volatile("cp.async.wait_group 0;" ::: "memory");
}
__device__ __forceinline__ void cp_wait1() {
    asm volatile("cp.async.wait_group 1;" ::: "memory");
}
__device__ __forceinline__ void ldm_x4(uint32_t* r, uint32_t addr) {
    asm volatile("ldmatrix.sync.aligned.m8n8.x4.shared.b16 {%0,%1,%2,%3}, [%4];"
                 : "=r"(r[0]), "=r"(r[1]), "=r"(r[2]), "=r"(r[3]) : "r"(addr));
}
__device__ __forceinline__ void ldm_x4_t(uint32_t* r, uint32_t addr) {
    asm volatile("ldmatrix.sync.aligned.m8n8.x4.trans.shared.b16 {%0,%1,%2,%3}, [%4];"
                 : "=r"(r[0]), "=r"(r[1]), "=r"(r[2]), "=r"(r[3]) : "r"(addr));
}
// fp16 inputs, fp32 accumulate
__device__ __forceinline__ void mma16816(float* c, const uint32_t* a, const uint32_t* b) {
    asm volatile(
        "mma.sync.aligned.m16n8k16.row.col.f32.f16.f16.f32 "
        "{%0,%1,%2,%3}, {%4,%5,%6,%7}, {%8,%9}, {%0,%1,%2,%3};"
        : "+f"(c[0]), "+f"(c[1]), "+f"(c[2]), "+f"(c[3])
        : "r"(a[0]), "r"(a[1]), "r"(a[2]), "r"(a[3]), "r"(b[0]), "r"(b[1]));
}

// round 4 floats -> fp16x4 (uint2)
__device__ __forceinline__ uint2 round4h(float4 v) {
    uint2 hi;
    __half2 p01 = __floats2half2_rn(v.x, v.y);
    __half2 p23 = __floats2half2_rn(v.z, v.w);
    hi.x = *(uint32_t*)&p01;
    hi.y = *(uint32_t*)&p23;
    return hi;
}
// round 2 floats -> fp16x2 word
__device__ __forceinline__ uint32_t round2h(float a, float b) {
    __half2 p = __floats2half2_rn(a, b);
    return *(uint32_t*)&p;
}

// ---------------------------------------------------------------------------
// Kernel 1 (merged prep): xr build + weight rounds, all single fp16 planes
// ---------------------------------------------------------------------------
#define N_XR (MPAD_ * (D_ / 4))
#define N_WQ (QKVW_ * D_ / 4)
#define N_WO (D_ * D_ / 4)
#define N_PREP (N_XR + N_WQ + N_WO)

__global__ void prep_split(const float* __restrict__ x,
                           const float* __restrict__ ada,
                           const float* __restrict__ regs,
                           const float* __restrict__ Wq,
                           const float* __restrict__ Wo,
                           __half* __restrict__ xh,
                           __half* __restrict__ wqh,
                           __half* __restrict__ woh)
{
    int i = blockIdx.x * blockDim.x + threadIdx.x;
    if (i >= N_PREP) return;
    const int D4 = D_ / 4;

    if (i < N_XR) {
        int d4 = i % D4;
        int row = i / D4;
        uint2 hi = make_uint2(0u, 0u);
        if (row < B_ * T_) {
            int t = row % T_;
            int b = row / T_;
            float4 v;
            if (t < R_) {
                float4 rv = ((const float4*)regs)[t * D4 + d4];
                float4 av = ((const float4*)ada)[b * D4 + d4];
                v = make_float4(rv.x * (1.f + av.x), rv.y * (1.f + av.y),
                                rv.z * (1.f + av.z), rv.w * (1.f + av.w));
            } else {
                v = ((const float4*)x)[((size_t)b * S_ + (t - R_)) * D4 + d4];
            }
            hi = round4h(v);
        }
        ((uint2*)xh)[i] = hi;
    } else if (i < N_XR + N_WQ) {
        int j = i - N_XR;
        ((uint2*)wqh)[j] = round4h(((const float4*)Wq)[j]);
    } else {
        int j = i - N_XR - N_WQ;
        ((uint2*)woh)[j] = round4h(((const float4*)Wo)[j]);
    }
}

// ---------------------------------------------------------------------------
// Kernel: plain fp16 tensor-core GEMM, 256x128 CTA tile, fp32 accum.
// C[M,N] = A @ B^T + bias.  Stage: [A 32K][B 16K] = 48KB; 2 stages = 96KB.
// ---------------------------------------------------------------------------
#define GSTAGE_BYTES 49152
#define GEMM_SMEM (2 * GSTAGE_BYTES)

__global__ __launch_bounds__(256, 1)
void gemm_fp16(const __half* __restrict__ Ah,
               const __half* __restrict__ Bh,
               const float* __restrict__ bias,
               float* __restrict__ Cf,
               __half* __restrict__ Ch,
               int M, int N, int K, int halfOut)
{
    extern __shared__ __align__(128) char smem[];
    const uint32_t sb = smem_u32(smem);
    const int tid = threadIdx.x, wid = tid >> 5, lane = tid & 31;
    const int brow = blockIdx.y * 256, bcol = blockIdx.x * 128;

    const int r0 = tid >> 3, lseg = tid & 7;
    const uint32_t sw0 = sw128((uint32_t)r0 * 128 + lseg * 16);
    const size_t aBase = (size_t)(brow + r0) * K;
    const size_t bBase = (size_t)(bcol + r0) * K;
    const int esel = lseg * 8;
    const size_t rstep = (size_t)32 * K;

    auto issue = [&](int c) {
        const uint32_t sdst = sb + (c & 1) * GSTAGE_BYTES;
        const size_t ebase = (size_t)c * 64 + esel;
#pragma unroll
        for (int j = 0; j < 8; j++) {
            cp16(sdst + sw0 + j * 4096, Ah + aBase + j * rstep + ebase);
        }
#pragma unroll
        for (int j = 0; j < 4; j++) {
            cp16(sdst + 32768 + sw0 + j * 4096, Bh + bBase + j * rstep + ebase);
        }
        cp_commit();
    };

    issue(0);

    float acc[4][8][4];
#pragma unroll
    for (int a = 0; a < 4; a++)
#pragma unroll
        for (int b = 0; b < 8; b++)
#pragma unroll
            for (int cc = 0; cc < 4; cc++) acc[a][b][cc] = 0.f;

    const int mb = (wid >> 1) * 64, nb = (wid & 1) * 64;
    const int laneA_row = mb + (lane & 15);
    const uint32_t laneA_k = (lane >> 4) * 16;
    const int laneB_row = nb + ((lane >> 4) << 3) + (lane & 7);
    const uint32_t laneB_k = ((lane >> 3) & 1) * 16;

    const int nCh = K >> 6;
    for (int c = 0; c < nCh; c++) {
        cp_wait0();
        __syncthreads();
        if (c + 1 < nCh) issue(c + 1);

        const uint32_t s = sb + (c & 1) * GSTAGE_BYTES;
#pragma unroll
        for (int ks = 0; ks < 4; ks++) {
            uint32_t bh[8][2];
#pragma unroll
            for (int ntp = 0; ntp < 4; ntp++) {
                uint32_t byte = (uint32_t)(laneB_row + ntp * 16) * 128 + ks * 32 + laneB_k;
                uint32_t sw = sw128(byte);
                uint32_t r[4];
                ldm_x4(r, s + 32768 + sw);
                bh[2 * ntp][0] = r[0]; bh[2 * ntp][1] = r[1];
                bh[2 * ntp + 1][0] = r[2]; bh[2 * ntp + 1][1] = r[3];
            }
#pragma unroll
            for (int mt = 0; mt < 4; mt++) {
                uint32_t byte = (uint32_t)(laneA_row + mt * 16) * 128 + ks * 32 + laneA_k;
                uint32_t sw = sw128(byte);
                uint32_t ah[4];
                ldm_x4(ah, s + sw);
#pragma unroll
                for (int nt = 0; nt < 8; nt++) mma16816(acc[mt][nt], ah, bh[nt]);
            }
        }
    }

#pragma unroll
    for (int mt = 0; mt < 4; mt++) {
        const int rr0 = brow + mb + mt * 16 + (lane >> 2);
        const int rr1 = rr0 + 8;
#pragma unroll
        for (int nt = 0; nt < 8; nt++) {
            const int col = bcol + nb + nt * 8 + (lane & 3) * 2;
            float2 bv = *(const float2*)(bias + col);
            if (halfOut) {
                if (rr0 < M)
                    *(uint32_t*)(Ch + (size_t)rr0 * N + col) =
                        round2h(acc[mt][nt][0] + bv.x, acc[mt][nt][1] + bv.y);
                if (rr1 < M)
                    *(uint32_t*)(Ch + (size_t)rr1 * N + col) =
                        round2h(acc[mt][nt][2] + bv.x, acc[mt][nt][3] + bv.y);
            } else {
                if (rr0 < M) {
                    float2 o = make_float2(acc[mt][nt][0] + bv.x, acc[mt][nt][1] + bv.y);
                    *(float2*)(Cf + (size_t)rr0 * N + col) = o;
                }
                if (rr1 < M) {
                    float2 o = make_float2(acc[mt][nt][2] + bv.x, acc[mt][nt][3] + bv.y);
                    *(float2*)(Cf + (size_t)rr1 * N + col) = o;
                }
            }
        }
    }
}

// ---------------------------------------------------------------------------
// Kernel: pure-fp16 tensor-core sliding-window flash attention.
// 64q x 1 head, 128 threads; register fast path; 2-stage 16KB K/V ring.
// smem: Q 8KB + reg 4KB + ring 32KB = 44KB.
// ---------------------------------------------------------------------------
#define ATTN_SMEM (8192 + 4096 + 2 * 16384)

__global__ __launch_bounds__(128)
void attn_tc(const __half* __restrict__ qkv, __half* __restrict__ outp)
{
    extern __shared__ __align__(1024) char asmem[];
    const uint32_t sbase = smem_u32(asmem);
    const uint32_t sQ = sbase;
    const uint32_t sReg = sbase + 8192;             // RK 2KB, RV 2KB
    const uint32_t sRing = sbase + 12288;

    const int b  = blockIdx.z, h = blockIdx.y;
    const int qb = blockIdx.x * 64;
    const int tid = threadIdx.x, warp = tid >> 5, lane = tid & 31;
    const size_t bbase = (size_t)b * T_ * QKVW_;
    const int hcol = h * HD_;

    const int kstart = max(0, qb - HALF_);
    const int kend   = min(S_, qb + 64 + HALF_);
    const int nwin   = (kend - kstart) >> 6;        // 3..5 window chunks

    // window chunk loader: K,V (8 cp16/thread)
    auto issueKV = [&](int c) {
        const uint32_t kvb = sRing + (c & 1) * 16384;
#pragma unroll
        for (int i = 0; i < 8; i++) {
            int slot = tid + i * 128;          // 0..1023
            int plane = slot >> 9;             // 0=K 1=V
            int s2 = slot & 511;
            int row = s2 >> 3, seg = s2 & 7;
            int grow = R_ + kstart + c * 64 + row;
            const __half* src = qkv + bbase + (size_t)grow * QKVW_ +
                                (plane + 1) * D_ + hcol + seg * 8;
            cp16(kvb + plane * 8192 + sw128((uint32_t)row * 128 + seg * 16), src);
        }
        cp_commit();
    };

    // group A: Q (512 slots) + reg K/V 16 rows (256 slots)
    {
#pragma unroll
        for (int i = 0; i < 4; i++) {
            int slot = tid + i * 128;          // 0..511
            int row = slot >> 3, seg = slot & 7;
            const __half* src = qkv + bbase + (size_t)(R_ + qb + row) * QKVW_ +
                                hcol + seg * 8;
            cp16(sQ + sw128((uint32_t)row * 128 + seg * 16), src);
        }
#pragma unroll
        for (int i = 0; i < 2; i++) {
            int slot = tid + i * 128;          // 0..255
            int plane = slot >> 7;             // 0=RK 1=RV
            int s2 = slot & 127;
            int row = s2 >> 3, seg = s2 & 7;   // rows 0..15 (8..15 dup row 0)
            int grow = (row < R_) ? row : 0;
            const __half* src = qkv + bbase + (size_t)grow * QKVW_ +
                                (plane + 1) * D_ + hcol + seg * 8;
            cp16(sReg + plane * 2048 + sw128((uint32_t)row * 128 + seg * 16), src);
        }
        cp_commit();    // group A
        issueKV(0);     // group B
    }

    float oacc[8][4];
    float m[2], lsum[2];
#pragma unroll
    for (int nt = 0; nt < 8; nt++)
#pragma unroll
        for (int e = 0; e < 4; e++) oacc[nt][e] = 0.f;

    const int qtok0 = qb + warp * 16 + (lane >> 2);
    const int laneA_row = warp * 16 + (lane & 15);
    const uint32_t laneA_k = (lane >> 4) * 16;
    const int col2 = 2 * (lane & 3);

    // ---- register path ----
    cp_wait1();
    __syncthreads();
    {
        float racc[2][4];
#pragma unroll
        for (int nt = 0; nt < 2; nt++)
#pragma unroll
            for (int e = 0; e < 4; e++) racc[nt][e] = 0.f;

#pragma unroll
        for (int ks = 0; ks < 4; ks++) {
            uint32_t ah[4];
            uint32_t qoff = sw128((uint32_t)laneA_row * 128 + ks * 32 + laneA_k);
            ldm_x4(ah, sQ + qoff);
            uint32_t row = ((lane >> 4) << 3) + (lane & 7);
            uint32_t off = sw128(row * 128 + ks * 32 + ((lane >> 3) & 1) * 16);
            uint32_t rh[4];
            ldm_x4(rh, sReg + off);            // RK
            uint32_t bh0[2] = {rh[0], rh[1]}, bh1[2] = {rh[2], rh[3]};
            mma16816(racc[0], ah, bh0);
            mma16816(racc[1], ah, bh1);
        }

#pragma unroll
        for (int nt = 0; nt < 2; nt++)
#pragma unroll
            for (int e = 0; e < 4; e++) {
                int klocal = nt * 8 + col2 + (e & 1);
                racc[nt][e] = (klocal < R_) ? racc[nt][e] * 0.125f : -1e30f;
            }

        float mx[2];
        mx[0] = fmaxf(fmaxf(racc[0][0], racc[0][1]), fmaxf(racc[1][0], racc[1][1]));
        mx[1] = fmaxf(fmaxf(racc[0][2], racc[0][3]), fmaxf(racc[1][2], racc[1][3]));
#pragma unroll
        for (int i = 0; i < 2; i++) {
            mx[i] = fmaxf(mx[i], __shfl_xor_sync(0xffffffffu, mx[i], 1));
            mx[i] = fmaxf(mx[i], __shfl_xor_sync(0xffffffffu, mx[i], 2));
            m[i] = mx[i];
        }
        float ps[2] = {0.f, 0.f};
#pragma unroll
        for (int nt = 0; nt < 2; nt++) {
            racc[nt][0] = __expf(racc[nt][0] - m[0]);
            racc[nt][1] = __expf(racc[nt][1] - m[0]);
            racc[nt][2] = __expf(racc[nt][2] - m[1]);
            racc[nt][3] = __expf(racc[nt][3] - m[1]);
            ps[0] += racc[nt][0] + racc[nt][1];
            ps[1] += racc[nt][2] + racc[nt][3];
        }
#pragma unroll
        for (int i = 0; i < 2; i++) {
            ps[i] += __shfl_xor_sync(0xffffffffu, ps[i], 1);
            ps[i] += __shfl_xor_sync(0xffffffffu, ps[i], 2);
            lsum[i] = ps[i];
        }

        uint32_t aph[4];
        aph[0] = round2h(racc[0][0], racc[0][1]);
        aph[1] = round2h(racc[0][2], racc[0][3]);
        aph[2] = round2h(racc[1][0], racc[1][1]);
        aph[3] = round2h(racc[1][2], racc[1][3]);

        uint32_t bvh[8][2];
#pragma unroll
        for (int ntp = 0; ntp < 4; ntp++) {
            uint32_t row = ((lane >> 3) & 1) * 8 + (lane & 7);
            uint32_t off = sw128(row * 128 + ntp * 32 + (lane >> 4) * 16);
            uint32_t r[4];
            ldm_x4_t(r, sReg + 2048 + off);    // RV
            bvh[2 * ntp][0] = r[0]; bvh[2 * ntp][1] = r[1];
            bvh[2 * ntp + 1][0] = r[2]; bvh[2 * ntp + 1][1] = r[3];
        }
#pragma unroll
        for (int nt = 0; nt < 8; nt++) mma16816(oacc[nt], aph, bvh[nt]);
    }

    // ---- window chunks ----
    for (int c = 0; c < nwin; c++) {
        __syncthreads();
        if (c + 1 < nwin) { issueKV(c + 1); cp_wait1(); }
        else              { cp_wait0(); }
        __syncthreads();

        const uint32_t kvb = sRing + (c & 1) * 16384;
        const uint32_t sK = kvb, sV = kvb + 8192;

        float sacc[8][4];
#pragma unroll
        for (int nt = 0; nt < 8; nt++)
#pragma unroll
            for (int e = 0; e < 4; e++) sacc[nt][e] = 0.f;

#pragma unroll
        for (int ks = 0; ks < 4; ks++) {
            uint32_t ah[4];
            uint32_t qoff = sw128((uint32_t)laneA_row * 128 + ks * 32 + laneA_k);
            ldm_x4(ah, sQ + qoff);
            uint32_t bh[8][2];
#pragma unroll
            for (int ntp = 0; ntp < 4; ntp++) {
                uint32_t row = ntp * 16 + ((lane >> 4) << 3) + (lane & 7);
                uint32_t off = sw128(row * 128 + ks * 32 + ((lane >> 3) & 1) * 16);
                uint32_t r[4];
                ldm_x4(r, sK + off);
                bh[2 * ntp][0] = r[0]; bh[2 * ntp][1] = r[1];
                bh[2 * ntp + 1][0] = r[2]; bh[2 * ntp + 1][1] = r[3];
            }
#pragma unroll
            for (int nt = 0; nt < 8; nt++) mma16816(sacc[nt], ah, bh[nt]);
        }

        const int colbase = kstart + c * 64;
#pragma unroll
        for (int nt = 0; nt < 8; nt++) {
#pragma unroll
            for (int e = 0; e < 4; e++) {
                int ktok = colbase + nt * 8 + col2 + (e & 1);
                int qtok = qtok0 + (e >> 1) * 8;
                bool valid = (ktok >= qtok - HALF_) && (ktok <= qtok + HALF_);
                sacc[nt][e] = valid ? sacc[nt][e] * 0.125f : -1e30f;
            }
        }

        float mx[2] = {-1e30f, -1e30f};
#pragma unroll
        for (int nt = 0; nt < 8; nt++) {
            mx[0] = fmaxf(mx[0], fmaxf(sacc[nt][0], sacc[nt][1]));
            mx[1] = fmaxf(mx[1], fmaxf(sacc[nt][2], sacc[nt][3]));
        }
#pragma unroll
        for (int i = 0; i < 2; i++) {
            mx[i] = fmaxf(mx[i], __shfl_xor_sync(0xffffffffu, mx[i], 1));
            mx[i] = fmaxf(mx[i], __shfl_xor_sync(0xffffffffu, mx[i], 2));
        }
        float corr[2], ps[2] = {0.f, 0.f};
#pragma unroll
        for (int i = 0; i < 2; i++) {
            float mn = fmaxf(m[i], mx[i]);
            corr[i] = __expf(m[i] - mn);
            m[i] = mn;
        }
#pragma unroll
        for (int nt = 0; nt < 8; nt++) {
            sacc[nt][0] = __expf(sacc[nt][0] - m[0]);
            sacc[nt][1] = __expf(sacc[nt][1] - m[0]);
            sacc[nt][2] = __expf(sacc[nt][2] - m[1]);
            sacc[nt][3] = __expf(sacc[nt][3] - m[1]);
            ps[0] += sacc[nt][0] + sacc[nt][1];
            ps[1] += sacc[nt][2] + sacc[nt][3];
        }
#pragma unroll
        for (int i = 0; i < 2; i++) {
            ps[i] += __shfl_xor_sync(0xffffffffu, ps[i], 1);
            ps[i] += __shfl_xor_sync(0xffffffffu, ps[i], 2);
            lsum[i] = lsum[i] * corr[i] + ps[i];
        }
#pragma unroll
        for (int nt = 0; nt < 8; nt++) {
            oacc[nt][0] *= corr[0]; oacc[nt][1] *= corr[0];
            oacc[nt][2] *= corr[1]; oacc[nt][3] *= corr[1];
        }

        uint32_t aph[4][4];
#pragma unroll
        for (int ks = 0; ks < 4; ks++) {
            aph[ks][0] = round2h(sacc[2 * ks][0],     sacc[2 * ks][1]);
            aph[ks][1] = round2h(sacc[2 * ks][2],     sacc[2 * ks][3]);
            aph[ks][2] = round2h(sacc[2 * ks + 1][0], sacc[2 * ks + 1][1]);
            aph[ks][3] = round2h(sacc[2 * ks + 1][2], sacc[2 * ks + 1][3]);
        }

#pragma unroll
        for (int ks = 0; ks < 4; ks++) {
            uint32_t bvh[8][2];
#pragma unroll
            for (int ntp = 0; ntp < 4; ntp++) {
                uint32_t row = ks * 16 + ((lane >> 3) & 1) * 8 + (lane & 7);
                uint32_t off = sw128(row * 128 + ntp * 32 + (lane >> 4) * 16);
                uint32_t r[4];
                ldm_x4_t(r, sV + off);
                bvh[2 * ntp][0] = r[0]; bvh[2 * ntp][1] = r[1];
                bvh[2 * ntp + 1][0] = r[2]; bvh[2 * ntp + 1][1] = r[3];
            }
#pragma unroll
            for (int nt = 0; nt < 8; nt++) mma16816(oacc[nt], aph[ks], bvh[nt]);
        }
    }

    const float inv0 = 1.0f / lsum[0];
    const float inv1 = 1.0f / lsum[1];
    const int tok0 = qb + warp * 16 + (lane >> 2);
#pragma unroll
    for (int nt = 0; nt < 8; nt++) {
        const int d0 = nt * 8 + 2 * (lane & 3);
        size_t i0 = ((size_t)b * S_ + tok0) * D_ + h * HD_ + d0;
        size_t i1 = ((size_t)b * S_ + tok0 + 8) * D_ + h * HD_ + d0;
        *(uint32_t*)(outp + i0) = round2h(oacc[nt][0] * inv0, oacc[nt][1] * inv0);
        *(uint32_t*)(outp + i1) = round2h(oacc[nt][2] * inv1, oacc[nt][3] * inv1);
    }
}

// ---------------------------------------------------------------------------
// Launch
// ---------------------------------------------------------------------------
extern "C" void kernel_launch(void* const* d_in, const int* in_sizes, int n_in,
                              void* d_out, int out_size)
{
    const float* x      = (const float*)d_in[0];
    const float* ada    = (const float*)d_in[1];
    const float* regs   = (const float*)d_in[2];
    const float* W_qkv  = (const float*)d_in[3];
    const float* b_qkv  = (const float*)d_in[4];
    const float* W_out  = (const float*)d_in[5];
    const float* b_out  = (const float*)d_in[6];
    float* out = (float*)d_out;

    __half *xrh, *wqh, *woh, *ath, *qvh;
    cudaGetSymbolAddress((void**)&xrh, g_xr);
    cudaGetSymbolAddress((void**)&wqh, g_wq);
    cudaGetSymbolAddress((void**)&woh, g_wo);
    cudaGetSymbolAddress((void**)&ath, g_at);
    cudaGetSymbolAddress((void**)&qvh, g_qkv);

    cudaFuncSetAttribute(gemm_fp16, cudaFuncAttributeMaxDynamicSharedMemorySize, GEMM_SMEM);
    cudaFuncSetAttribute(attn_tc, cudaFuncAttributeMaxDynamicSharedMemorySize, ATTN_SMEM);

    // 1. merged prep (all fp16 single planes)
    prep_split<<<(N_PREP + 255) / 256, 256>>>(x, ada, regs, W_qkv, W_out,
                                              xrh, wqh, woh);

    // 2. qkv = round(xr @ Wq^T + b_qkv) : M=4112, N=3072, K=1024
    gemm_fp16<<<dim3(QKVW_ / 128, MPAD_ / 256), 256, GEMM_SMEM>>>(
        xrh, wqh, b_qkv, nullptr, qvh, B_ * T_, QKVW_, D_, 1);

    // 3. windowed attention (pure fp16) -> fp16 plane
    attn_tc<<<dim3(S_ / 64, H_, B_), 128, ATTN_SMEM>>>(qvh, ath);

    // 4. out = attn @ Wo^T + b_out : M=4096, N=1024, K=1024 (fp32 out)
    gemm_fp16<<<dim3(D_ / 128, (B_ * S_) / 256), 256, GEMM_SMEM>>>(
        ath, woh, b_out, out, nullptr, B_ * S_, D_, D_, 0);
}

// round 17
// speedup vs baseline: 2.6254x; 1.0595x over previous
#include <cuda_runtime.h>
#include <cuda_fp16.h>
#include <math.h>
#include <stdint.h>

// Problem constants
#define B_   2
#define S_   2048
#define D_   1024
#define H_   16
#define HD_  64
#define R_   8
#define T_   2056      // S_ + R_
#define HALF_ 128
#define QKVW_ 3072     // 3*D_
#define MPAD_ 4352     // B_*T_ = 4112 padded to multiple of 256 (and 128)

// Scratch (device globals; no allocation allowed)
__device__ __align__(16) __half g_xr[(size_t)MPAD_ * D_];
__device__ __align__(16) __half g_wq[(size_t)QKVW_ * D_];
__device__ __align__(16) __half g_wo[(size_t)D_ * D_];
__device__ __align__(16) __half g_at[(size_t)B_ * S_ * D_];
__device__ __align__(16) __half g_qkv[(size_t)B_ * T_ * QKVW_];

// ---------------------------------------------------------------------------
// helpers
// ---------------------------------------------------------------------------
__device__ __forceinline__ uint32_t smem_u32(const void* p) {
    uint32_t a;
    asm("{ .reg .u64 t; cvta.to.shared.u64 t, %1; cvt.u32.u64 %0, t; }"
        : "=r"(a) : "l"(p));
    return a;
}
__device__ __forceinline__ uint32_t sw128(uint32_t off) {
    return off ^ ((off >> 3) & 0x70);
}
__device__ __forceinline__ void cp16(uint32_t dst, const void* src) {
    asm volatile("cp.async.cg.shared.global [%0], [%1], 16;"
                 :: "r"(dst), "l"(src) : "memory");
}
__device__ __forceinline__ void cp_commit() {
    asm volatile("cp.async.commit_group;" ::: "memory");
}
__device__ __forceinline__ void cp_wait0() {
    asm volatile("cp.async.wait_group 0;" ::: "memory");
}
__device__ __forceinline__ void cp_wait1() {
    asm volatile("cp.async.wait_group 1;" ::: "memory");
}
__device__ __forceinline__ void ldm_x4(uint32_t* r, uint32_t addr) {
    asm volatile("ldmatrix.sync.aligned.m8n8.x4.shared.b16 {%0,%1,%2,%3}, [%4];"
                 : "=r"(r[0]), "=r"(r[1]), "=r"(r[2]), "=r"(r[3]) : "r"(addr));
}
__device__ __forceinline__ void ldm_x4_t(uint32_t* r, uint32_t addr) {
    asm volatile("ldmatrix.sync.aligned.m8n8.x4.trans.shared.b16 {%0,%1,%2,%3}, [%4];"
                 : "=r"(r[0]), "=r"(r[1]), "=r"(r[2]), "=r"(r[3]) : "r"(addr));
}
// fp16 inputs, fp32 accumulate
__device__ __forceinline__ void mma16816(float* c, const uint32_t* a, const uint32_t* b) {
    asm volatile(
        "mma.sync.aligned.m16n8k16.row.col.f32.f16.f16.f32 "
        "{%0,%1,%2,%3}, {%4,%5,%6,%7}, {%8,%9}, {%0,%1,%2,%3};"
        : "+f"(c[0]), "+f"(c[1]), "+f"(c[2]), "+f"(c[3])
        : "r"(a[0]), "r"(a[1]), "r"(a[2]), "r"(a[3]), "r"(b[0]), "r"(b[1]));
}

// round 4 floats -> fp16x4 (uint2)
__device__ __forceinline__ uint2 round4h(float4 v) {
    uint2 hi;
    __half2 p01 = __floats2half2_rn(v.x, v.y);
    __half2 p23 = __floats2half2_rn(v.z, v.w);
    hi.x = *(uint32_t*)&p01;
    hi.y = *(uint32_t*)&p23;
    return hi;
}
// round 2 floats -> fp16x2 word
__device__ __forceinline__ uint32_t round2h(float a, float b) {
    __half2 p = __floats2half2_rn(a, b);
    return *(uint32_t*)&p;
}

// ---------------------------------------------------------------------------
// Kernel 1 (merged prep): xr build + weight rounds, all single fp16 planes
// ---------------------------------------------------------------------------
#define N_XR (MPAD_ * (D_ / 4))
#define N_WQ (QKVW_ * D_ / 4)
#define N_WO (D_ * D_ / 4)
#define N_PREP (N_XR + N_WQ + N_WO)

__global__ void prep_split(const float* __restrict__ x,
                           const float* __restrict__ ada,
                           const float* __restrict__ regs,
                           const float* __restrict__ Wq,
                           const float* __restrict__ Wo,
                           __half* __restrict__ xh,
                           __half* __restrict__ wqh,
                           __half* __restrict__ woh)
{
    int i = blockIdx.x * blockDim.x + threadIdx.x;
    if (i >= N_PREP) return;
    const int D4 = D_ / 4;

    if (i < N_XR) {
        int d4 = i % D4;
        int row = i / D4;
        uint2 hi = make_uint2(0u, 0u);
        if (row < B_ * T_) {
            int t = row % T_;
            int b = row / T_;
            float4 v;
            if (t < R_) {
                float4 rv = ((const float4*)regs)[t * D4 + d4];
                float4 av = ((const float4*)ada)[b * D4 + d4];
                v = make_float4(rv.x * (1.f + av.x), rv.y * (1.f + av.y),
                                rv.z * (1.f + av.z), rv.w * (1.f + av.w));
            } else {
                v = ((const float4*)x)[((size_t)b * S_ + (t - R_)) * D4 + d4];
            }
            hi = round4h(v);
        }
        ((uint2*)xh)[i] = hi;
    } else if (i < N_XR + N_WQ) {
        int j = i - N_XR;
        ((uint2*)wqh)[j] = round4h(((const float4*)Wq)[j]);
    } else {
        int j = i - N_XR - N_WQ;
        ((uint2*)woh)[j] = round4h(((const float4*)Wo)[j]);
    }
}

// ---------------------------------------------------------------------------
// Kernel: plain fp16 tensor-core GEMM, 128x128 CTA tile, 2 CTAs/SM.
// 8 warps as 2(M) x 4(N), warp tile 64x32, fp32 accum.
// Stage: [A 16K][B 16K] = 32KB; 2 stages = 64KB -> 2 CTAs/SM.
// ---------------------------------------------------------------------------
#define GSTAGE_BYTES 32768
#define GEMM_SMEM (2 * GSTAGE_BYTES)

__global__ __launch_bounds__(256, 2)
void gemm_fp16(const __half* __restrict__ Ah,
               const __half* __restrict__ Bh,
               const float* __restrict__ bias,
               float* __restrict__ Cf,
               __half* __restrict__ Ch,
               int M, int N, int K, int halfOut)
{
    extern __shared__ __align__(128) char smem[];
    const uint32_t sb = smem_u32(smem);
    const int tid = threadIdx.x, wid = tid >> 5, lane = tid & 31;
    const int brow = blockIdx.y * 128, bcol = blockIdx.x * 128;

    const int r0 = tid >> 3, lseg = tid & 7;     // r0: 0..31
    const uint32_t sw0 = sw128((uint32_t)r0 * 128 + lseg * 16);
    const size_t aBase = (size_t)(brow + r0) * K;
    const size_t bBase = (size_t)(bcol + r0) * K;
    const int esel = lseg * 8;
    const size_t rstep = (size_t)32 * K;

    auto issue = [&](int c) {
        const uint32_t sdst = sb + (c & 1) * GSTAGE_BYTES;
        const size_t ebase = (size_t)c * 64 + esel;
#pragma unroll
        for (int j = 0; j < 4; j++) {
            cp16(sdst + sw0 + j * 4096, Ah + aBase + j * rstep + ebase);
        }
#pragma unroll
        for (int j = 0; j < 4; j++) {
            cp16(sdst + 16384 + sw0 + j * 4096, Bh + bBase + j * rstep + ebase);
        }
        cp_commit();
    };

    issue(0);

    float acc[4][4][4];
#pragma unroll
    for (int a = 0; a < 4; a++)
#pragma unroll
        for (int b = 0; b < 4; b++)
#pragma unroll
            for (int cc = 0; cc < 4; cc++) acc[a][b][cc] = 0.f;

    const int mb = (wid >> 2) * 64, nb = (wid & 3) * 32;
    const int laneA_row = mb + (lane & 15);
    const uint32_t laneA_k = (lane >> 4) * 16;
    const int laneB_row = nb + ((lane >> 4) << 3) + (lane & 7);
    const uint32_t laneB_k = ((lane >> 3) & 1) * 16;

    const int nCh = K >> 6;
    for (int c = 0; c < nCh; c++) {
        cp_wait0();
        __syncthreads();
        if (c + 1 < nCh) issue(c + 1);

        const uint32_t s = sb + (c & 1) * GSTAGE_BYTES;
#pragma unroll
        for (int ks = 0; ks < 4; ks++) {
            uint32_t bh[4][2];
#pragma unroll
            for (int ntp = 0; ntp < 2; ntp++) {
                uint32_t byte = (uint32_t)(laneB_row + ntp * 16) * 128 + ks * 32 + laneB_k;
                uint32_t sw = sw128(byte);
                uint32_t r[4];
                ldm_x4(r, s + 16384 + sw);
                bh[2 * ntp][0] = r[0]; bh[2 * ntp][1] = r[1];
                bh[2 * ntp + 1][0] = r[2]; bh[2 * ntp + 1][1] = r[3];
            }
#pragma unroll
            for (int mt = 0; mt < 4; mt++) {
                uint32_t byte = (uint32_t)(laneA_row + mt * 16) * 128 + ks * 32 + laneA_k;
                uint32_t sw = sw128(byte);
                uint32_t ah[4];
                ldm_x4(ah, s + sw);
#pragma unroll
                for (int nt = 0; nt < 4; nt++) mma16816(acc[mt][nt], ah, bh[nt]);
            }
        }
    }

#pragma unroll
    for (int mt = 0; mt < 4; mt++) {
        const int rr0 = brow + mb + mt * 16 + (lane >> 2);
        const int rr1 = rr0 + 8;
#pragma unroll
        for (int nt = 0; nt < 4; nt++) {
            const int col = bcol + nb + nt * 8 + (lane & 3) * 2;
            float2 bv = *(const float2*)(bias + col);
            if (halfOut) {
                if (rr0 < M)
                    *(uint32_t*)(Ch + (size_t)rr0 * N + col) =
                        round2h(acc[mt][nt][0] + bv.x, acc[mt][nt][1] + bv.y);
                if (rr1 < M)
                    *(uint32_t*)(Ch + (size_t)rr1 * N + col) =
                        round2h(acc[mt][nt][2] + bv.x, acc[mt][nt][3] + bv.y);
            } else {
                if (rr0 < M) {
                    float2 o = make_float2(acc[mt][nt][0] + bv.x, acc[mt][nt][1] + bv.y);
                    *(float2*)(Cf + (size_t)rr0 * N + col) = o;
                }
                if (rr1 < M) {
                    float2 o = make_float2(acc[mt][nt][2] + bv.x, acc[mt][nt][3] + bv.y);
                    *(float2*)(Cf + (size_t)rr1 * N + col) = o;
                }
            }
        }
    }
}

// ---------------------------------------------------------------------------
// Kernel: pure-fp16 tensor-core sliding-window flash attention (proven R16).
// 64q x 1 head, 128 threads; register fast path; 2-stage 16KB K/V ring.
// smem: Q 8KB + reg 4KB + ring 32KB = 44KB.
// ---------------------------------------------------------------------------
#define ATTN_SMEM (8192 + 4096 + 2 * 16384)

__global__ __launch_bounds__(128)
void attn_tc(const __half* __restrict__ qkv, __half* __restrict__ outp)
{
    extern __shared__ __align__(1024) char asmem[];
    const uint32_t sbase = smem_u32(asmem);
    const uint32_t sQ = sbase;
    const uint32_t sReg = sbase + 8192;             // RK 2KB, RV 2KB
    const uint32_t sRing = sbase + 12288;

    const int b  = blockIdx.z, h = blockIdx.y;
    const int qb = blockIdx.x * 64;
    const int tid = threadIdx.x, warp = tid >> 5, lane = tid & 31;
    const size_t bbase = (size_t)b * T_ * QKVW_;
    const int hcol = h * HD_;

    const int kstart = max(0, qb - HALF_);
    const int kend   = min(S_, qb + 64 + HALF_);
    const int nwin   = (kend - kstart) >> 6;        // 3..5 window chunks

    auto issueKV = [&](int c) {
        const uint32_t kvb = sRing + (c & 1) * 16384;
#pragma unroll
        for (int i = 0; i < 8; i++) {
            int slot = tid + i * 128;          // 0..1023
            int plane = slot >> 9;             // 0=K 1=V
            int s2 = slot & 511;
            int row = s2 >> 3, seg = s2 & 7;
            int grow = R_ + kstart + c * 64 + row;
            const __half* src = qkv + bbase + (size_t)grow * QKVW_ +
                                (plane + 1) * D_ + hcol + seg * 8;
            cp16(kvb + plane * 8192 + sw128((uint32_t)row * 128 + seg * 16), src);
        }
        cp_commit();
    };

    // group A: Q (512 slots) + reg K/V 16 rows (256 slots)
    {
#pragma unroll
        for (int i = 0; i < 4; i++) {
            int slot = tid + i * 128;          // 0..511
            int row = slot >> 3, seg = slot & 7;
            const __half* src = qkv + bbase + (size_t)(R_ + qb + row) * QKVW_ +
                                hcol + seg * 8;
            cp16(sQ + sw128((uint32_t)row * 128 + seg * 16), src);
        }
#pragma unroll
        for (int i = 0; i < 2; i++) {
            int slot = tid + i * 128;          // 0..255
            int plane = slot >> 7;             // 0=RK 1=RV
            int s2 = slot & 127;
            int row = s2 >> 3, seg = s2 & 7;   // rows 0..15 (8..15 dup row 0)
            int grow = (row < R_) ? row : 0;
            const __half* src = qkv + bbase + (size_t)grow * QKVW_ +
                                (plane + 1) * D_ + hcol + seg * 8;
            cp16(sReg + plane * 2048 + sw128((uint32_t)row * 128 + seg * 16), src);
        }
        cp_commit();    // group A
        issueKV(0);     // group B
    }

    float oacc[8][4];
    float m[2], lsum[2];
#pragma unroll
    for (int nt = 0; nt < 8; nt++)
#pragma unroll
        for (int e = 0; e < 4; e++) oacc[nt][e] = 0.f;

    const int qtok0 = qb + warp * 16 + (lane >> 2);
    const int laneA_row = warp * 16 + (lane & 15);
    const uint32_t laneA_k = (lane >> 4) * 16;
    const int col2 = 2 * (lane & 3);

    // ---- register path ----
    cp_wait1();
    __syncthreads();
    {
        float racc[2][4];
#pragma unroll
        for (int nt = 0; nt < 2; nt++)
#pragma unroll
            for (int e = 0; e < 4; e++) racc[nt][e] = 0.f;

#pragma unroll
        for (int ks = 0; ks < 4; ks++) {
            uint32_t ah[4];
            uint32_t qoff = sw128((uint32_t)laneA_row * 128 + ks * 32 + laneA_k);
            ldm_x4(ah, sQ + qoff);
            uint32_t row = ((lane >> 4) << 3) + (lane & 7);
            uint32_t off = sw128(row * 128 + ks * 32 + ((lane >> 3) & 1) * 16);
            uint32_t rh[4];
            ldm_x4(rh, sReg + off);            // RK
            uint32_t bh0[2] = {rh[0], rh[1]}, bh1[2] = {rh[2], rh[3]};
            mma16816(racc[0], ah, bh0);
            mma16816(racc[1], ah, bh1);
        }

#pragma unroll
        for (int nt = 0; nt < 2; nt++)
#pragma unroll
            for (int e = 0; e < 4; e++) {
                int klocal = nt * 8 + col2 + (e & 1);
                racc[nt][e] = (klocal < R_) ? racc[nt][e] * 0.125f : -1e30f;
            }

        float mx[2];
        mx[0] = fmaxf(fmaxf(racc[0][0], racc[0][1]), fmaxf(racc[1][0], racc[1][1]));
        mx[1] = fmaxf(fmaxf(racc[0][2], racc[0][3]), fmaxf(racc[1][2], racc[1][3]));
#pragma unroll
        for (int i = 0; i < 2; i++) {
            mx[i] = fmaxf(mx[i], __shfl_xor_sync(0xffffffffu, mx[i], 1));
            mx[i] = fmaxf(mx[i], __shfl_xor_sync(0xffffffffu, mx[i], 2));
            m[i] = mx[i];
        }
        float ps[2] = {0.f, 0.f};
#pragma unroll
        for (int nt = 0; nt < 2; nt++) {
            racc[nt][0] = __expf(racc[nt][0] - m[0]);
            racc[nt][1] = __expf(racc[nt][1] - m[0]);
            racc[nt][2] = __expf(racc[nt][2] - m[1]);
            racc[nt][3] = __expf(racc[nt][3] - m[1]);
            ps[0] += racc[nt][0] + racc[nt][1];
            ps[1] += racc[nt][2] + racc[nt][3];
        }
#pragma unroll
        for (int i = 0; i < 2; i++) {
            ps[i] += __shfl_xor_sync(0xffffffffu, ps[i], 1);
            ps[i] += __shfl_xor_sync(0xffffffffu, ps[i], 2);
            lsum[i] = ps[i];
        }

        uint32_t aph[4];
        aph[0] = round2h(racc[0][0], racc[0][1]);
        aph[1] = round2h(racc[0][2], racc[0][3]);
        aph[2] = round2h(racc[1][0], racc[1][1]);
        aph[3] = round2h(racc[1][2], racc[1][3]);

        uint32_t bvh[8][2];
#pragma unroll
        for (int ntp = 0; ntp < 4; ntp++) {
            uint32_t row = ((lane >> 3) & 1) * 8 + (lane & 7);
            uint32_t off = sw128(row * 128 + ntp * 32 + (lane >> 4) * 16);
            uint32_t r[4];
            ldm_x4_t(r, sReg + 2048 + off);    // RV
            bvh[2 * ntp][0] = r[0]; bvh[2 * ntp][1] = r[1];
            bvh[2 * ntp + 1][0] = r[2]; bvh[2 * ntp + 1][1] = r[3];
        }
#pragma unroll
        for (int nt = 0; nt < 8; nt++) mma16816(oacc[nt], aph, bvh[nt]);
    }

    // ---- window chunks ----
    for (int c = 0; c < nwin; c++) {
        __syncthreads();
        if (c + 1 < nwin) { issueKV(c + 1); cp_wait1(); }
        else              { cp_wait0(); }
        __syncthreads();

        const uint32_t kvb = sRing + (c & 1) * 16384;
        const uint32_t sK = kvb, sV = kvb + 8192;

        float sacc[8][4];
#pragma unroll
        for (int nt = 0; nt < 8; nt++)
#pragma unroll
            for (int e = 0; e < 4; e++) sacc[nt][e] = 0.f;

#pragma unroll
        for (int ks = 0; ks < 4; ks++) {
            uint32_t ah[4];
            uint32_t qoff = sw128((uint32_t)laneA_row * 128 + ks * 32 + laneA_k);
            ldm_x4(ah, sQ + qoff);
            uint32_t bh[8][2];
#pragma unroll
            for (int ntp = 0; ntp < 4; ntp++) {
                uint32_t row = ntp * 16 + ((lane >> 4) << 3) + (lane & 7);
                uint32_t off = sw128(row * 128 + ks * 32 + ((lane >> 3) & 1) * 16);
                uint32_t r[4];
                ldm_x4(r, sK + off);
                bh[2 * ntp][0] = r[0]; bh[2 * ntp][1] = r[1];
                bh[2 * ntp + 1][0] = r[2]; bh[2 * ntp + 1][1] = r[3];
            }
#pragma unroll
            for (int nt = 0; nt < 8; nt++) mma16816(sacc[nt], ah, bh[nt]);
        }

        const int colbase = kstart + c * 64;
#pragma unroll
        for (int nt = 0; nt < 8; nt++) {
#pragma unroll
            for (int e = 0; e < 4; e++) {
                int ktok = colbase + nt * 8 + col2 + (e & 1);
                int qtok = qtok0 + (e >> 1) * 8;
                bool valid = (ktok >= qtok - HALF_) && (ktok <= qtok + HALF_);
                sacc[nt][e] = valid ? sacc[nt][e] * 0.125f : -1e30f;
            }
        }

        float mx[2] = {-1e30f, -1e30f};
#pragma unroll
        for (int nt = 0; nt < 8; nt++) {
            mx[0] = fmaxf(mx[0], fmaxf(sacc[nt][0], sacc[nt][1]));
            mx[1] = fmaxf(mx[1], fmaxf(sacc[nt][2], sacc[nt][3]));
        }
#pragma unroll
        for (int i = 0; i < 2; i++) {
            mx[i] = fmaxf(mx[i], __shfl_xor_sync(0xffffffffu, mx[i], 1));
            mx[i] = fmaxf(mx[i], __shfl_xor_sync(0xffffffffu, mx[i], 2));
        }
        float corr[2], ps[2] = {0.f, 0.f};
#pragma unroll
        for (int i = 0; i < 2; i++) {
            float mn = fmaxf(m[i], mx[i]);
            corr[i] = __expf(m[i] - mn);
            m[i] = mn;
        }
#pragma unroll
        for (int nt = 0; nt < 8; nt++) {
            sacc[nt][0] = __expf(sacc[nt][0] - m[0]);
            sacc[nt][1] = __expf(sacc[nt][1] - m[0]);
            sacc[nt][2] = __expf(sacc[nt][2] - m[1]);
            sacc[nt][3] = __expf(sacc[nt][3] - m[1]);
            ps[0] += sacc[nt][0] + sacc[nt][1];
            ps[1] += sacc[nt][2] + sacc[nt][3];
        }
#pragma unroll
        for (int i = 0; i < 2; i++) {
            ps[i] += __shfl_xor_sync(0xffffffffu, ps[i], 1);
            ps[i] += __shfl_xor_sync(0xffffffffu, ps[i], 2);
            lsum[i] = lsum[i] * corr[i] + ps[i];
        }
#pragma unroll
        for (int nt = 0; nt < 8; nt++) {
            oacc[nt][0] *= corr[0]; oacc[nt][1] *= corr[0];
            oacc[nt][2] *= corr[1]; oacc[nt][3] *= corr[1];
        }

        uint32_t aph[4][4];
#pragma unroll
        for (int ks = 0; ks < 4; ks++) {
            aph[ks][0] = round2h(sacc[2 * ks][0],     sacc[2 * ks][1]);
            aph[ks][1] = round2h(sacc[2 * ks][2],     sacc[2 * ks][3]);
            aph[ks][2] = round2h(sacc[2 * ks + 1][0], sacc[2 * ks + 1][1]);
            aph[ks][3] = round2h(sacc[2 * ks + 1][2], sacc[2 * ks + 1][3]);
        }

#pragma unroll
        for (int ks = 0; ks < 4; ks++) {
            uint32_t bvh[8][2];
#pragma unroll
            for (int ntp = 0; ntp < 4; ntp++) {
                uint32_t row = ks * 16 + ((lane >> 3) & 1) * 8 + (lane & 7);
                uint32_t off = sw128(row * 128 + ntp * 32 + (lane >> 4) * 16);
                uint32_t r[4];
                ldm_x4_t(r, sV + off);
                bvh[2 * ntp][0] = r[0]; bvh[2 * ntp][1] = r[1];
                bvh[2 * ntp + 1][0] = r[2]; bvh[2 * ntp + 1][1] = r[3];
            }
#pragma unroll
            for (int nt = 0; nt < 8; nt++) mma16816(oacc[nt], aph[ks], bvh[nt]);
        }
    }

    const float inv0 = 1.0f / lsum[0];
    const float inv1 = 1.0f / lsum[1];
    const int tok0 = qb + warp * 16 + (lane >> 2);
#pragma unroll
    for (int nt = 0; nt < 8; nt++) {
        const int d0 = nt * 8 + 2 * (lane & 3);
        size_t i0 = ((size_t)b * S_ + tok0) * D_ + h * HD_ + d0;
        size_t i1 = ((size_t)b * S_ + tok0 + 8) * D_ + h * HD_ + d0;
        *(uint32_t*)(outp + i0) = round2h(oacc[nt][0] * inv0, oacc[nt][1] * inv0);
        *(uint32_t*)(outp + i1) = round2h(oacc[nt][2] * inv1, oacc[nt][3] * inv1);
    }
}

// ---------------------------------------------------------------------------
// Launch
// ---------------------------------------------------------------------------
extern "C" void kernel_launch(void* const* d_in, const int* in_sizes, int n_in,
                              void* d_out, int out_size)
{
    const float* x      = (const float*)d_in[0];
    const float* ada    = (const float*)d_in[1];
    const float* regs   = (const float*)d_in[2];
    const float* W_qkv  = (const float*)d_in[3];
    const float* b_qkv  = (const float*)d_in[4];
    const float* W_out  = (const float*)d_in[5];
    const float* b_out  = (const float*)d_in[6];
    float* out = (float*)d_out;

    __half *xrh, *wqh, *woh, *ath, *qvh;
    cudaGetSymbolAddress((void**)&xrh, g_xr);
    cudaGetSymbolAddress((void**)&wqh, g_wq);
    cudaGetSymbolAddress((void**)&woh, g_wo);
    cudaGetSymbolAddress((void**)&ath, g_at);
    cudaGetSymbolAddress((void**)&qvh, g_qkv);

    cudaFuncSetAttribute(gemm_fp16, cudaFuncAttributeMaxDynamicSharedMemorySize, GEMM_SMEM);
    cudaFuncSetAttribute(attn_tc, cudaFuncAttributeMaxDynamicSharedMemorySize, ATTN_SMEM);

    // 1. merged prep (all fp16 single planes)
    prep_split<<<(N_PREP + 255) / 256, 256>>>(x, ada, regs, W_qkv, W_out,
                                              xrh, wqh, woh);

    // 2. qkv = round(xr @ Wq^T + b_qkv) : M=4112, N=3072, K=1024
    gemm_fp16<<<dim3(QKVW_ / 128, MPAD_ / 128), 256, GEMM_SMEM>>>(
        xrh, wqh, b_qkv, nullptr, qvh, B_ * T_, QKVW_, D_, 1);

    // 3. windowed attention (pure fp16) -> fp16 plane
    attn_tc<<<dim3(S_ / 64, H_, B_), 128, ATTN_SMEM>>>(qvh, ath);

    // 4. out = attn @ Wo^T + b_out : M=4096, N=1024, K=1024 (fp32 out)
    gemm_fp16<<<dim3(D_ / 128, (B_ * S_) / 128), 256, GEMM_SMEM>>>(
        ath, woh, b_out, out, nullptr, B_ * S_, D_, D_, 0);
}